// round 3
// baseline (speedup 1.0000x reference)
#include <cuda_runtime.h>
#include <cstddef>

// Problem constants
#define Bd 4
#define Sd 1024
#define Dd 1024
#define Ed 8
#define Rd 8
#define Hd 16
#define DHd 64
#define Md (Bd*Sd)            // 4096 rows (B*S)
#define OUT_OFF ((size_t)Bd*Sd*Dd) // 4194304: out first, qk second

// ---------------- scratch (static device memory; no allocations) ----------------
__device__ float g_xp[Md*Dd];        // router conv output [B,S,D]
__device__ float g_q[Md*Dd];
__device__ float g_k[Md*Dd];
__device__ float g_v[Md*Dd];
__device__ float g_wv[Md*Dd];        // attention output (pre o-proj)
__device__ float g_h[Md*64];         // LoRA intermediate [B*S, E*R]
__device__ float g_ct[3*Dd*Dd];      // conv_w transposed: [t][o][i]
__device__ float g_Bt[Dd*64];        // LoRA B transposed: [n][e*8+r]
__device__ float g_scores[Md];
__device__ float g_wsm[Md];
__device__ float g_pooled[Bd*Dd];
__device__ float g_route[Bd*Ed];
__device__ float g_rowmax[Bd*Hd*Sd];
__device__ float g_rowsum[Bd*Hd*Sd];

// ---------------- helpers ----------------
__device__ __forceinline__ float warpRedSum(float v){
    #pragma unroll
    for (int o=16;o;o>>=1) v += __shfl_xor_sync(0xffffffffu, v, o);
    return v;
}
__device__ __forceinline__ float warpRedMax(float v){
    #pragma unroll
    for (int o=16;o;o>>=1) v = fmaxf(v, __shfl_xor_sync(0xffffffffu, v, o));
    return v;
}

// Fast e^x for x <= 0 (softmax after max-subtraction). FMA-only (no MUFU).
// 2^t = 2^floor(t) * poly(frac), degree-6 Taylor of 2^f, rel err ~2e-5.
__device__ __forceinline__ float fexp(float x){
    float t = x * 1.4426950408889634f;
    t = fmaxf(t, -126.0f);
    float ti = floorf(t);
    float f = t - ti;
    float p = 1.5403530393381608e-4f;
    p = fmaf(p, f, 1.3333558146428443e-3f);
    p = fmaf(p, f, 9.6181291076284770e-3f);
    p = fmaf(p, f, 5.5504108664821580e-2f);
    p = fmaf(p, f, 2.4022650695910070e-1f);
    p = fmaf(p, f, 6.9314718055994530e-1f);
    p = fmaf(p, f, 1.0f);
    float sc = __int_as_float(((int)ti + 127) << 23);
    return sc * p;
}

// ---------------- transposes ----------------
__global__ void tr_convw(const float* __restrict__ cw, float* __restrict__ ct){
    size_t idx = (size_t)blockIdx.x*blockDim.x + threadIdx.x;
    if (idx >= (size_t)3*Dd*Dd) return;
    int t = (int)(idx / ((size_t)Dd*Dd));
    int rem = (int)(idx - (size_t)t*Dd*Dd);
    int o = rem >> 10, i = rem & 1023;
    ct[idx] = cw[(size_t)o*Dd*3 + (size_t)i*3 + t];
}

__global__ void tr_loraB(const float* __restrict__ Bp, float* __restrict__ Bt){
    int idx = blockIdx.x*blockDim.x + threadIdx.x; // 65536
    if (idx >= Dd*64) return;
    int n = idx >> 6, e = (idx >> 3) & 7, r = idx & 7;
    Bt[idx] = Bp[(size_t)e*Dd*Rd + (size_t)n*Rd + r];
}

// ---------------- generic NT SGEMM: C = alpha * A(MxK) * B(NxK)^T ----------------
// epilogue: optional route scale (for LoRA h), bias, accumulate.
__global__ __launch_bounds__(256) void sgemm_nt(
    const float* __restrict__ A, const float* __restrict__ B, float* __restrict__ C,
    int M, int N, int K, int lda, int ldb, int ldc,
    long long sAb, long long sAh, long long sBb, long long sBh,
    long long sCb, long long sCh, int ZH,
    float alpha, const float* __restrict__ bias, const float* __restrict__ route, int addC)
{
    int z = blockIdx.z;
    int zb = z / ZH, zh = z - zb*ZH;
    A += (size_t)zb*sAb + (size_t)zh*sAh;
    B += (size_t)zb*sBb + (size_t)zh*sBh;
    C += (size_t)zb*sCb + (size_t)zh*sCh;

    __shared__ __align__(16) float As[8][128];
    __shared__ __align__(16) float Bs[8][128];
    const int tid = threadIdx.x;
    const int bm = blockIdx.y*128, bn = blockIdx.x*128;
    const int tx = tid & 15, ty = tid >> 4;
    const int lm = tid >> 1;
    const int lk = (tid & 1) * 4;

    float acc[8][8];
    #pragma unroll
    for (int i=0;i<8;i++)
        #pragma unroll
        for (int j=0;j<8;j++) acc[i][j] = 0.f;

    const bool aok = (bm+lm) < M;
    const bool bok = (bn+lm) < N;
    const float* Aptr = A + (size_t)(aok ? (bm+lm) : 0)*lda + lk;
    const float* Bptr = B + (size_t)(bok ? (bn+lm) : 0)*ldb + lk;

    for (int k0 = 0; k0 < K; k0 += 8) {
        float4 av = make_float4(0.f,0.f,0.f,0.f);
        float4 bv = make_float4(0.f,0.f,0.f,0.f);
        if (aok) av = *(const float4*)(Aptr + k0);
        if (bok) bv = *(const float4*)(Bptr + k0);
        As[lk+0][lm]=av.x; As[lk+1][lm]=av.y; As[lk+2][lm]=av.z; As[lk+3][lm]=av.w;
        Bs[lk+0][lm]=bv.x; Bs[lk+1][lm]=bv.y; Bs[lk+2][lm]=bv.z; Bs[lk+3][lm]=bv.w;
        __syncthreads();
        #pragma unroll
        for (int kk=0; kk<8; kk++){
            float a[8], b[8];
            *(float4*)&a[0] = *(const float4*)&As[kk][ty*8];
            *(float4*)&a[4] = *(const float4*)&As[kk][ty*8+4];
            *(float4*)&b[0] = *(const float4*)&Bs[kk][tx*8];
            *(float4*)&b[4] = *(const float4*)&Bs[kk][tx*8+4];
            #pragma unroll
            for (int i=0;i<8;i++)
                #pragma unroll
                for (int j=0;j<8;j++)
                    acc[i][j] = fmaf(a[i], b[j], acc[i][j]);
        }
        __syncthreads();
    }

    #pragma unroll
    for (int i=0;i<8;i++){
        int m = bm + ty*8 + i;
        if (m >= M) continue;
        #pragma unroll
        for (int j=0;j<8;j++){
            int n = bn + tx*8 + j;
            if (n >= N) continue;
            float val = alpha * acc[i][j];
            if (route) val *= route[((m>>10)<<3) + (n>>3)];
            if (bias)  val += bias[n];
            float* cp = C + (size_t)m*ldc + n;
            if (addC) val += *cp;
            *cp = val;
        }
    }
}

// ---------------- conv1d (k=3, pad=1) as GEMM: xp[b,s,o] ----------------
__global__ __launch_bounds__(256) void conv_gemm(
    const float* __restrict__ x, const float* __restrict__ ct,
    const float* __restrict__ cb, float* __restrict__ xp)
{
    const int tid = threadIdx.x;
    const int bm = blockIdx.y*128, bn = blockIdx.x*128;
    const int tx = tid & 15, ty = tid >> 4;
    const int lm = tid >> 1, lk = (tid & 1)*4;
    const int mrow = bm + lm;
    const int b = mrow >> 10, s = mrow & 1023;

    __shared__ __align__(16) float As[8][128];
    __shared__ __align__(16) float Bs[8][128];
    float acc[8][8];
    #pragma unroll
    for (int i=0;i<8;i++)
        #pragma unroll
        for (int j=0;j<8;j++) acc[i][j]=0.f;

    for (int t=0;t<3;t++){
        int s2 = s + t - 1;
        bool ok = ((unsigned)s2 < 1024u);
        const float* Arow = x + ((size_t)b*Sd + (ok ? s2 : 0))*Dd + lk;
        const float* Brow = ct + (size_t)t*Dd*Dd + (size_t)(bn+lm)*Dd + lk;
        for (int k0=0;k0<Dd;k0+=8){
            float4 av = make_float4(0.f,0.f,0.f,0.f);
            if (ok) av = *(const float4*)(Arow + k0);
            float4 bv = *(const float4*)(Brow + k0);
            As[lk+0][lm]=av.x; As[lk+1][lm]=av.y; As[lk+2][lm]=av.z; As[lk+3][lm]=av.w;
            Bs[lk+0][lm]=bv.x; Bs[lk+1][lm]=bv.y; Bs[lk+2][lm]=bv.z; Bs[lk+3][lm]=bv.w;
            __syncthreads();
            #pragma unroll
            for (int kk=0; kk<8; kk++){
                float a[8], b2[8];
                *(float4*)&a[0]  = *(const float4*)&As[kk][ty*8];
                *(float4*)&a[4]  = *(const float4*)&As[kk][ty*8+4];
                *(float4*)&b2[0] = *(const float4*)&Bs[kk][tx*8];
                *(float4*)&b2[4] = *(const float4*)&Bs[kk][tx*8+4];
                #pragma unroll
                for (int i=0;i<8;i++)
                    #pragma unroll
                    for (int j=0;j<8;j++)
                        acc[i][j] = fmaf(a[i], b2[j], acc[i][j]);
            }
            __syncthreads();
        }
    }
    #pragma unroll
    for (int i=0;i<8;i++){
        int m = bm + ty*8 + i;
        #pragma unroll
        for (int j=0;j<8;j++){
            int n = bn + tx*8 + j;
            xp[(size_t)m*Dd + n] = acc[i][j] + cb[n];
        }
    }
}

// ---------------- router small kernels ----------------
__global__ void scores_k(const float* __restrict__ xp, const float* __restrict__ pw,
                         const float* __restrict__ pb, float* __restrict__ scores){
    int row = blockIdx.x;               // 4096
    int tid = threadIdx.x;              // 128
    const float4* xr = (const float4*)(xp + (size_t)row*Dd);
    const float4* pr = (const float4*)pw;
    float s = 0.f;
    #pragma unroll
    for (int i=0;i<2;i++){
        float4 a = xr[tid*2+i], b = pr[tid*2+i];
        s += a.x*b.x + a.y*b.y + a.z*b.z + a.w*b.w;
    }
    s = warpRedSum(s);
    __shared__ float sm[4];
    if ((tid&31)==0) sm[tid>>5]=s;
    __syncthreads();
    if (tid==0) scores[row] = sm[0]+sm[1]+sm[2]+sm[3] + pb[0];
}

__global__ void softmax_w(const float* __restrict__ scores, float* __restrict__ w){
    int b = blockIdx.x; int tid = threadIdx.x; // 256
    float4 v = *(const float4*)(scores + (size_t)b*Sd + tid*4);
    float m = fmaxf(fmaxf(v.x,v.y), fmaxf(v.z,v.w));
    m = warpRedMax(m);
    __shared__ float sm[8];
    __shared__ float gmax, gisum;
    if ((tid&31)==0) sm[tid>>5]=m;
    __syncthreads();
    if (tid==0){ float mm=sm[0]; for(int i=1;i<8;i++) mm=fmaxf(mm,sm[i]); gmax=mm; }
    __syncthreads();
    float e0=expf(v.x-gmax), e1=expf(v.y-gmax), e2=expf(v.z-gmax), e3=expf(v.w-gmax);
    float s = e0+e1+e2+e3;
    s = warpRedSum(s);
    if ((tid&31)==0) sm[tid>>5]=s;
    __syncthreads();
    if (tid==0){ float ss=0; for(int i=0;i<8;i++) ss+=sm[i]; gisum = 1.f/ss; }
    __syncthreads();
    float4 o = make_float4(e0*gisum, e1*gisum, e2*gisum, e3*gisum);
    *(float4*)(w + (size_t)b*Sd + tid*4) = o;
}

__global__ void pooled_k(const float* __restrict__ xp, const float* __restrict__ w,
                         float* __restrict__ pooled){
    int b = blockIdx.y;
    int d = blockIdx.x*128 + threadIdx.x;
    __shared__ float ws[Sd];
    for (int i = threadIdx.x; i < Sd; i += 128) ws[i] = w[(size_t)b*Sd + i];
    __syncthreads();
    float s = 0.f;
    const float* base = xp + (size_t)b*Sd*Dd + d;
    for (int i=0;i<Sd;i++) s = fmaf(ws[i], base[(size_t)i*Dd], s);
    pooled[b*Dd + d] = s;
}

__global__ void route_k(const float* __restrict__ pooled, const float* __restrict__ rw,
                        const float* __restrict__ rb, float* __restrict__ route){
    int tid = threadIdx.x; // 256
    int e = tid >> 5, lane = tid & 31;
    __shared__ float lg[8];
    for (int b=0;b<Bd;b++){
        float s=0.f;
        for (int d=lane; d<Dd; d+=32) s += pooled[b*Dd+d]*rw[e*Dd+d];
        s = warpRedSum(s);
        if (lane==0) lg[e] = s + rb[e];
        __syncthreads();
        if (tid==0){
            float mm=lg[0];
            for (int i=1;i<8;i++) mm=fmaxf(mm,lg[i]);
            float ex[8]; float ss=0.f;
            for (int i=0;i<8;i++){ ex[i]=expf(lg[i]-mm); ss+=ex[i]; }
            float inv = 1.f/ss;
            for (int i=0;i<8;i++) route[b*8+i]=ex[i]*inv;
        }
        __syncthreads();
    }
}

// ---------------- attention ----------------
__global__ void row_max_k(const float* __restrict__ qk, float* __restrict__ rowmax){
    int row = blockIdx.x;               // 65536
    int tid = threadIdx.x;              // 128
    const float4* p = (const float4*)(qk + (size_t)row*Sd);
    float4 a = p[tid*2], b = p[tid*2+1];
    float m = fmaxf(fmaxf(fmaxf(a.x,a.y),fmaxf(a.z,a.w)),
                    fmaxf(fmaxf(b.x,b.y),fmaxf(b.z,b.w)));
    m = warpRedMax(m);
    __shared__ float sm[4];
    if ((tid&31)==0) sm[tid>>5]=m;
    __syncthreads();
    if (tid==0) rowmax[row] = fmaxf(fmaxf(sm[0],sm[1]), fmaxf(sm[2],sm[3]));
}

// PV: wv_un[b,i,h*64+d] = sum_j exp(qk - rowmax) * v ; also emits row sums.
// grid (1, S/128, B*H), block 256. N-tile = 64 (= dh).
__global__ __launch_bounds__(256) void attn_pv(
    const float* __restrict__ qk, const float* __restrict__ v,
    const float* __restrict__ rowmax, float* __restrict__ wv, float* __restrict__ rowsum)
{
    const int z = blockIdx.z;
    const int bq = z >> 4, h = z & 15;
    const float* Aq = qk + (size_t)z * Sd * Sd;
    const float* Vh = v + (size_t)bq * Sd * Dd + h*DHd;
    float* Cw = wv + (size_t)bq * Sd * Dd + h*DHd;
    const float* rmax = rowmax + (size_t)z*Sd;
    const int bm = blockIdx.y * 128;

    __shared__ __align__(16) float Ps[16][128];
    __shared__ __align__(16) float Vs[16][64];
    __shared__ float Sred[128][4];

    const int tid = threadIdx.x;
    const int tx = tid & 15, ty = tid >> 4;
    const int m0 = tid >> 2;            // 0..63
    const int kq = (tid & 3) * 4;
    const int kv = tid >> 4;            // 0..15
    const int dq = (tid & 15) * 4;

    const float rm0 = rmax[bm + m0];
    const float rm1 = rmax[bm + m0 + 64];

    float acc[8][4];
    #pragma unroll
    for (int i=0;i<8;i++)
        #pragma unroll
        for (int j=0;j<4;j++) acc[i][j]=0.f;
    float ps0 = 0.f, ps1 = 0.f;

    const float* Ar0 = Aq + (size_t)(bm+m0)*Sd + kq;
    const float* Ar1 = Ar0 + (size_t)64*Sd;

    for (int k0=0; k0<Sd; k0+=16){
        float4 a0 = *(const float4*)(Ar0 + k0);
        float4 a1 = *(const float4*)(Ar1 + k0);
        float p00=fexp(a0.x-rm0), p01=fexp(a0.y-rm0), p02=fexp(a0.z-rm0), p03=fexp(a0.w-rm0);
        float p10=fexp(a1.x-rm1), p11=fexp(a1.y-rm1), p12=fexp(a1.z-rm1), p13=fexp(a1.w-rm1);
        Ps[kq+0][m0]=p00; Ps[kq+1][m0]=p01; Ps[kq+2][m0]=p02; Ps[kq+3][m0]=p03;
        Ps[kq+0][m0+64]=p10; Ps[kq+1][m0+64]=p11; Ps[kq+2][m0+64]=p12; Ps[kq+3][m0+64]=p13;
        ps0 += p00+p01+p02+p03;
        ps1 += p10+p11+p12+p13;
        float4 vv = *(const float4*)(Vh + (size_t)(k0+kv)*Dd + dq);
        *(float4*)&Vs[kv][dq] = vv;
        __syncthreads();
        #pragma unroll
        for (int kk=0; kk<16; kk++){
            float a[8], bb[4];
            *(float4*)&a[0] = *(const float4*)&Ps[kk][ty*8];
            *(float4*)&a[4] = *(const float4*)&Ps[kk][ty*8+4];
            *(float4*)&bb[0] = *(const float4*)&Vs[kk][tx*4];
            #pragma unroll
            for (int i=0;i<8;i++)
                #pragma unroll
                for (int j=0;j<4;j++)
                    acc[i][j] = fmaf(a[i], bb[j], acc[i][j]);
        }
        __syncthreads();
    }

    Sred[m0][tid&3] = ps0;
    Sred[m0+64][tid&3] = ps1;
    __syncthreads();
    if (tid < 128)
        rowsum[(size_t)z*Sd + bm + tid] = Sred[tid][0]+Sred[tid][1]+Sred[tid][2]+Sred[tid][3];

    #pragma unroll
    for (int i=0;i<8;i++){
        size_t rowoff = (size_t)(bm + ty*8 + i)*Dd;
        #pragma unroll
        for (int j=0;j<4;j++)
            Cw[rowoff + tx*4 + j] = acc[i][j];
    }
}

__global__ void norm_wv(float* __restrict__ wv, const float* __restrict__ rowsum){
    int m = blockIdx.x;                 // 4096 = b*S + i
    int b = m >> 10, i = m & 1023;
    int tid = threadIdx.x;              // 256
    __shared__ float inv[16];
    if (tid < 16) inv[tid] = 1.f / rowsum[((size_t)(b*Hd + tid))*Sd + i];
    __syncthreads();
    float4* p = (float4*)(wv + (size_t)m*Dd);
    float4 vv = p[tid];
    float sc = inv[(tid*4) >> 6];
    vv.x*=sc; vv.y*=sc; vv.z*=sc; vv.w*=sc;
    p[tid]=vv;
}

// ---------------- host launcher ----------------
extern "C" void kernel_launch(void* const* d_in, const int* in_sizes, int n_in,
                              void* d_out, int out_size)
{
    (void)in_sizes; (void)n_in; (void)out_size;
    const float* x      = (const float*)d_in[0];
    const float* conv_w = (const float*)d_in[1];
    const float* conv_b = (const float*)d_in[2];
    const float* pool_w = (const float*)d_in[3];
    const float* pool_b = (const float*)d_in[4];
    const float* rlin_w = (const float*)d_in[5];
    const float* rlin_b = (const float*)d_in[6];
    const float* qW=(const float*)d_in[7],  *qb=(const float*)d_in[8];
    const float* qA=(const float*)d_in[9],  *qB=(const float*)d_in[10];
    const float* kW=(const float*)d_in[11], *kA=(const float*)d_in[12], *kB=(const float*)d_in[13];
    const float* vW=(const float*)d_in[14], *vb=(const float*)d_in[15];
    const float* vA=(const float*)d_in[16], *vB=(const float*)d_in[17];
    const float* oW=(const float*)d_in[18], *ob=(const float*)d_in[19];
    const float* oA=(const float*)d_in[20], *oB=(const float*)d_in[21];

    float* out = (float*)d_out;
    float* qk  = out + OUT_OFF;

    float *xp,*q,*k,*v,*wv,*h,*ct,*Bt,*scores,*w,*pooled,*route,*rowmax,*rowsum;
    cudaGetSymbolAddress((void**)&xp, g_xp);
    cudaGetSymbolAddress((void**)&q,  g_q);
    cudaGetSymbolAddress((void**)&k,  g_k);
    cudaGetSymbolAddress((void**)&v,  g_v);
    cudaGetSymbolAddress((void**)&wv, g_wv);
    cudaGetSymbolAddress((void**)&h,  g_h);
    cudaGetSymbolAddress((void**)&ct, g_ct);
    cudaGetSymbolAddress((void**)&Bt, g_Bt);
    cudaGetSymbolAddress((void**)&scores, g_scores);
    cudaGetSymbolAddress((void**)&w,  g_wsm);
    cudaGetSymbolAddress((void**)&pooled, g_pooled);
    cudaGetSymbolAddress((void**)&route,  g_route);
    cudaGetSymbolAddress((void**)&rowmax, g_rowmax);
    cudaGetSymbolAddress((void**)&rowsum, g_rowsum);

    const long long SD = (long long)Sd*Dd;
    const long long SS = (long long)Sd*Sd;

    // --- router ---
    tr_convw<<<(3*Dd*Dd + 255)/256, 256>>>(conv_w, ct);
    conv_gemm<<<dim3(8,32,1), 256>>>(x, ct, conv_b, xp);
    scores_k<<<Md, 128>>>(xp, pool_w, pool_b, scores);
    softmax_w<<<Bd, 256>>>(scores, w);
    pooled_k<<<dim3(8,Bd), 128>>>(xp, w, pooled);
    route_k<<<1, 256>>>(pooled, rlin_w, rlin_b, route);

    // --- q/k/v projections: base + LoRA ---
    const float* Ws[3]  = {qW, kW, vW};
    const float* bs[3]  = {qb, nullptr, vb};
    const float* As_[3] = {qA, kA, vA};
    const float* Bs_[3] = {qB, kB, vB};
    float* outs[3] = {q, k, v};
    for (int p = 0; p < 3; p++){
        sgemm_nt<<<dim3(8,32,1),256>>>(x, Ws[p], outs[p], Md, Dd, Dd, Dd, Dd, Dd,
                                       0,0,0,0,0,0,1, 1.f, bs[p], nullptr, 0);
        tr_loraB<<<(Dd*64+255)/256, 256>>>(Bs_[p], Bt);
        sgemm_nt<<<dim3(1,32,1),256>>>(x, As_[p], h, Md, 64, Dd, Dd, Dd, 64,
                                       0,0,0,0,0,0,1, 1.f, nullptr, route, 0);
        sgemm_nt<<<dim3(8,32,1),256>>>(h, Bt, outs[p], Md, Dd, 64, 64, 64, Dd,
                                       0,0,0,0,0,0,1, 2.0f, nullptr, nullptr, 1);
    }

    // --- qk logits (written straight into d_out), scale = dh^-0.5 = 0.125 ---
    sgemm_nt<<<dim3(8,8,Bd*Hd),256>>>(q, k, qk, Sd, Sd, DHd, Dd, Dd, Sd,
                                      SD, 64, SD, 64, (long long)Hd*SS, SS, Hd,
                                      0.125f, nullptr, nullptr, 0);

    // --- softmax + PV ---
    row_max_k<<<Bd*Hd*Sd, 128>>>(qk, rowmax);
    attn_pv<<<dim3(1, Sd/128, Bd*Hd), 256>>>(qk, v, rowmax, wv, rowsum);
    norm_wv<<<Md, 256>>>(wv, rowsum);

    // --- o projection: base + LoRA, into d_out[0 : B*S*D] ---
    sgemm_nt<<<dim3(8,32,1),256>>>(wv, oW, out, Md, Dd, Dd, Dd, Dd, Dd,
                                   0,0,0,0,0,0,1, 1.f, ob, nullptr, 0);
    tr_loraB<<<(Dd*64+255)/256, 256>>>(oB, Bt);
    sgemm_nt<<<dim3(1,32,1),256>>>(wv, oA, h, Md, 64, Dd, Dd, Dd, 64,
                                   0,0,0,0,0,0,1, 1.f, nullptr, route, 0);
    sgemm_nt<<<dim3(8,32,1),256>>>(h, Bt, out, Md, Dd, 64, 64, 64, Dd,
                                   0,0,0,0,0,0,1, 2.0f, nullptr, nullptr, 1);
}

// round 5
// speedup vs baseline: 2.5412x; 2.5412x over previous
#include <cuda_runtime.h>
#include <cstdint>
#include <cstddef>

#define Bd 4
#define Sd 1024
#define Dd 1024
#define Hd 16
#define DHd 64
#define Md (Bd*Sd)
#define OUT_OFF ((size_t)Bd*Sd*Dd)

__device__ float g_xp[Md*Dd];
__device__ float g_q[Md*Dd];
__device__ float g_k[Md*Dd];
__device__ float g_v[Md*Dd];
__device__ float g_wv[Md*Dd];
__device__ float g_h[Md*192];
__device__ float g_xsh[(size_t)Md*3072];
__device__ float g_ctK[(size_t)Dd*3072];
__device__ float g_AA[192*Dd];
__device__ float g_Bt[Dd*64];
__device__ float g_scores[Md];
__device__ float g_wsm[Md];
__device__ float g_pooled[Bd*Dd];
__device__ float g_route[Bd*8];
__device__ float g_rowmax[Bd*Hd*Sd];
__device__ float g_rowsum[Bd*Hd*Sd];

__device__ __forceinline__ float warpRedSum(float v){
    #pragma unroll
    for (int o=16;o;o>>=1) v += __shfl_xor_sync(0xffffffffu, v, o);
    return v;
}
__device__ __forceinline__ float warpRedMax(float v){
    #pragma unroll
    for (int o=16;o;o>>=1) v = fmaxf(v, __shfl_xor_sync(0xffffffffu, v, o));
    return v;
}
__device__ __forceinline__ float fexp(float x){
    float t = x * 1.4426950408889634f;
    t = fmaxf(t, -126.0f);
    float ti = floorf(t);
    float f = t - ti;
    float p = 1.5403530393381608e-4f;
    p = fmaf(p, f, 1.3333558146428443e-3f);
    p = fmaf(p, f, 9.6181291076284770e-3f);
    p = fmaf(p, f, 5.5504108664821580e-2f);
    p = fmaf(p, f, 2.4022650695910070e-1f);
    p = fmaf(p, f, 6.9314718055994530e-1f);
    p = fmaf(p, f, 1.0f);
    return __int_as_float(((int)ti + 127) << 23) * p;
}
__device__ __forceinline__ uint32_t f2tf(float f){
    uint32_t r; asm("cvt.rna.tf32.f32 %0, %1;" : "=r"(r) : "f"(f)); return r;
}
__device__ __forceinline__ void mma8(float* d, const uint32_t* a, const uint32_t* b){
    asm volatile("mma.sync.aligned.m16n8k8.row.col.f32.tf32.tf32.f32 "
        "{%0,%1,%2,%3}, {%4,%5,%6,%7}, {%8,%9}, {%0,%1,%2,%3};"
        : "+f"(d[0]),"+f"(d[1]),"+f"(d[2]),"+f"(d[3])
        : "r"(a[0]),"r"(a[1]),"r"(a[2]),"r"(a[3]), "r"(b[0]),"r"(b[1]));
}

// ---- tf32 mma.sync GEMM: C = alpha*A(MxK)B(NxK)^T [*route][+bias][+C] ----
// 128x128 tiles, BK=32, 256 thr (8 warps 2x4), double-buffered dyn smem.
#define GSTRIDE 36
#define GEMM_SMEM (4*128*GSTRIDE*4)   // 73728 bytes
__global__ __launch_bounds__(256,1)
void mma_gemm(const float* __restrict__ A, const float* __restrict__ B, float* __restrict__ C,
              int M, int N, int K, int lda, int ldb, int ldc,
              long long sAb, long long sAh, long long sBb, long long sBh,
              long long sCb, long long sCh, int ZH,
              float alpha, const float* __restrict__ bias, const float* __restrict__ route, int addC)
{
    extern __shared__ __align__(16) uint32_t sm[];
    uint32_t* As = sm;                    // [2][128*36]
    uint32_t* Bs = sm + 2*128*GSTRIDE;    // [2][128*36]

    const int tid = threadIdx.x, wid = tid >> 5, lane = tid & 31;
    const int wm = wid >> 2, wn = wid & 3;
    const int lr = lane >> 2, lc = lane & 3;
    int z = blockIdx.z, zb = z / ZH, zh = z - zb*ZH;
    A += (size_t)zb*sAb + (size_t)zh*sAh;
    B += (size_t)zb*sBb + (size_t)zh*sBh;
    C += (size_t)zb*sCb + (size_t)zh*sCh;
    const int bm = blockIdx.y*128, bn = blockIdx.x*128;

    const int row = tid >> 3, c4 = (tid & 7) << 2;   // per-thread ld slot (row, col4)
    const float* Ab = A + (size_t)bm*lda;
    const float* Bb = B + (size_t)bn*ldb;
    const int nch = K >> 5;

    float acc[4][4][4];
    #pragma unroll
    for (int i=0;i<4;i++)
        #pragma unroll
        for (int j=0;j<4;j++)
            #pragma unroll
            for (int r=0;r<4;r++) acc[i][j][r]=0.f;

    // load chunk 0
    {
        #pragma unroll
        for (int j=0;j<4;j++){
            int rr = row + j*32;
            float4 av = *(const float4*)(Ab + (size_t)rr*lda + c4);
            uint32_t* d = As + rr*GSTRIDE + c4;
            d[0]=f2tf(av.x); d[1]=f2tf(av.y); d[2]=f2tf(av.z); d[3]=f2tf(av.w);
            float4 bv = make_float4(0.f,0.f,0.f,0.f);
            if (bn + rr < N) bv = *(const float4*)(Bb + (size_t)rr*ldb + c4);
            uint32_t* e = Bs + rr*GSTRIDE + c4;
            e[0]=f2tf(bv.x); e[1]=f2tf(bv.y); e[2]=f2tf(bv.z); e[3]=f2tf(bv.w);
        }
    }
    __syncthreads();

    for (int c = 0; c < nch; c++){
        const uint32_t* Ac = As + (c&1)*128*GSTRIDE;
        const uint32_t* Bc = Bs + (c&1)*128*GSTRIDE;
        float4 pa[4], pb[4];
        if (c+1 < nch){
            int k0 = (c+1) << 5;
            #pragma unroll
            for (int j=0;j<4;j++){
                int rr = row + j*32;
                pa[j] = *(const float4*)(Ab + (size_t)rr*lda + k0 + c4);
                pb[j] = make_float4(0.f,0.f,0.f,0.f);
                if (bn + rr < N) pb[j] = *(const float4*)(Bb + (size_t)rr*ldb + k0 + c4);
            }
        }
        #pragma unroll
        for (int ks=0; ks<4; ks++){
            uint32_t af[4][4], bf[4][2];
            #pragma unroll
            for (int mt=0; mt<4; mt++){
                const uint32_t* p = Ac + (wm*64 + mt*16)*GSTRIDE + ks*8;
                af[mt][0] = p[lr*GSTRIDE + lc];
                af[mt][1] = p[(lr+8)*GSTRIDE + lc];
                af[mt][2] = p[lr*GSTRIDE + lc + 4];
                af[mt][3] = p[(lr+8)*GSTRIDE + lc + 4];
            }
            #pragma unroll
            for (int nt=0; nt<4; nt++){
                const uint32_t* p = Bc + (wn*32 + nt*8)*GSTRIDE + ks*8;
                bf[nt][0] = p[lr*GSTRIDE + lc];
                bf[nt][1] = p[lr*GSTRIDE + lc + 4];
            }
            #pragma unroll
            for (int mt=0; mt<4; mt++)
                #pragma unroll
                for (int nt=0; nt<4; nt++)
                    mma8(acc[mt][nt], af[mt], bf[nt]);
        }
        if (c+1 < nch){
            uint32_t* An = As + ((c+1)&1)*128*GSTRIDE;
            uint32_t* Bn = Bs + ((c+1)&1)*128*GSTRIDE;
            #pragma unroll
            for (int j=0;j<4;j++){
                int rr = row + j*32;
                uint32_t* d = An + rr*GSTRIDE + c4;
                d[0]=f2tf(pa[j].x); d[1]=f2tf(pa[j].y); d[2]=f2tf(pa[j].z); d[3]=f2tf(pa[j].w);
                uint32_t* e = Bn + rr*GSTRIDE + c4;
                e[0]=f2tf(pb[j].x); e[1]=f2tf(pb[j].y); e[2]=f2tf(pb[j].z); e[3]=f2tf(pb[j].w);
            }
        }
        __syncthreads();
    }

    // epilogue: fragments -> global
    #pragma unroll
    for (int mt=0; mt<4; mt++){
        #pragma unroll
        for (int nt=0; nt<4; nt++){
            int n = bn + wn*32 + nt*8 + 2*lc;
            if (n >= N) continue;
            int m0 = bm + wm*64 + mt*16 + lr;
            #pragma unroll
            for (int half=0; half<2; half++){
                int m = m0 + half*8;
                float v0 = alpha*acc[mt][nt][half*2+0];
                float v1 = alpha*acc[mt][nt][half*2+1];
                if (route){
                    float rs = route[((m >> 10) << 3) + ((n & 63) >> 3)];
                    v0 *= rs; v1 *= rs;
                }
                if (bias){ v0 += bias[n]; v1 += bias[n+1]; }
                float2* cp = (float2*)(C + (size_t)m*ldc + n);
                if (addC){ float2 o = *cp; v0 += o.x; v1 += o.y; }
                *cp = make_float2(v0, v1);
            }
        }
    }
}

// ---- prep kernels ----
__global__ void prep_xsh(const float* __restrict__ x, float* __restrict__ xsh){
    int idx = blockIdx.x*blockDim.x + threadIdx.x;
    if (idx >= Md*768) return;
    int m = idx / 768, rem = idx - m*768;
    int t = rem >> 8, i4 = rem & 255;
    int b = m >> 10, s = m & 1023;
    int s2 = s + t - 1;
    float4 v = make_float4(0.f,0.f,0.f,0.f);
    if ((unsigned)s2 < 1024u) v = *(const float4*)(x + ((size_t)(b*1024+s2)*1024) + i4*4);
    *(float4*)(xsh + (size_t)m*3072 + t*1024 + i4*4) = v;
}
__global__ void prep_ctK(const float* __restrict__ cw, float* __restrict__ ctK){
    int idx = blockIdx.x*blockDim.x + threadIdx.x;
    if (idx >= Dd*3072) return;
    int o = idx / 3072, rem = idx - o*3072;
    int t = rem >> 10, i = rem & 1023;
    ctK[idx] = cw[(size_t)o*3072 + (size_t)i*3 + t];
}
__global__ void tr_loraB(const float* __restrict__ Bp, float* __restrict__ Bt){
    int idx = blockIdx.x*blockDim.x + threadIdx.x;
    if (idx >= Dd*64) return;
    int n = idx >> 6, e = (idx >> 3) & 7, r = idx & 7;
    Bt[idx] = Bp[(size_t)e*Dd*8 + (size_t)n*8 + r];
}

// ---- router ----
__global__ void scores_k(const float* __restrict__ xp, const float* __restrict__ pw,
                         const float* __restrict__ pb, float* __restrict__ scores){
    int row = blockIdx.x, tid = threadIdx.x;
    const float4* xr = (const float4*)(xp + (size_t)row*Dd);
    const float4* pr = (const float4*)pw;
    float s = 0.f;
    #pragma unroll
    for (int i=0;i<2;i++){
        float4 a = xr[tid*2+i], b = pr[tid*2+i];
        s += a.x*b.x + a.y*b.y + a.z*b.z + a.w*b.w;
    }
    s = warpRedSum(s);
    __shared__ float sm[4];
    if ((tid&31)==0) sm[tid>>5]=s;
    __syncthreads();
    if (tid==0) scores[row] = sm[0]+sm[1]+sm[2]+sm[3] + pb[0];
}
__global__ void softmax_w(const float* __restrict__ scores, float* __restrict__ w){
    int b = blockIdx.x, tid = threadIdx.x;
    float4 v = *(const float4*)(scores + (size_t)b*Sd + tid*4);
    float m = fmaxf(fmaxf(v.x,v.y), fmaxf(v.z,v.w));
    m = warpRedMax(m);
    __shared__ float sm[8];
    __shared__ float gmax, gisum;
    if ((tid&31)==0) sm[tid>>5]=m;
    __syncthreads();
    if (tid==0){ float mm=sm[0]; for(int i=1;i<8;i++) mm=fmaxf(mm,sm[i]); gmax=mm; }
    __syncthreads();
    float e0=expf(v.x-gmax), e1=expf(v.y-gmax), e2=expf(v.z-gmax), e3=expf(v.w-gmax);
    float s = e0+e1+e2+e3;
    s = warpRedSum(s);
    if ((tid&31)==0) sm[tid>>5]=s;
    __syncthreads();
    if (tid==0){ float ss=0; for(int i=0;i<8;i++) ss+=sm[i]; gisum = 1.f/ss; }
    __syncthreads();
    *(float4*)(w + (size_t)b*Sd + tid*4) = make_float4(e0*gisum, e1*gisum, e2*gisum, e3*gisum);
}
__global__ void pooled_k(const float* __restrict__ xp, const float* __restrict__ w,
                         float* __restrict__ pooled){
    int b = blockIdx.y;
    int d = blockIdx.x*128 + threadIdx.x;
    __shared__ float ws[Sd];
    for (int i = threadIdx.x; i < Sd; i += 128) ws[i] = w[(size_t)b*Sd + i];
    __syncthreads();
    float s = 0.f;
    const float* base = xp + (size_t)b*Sd*Dd + d;
    for (int i=0;i<Sd;i++) s = fmaf(ws[i], base[(size_t)i*Dd], s);
    pooled[b*Dd + d] = s;
}
__global__ void route_k(const float* __restrict__ pooled, const float* __restrict__ rw,
                        const float* __restrict__ rb, float* __restrict__ route){
    int tid = threadIdx.x;
    int e = tid >> 5, lane = tid & 31;
    __shared__ float lg[8];
    for (int b=0;b<Bd;b++){
        float s=0.f;
        for (int d=lane; d<Dd; d+=32) s += pooled[b*Dd+d]*rw[e*Dd+d];
        s = warpRedSum(s);
        if (lane==0) lg[e] = s + rb[e];
        __syncthreads();
        if (tid==0){
            float mm=lg[0];
            for (int i=1;i<8;i++) mm=fmaxf(mm,lg[i]);
            float ex[8]; float ss=0.f;
            for (int i=0;i<8;i++){ ex[i]=expf(lg[i]-mm); ss+=ex[i]; }
            float inv = 1.f/ss;
            for (int i=0;i<8;i++) route[b*8+i]=ex[i]*inv;
        }
        __syncthreads();
    }
}

// ---- attention (SIMT softmax+PV) ----
__global__ void row_max_k(const float* __restrict__ qk, float* __restrict__ rowmax){
    int row = blockIdx.x, tid = threadIdx.x;
    const float4* p = (const float4*)(qk + (size_t)row*Sd);
    float4 a = p[tid*2], b = p[tid*2+1];
    float m = fmaxf(fmaxf(fmaxf(a.x,a.y),fmaxf(a.z,a.w)),
                    fmaxf(fmaxf(b.x,b.y),fmaxf(b.z,b.w)));
    m = warpRedMax(m);
    __shared__ float sm[4];
    if ((tid&31)==0) sm[tid>>5]=m;
    __syncthreads();
    if (tid==0) rowmax[row] = fmaxf(fmaxf(sm[0],sm[1]), fmaxf(sm[2],sm[3]));
}

__global__ __launch_bounds__(256) void attn_pv(
    const float* __restrict__ qk, const float* __restrict__ v,
    const float* __restrict__ rowmax, float* __restrict__ wv, float* __restrict__ rowsum)
{
    const int z = blockIdx.z;
    const int bq = z >> 4, h = z & 15;
    const float* Aq = qk + (size_t)z * Sd * Sd;
    const float* Vh = v + (size_t)bq * Sd * Dd + h*DHd;
    float* Cw = wv + (size_t)bq * Sd * Dd + h*DHd;
    const float* rmax = rowmax + (size_t)z*Sd;
    const int bm = blockIdx.y * 128;

    __shared__ __align__(16) float Ps[16][128];
    __shared__ __align__(16) float Vs[16][64];
    __shared__ float Sred[128][4];

    const int tid = threadIdx.x;
    const int tx = tid & 15, ty = tid >> 4;
    const int m0 = tid >> 2;
    const int kq = (tid & 3) * 4;
    const int kv = tid >> 4;
    const int dq = (tid & 15) * 4;

    const float rm0 = rmax[bm + m0];
    const float rm1 = rmax[bm + m0 + 64];

    float acc[8][4];
    #pragma unroll
    for (int i=0;i<8;i++)
        #pragma unroll
        for (int j=0;j<4;j++) acc[i][j]=0.f;
    float ps0 = 0.f, ps1 = 0.f;

    const float* Ar0 = Aq + (size_t)(bm+m0)*Sd + kq;
    const float* Ar1 = Ar0 + (size_t)64*Sd;

    for (int k0=0; k0<Sd; k0+=16){
        float4 a0 = *(const float4*)(Ar0 + k0);
        float4 a1 = *(const float4*)(Ar1 + k0);
        float p00=fexp(a0.x-rm0), p01=fexp(a0.y-rm0), p02=fexp(a0.z-rm0), p03=fexp(a0.w-rm0);
        float p10=fexp(a1.x-rm1), p11=fexp(a1.y-rm1), p12=fexp(a1.z-rm1), p13=fexp(a1.w-rm1);
        Ps[kq+0][m0]=p00; Ps[kq+1][m0]=p01; Ps[kq+2][m0]=p02; Ps[kq+3][m0]=p03;
        Ps[kq+0][m0+64]=p10; Ps[kq+1][m0+64]=p11; Ps[kq+2][m0+64]=p12; Ps[kq+3][m0+64]=p13;
        ps0 += p00+p01+p02+p03;
        ps1 += p10+p11+p12+p13;
        float4 vv = *(const float4*)(Vh + (size_t)(k0+kv)*Dd + dq);
        *(float4*)&Vs[kv][dq] = vv;
        __syncthreads();
        #pragma unroll
        for (int kk=0; kk<16; kk++){
            float a[8], bb[4];
            *(float4*)&a[0] = *(const float4*)&Ps[kk][ty*8];
            *(float4*)&a[4] = *(const float4*)&Ps[kk][ty*8+4];
            *(float4*)&bb[0] = *(const float4*)&Vs[kk][tx*4];
            #pragma unroll
            for (int i=0;i<8;i++)
                #pragma unroll
                for (int j=0;j<4;j++)
                    acc[i][j] = fmaf(a[i], bb[j], acc[i][j]);
        }
        __syncthreads();
    }

    Sred[m0][tid&3] = ps0;
    Sred[m0+64][tid&3] = ps1;
    __syncthreads();
    if (tid < 128)
        rowsum[(size_t)z*Sd + bm + tid] = Sred[tid][0]+Sred[tid][1]+Sred[tid][2]+Sred[tid][3];

    #pragma unroll
    for (int i=0;i<8;i++){
        size_t rowoff = (size_t)(bm + ty*8 + i)*Dd;
        #pragma unroll
        for (int j=0;j<4;j++)
            Cw[rowoff + tx*4 + j] = acc[i][j];
    }
}

__global__ void norm_wv(float* __restrict__ wv, const float* __restrict__ rowsum){
    int m = blockIdx.x;
    int b = m >> 10, i = m & 1023;
    int tid = threadIdx.x;
    __shared__ float inv[16];
    if (tid < 16) inv[tid] = 1.f / rowsum[((size_t)(b*Hd + tid))*Sd + i];
    __syncthreads();
    float4* p = (float4*)(wv + (size_t)m*Dd);
    float4 vv = p[tid];
    float sc = inv[(tid*4) >> 6];
    vv.x*=sc; vv.y*=sc; vv.z*=sc; vv.w*=sc;
    p[tid]=vv;
}

// ---- host launcher ----
extern "C" void kernel_launch(void* const* d_in, const int* in_sizes, int n_in,
                              void* d_out, int out_size)
{
    (void)in_sizes; (void)n_in; (void)out_size;
    const float* x      = (const float*)d_in[0];
    const float* conv_w = (const float*)d_in[1];
    const float* conv_b = (const float*)d_in[2];
    const float* pool_w = (const float*)d_in[3];
    const float* pool_b = (const float*)d_in[4];
    const float* rlin_w = (const float*)d_in[5];
    const float* rlin_b = (const float*)d_in[6];
    const float* qW=(const float*)d_in[7],  *qb=(const float*)d_in[8];
    const float* qA=(const float*)d_in[9],  *qB=(const float*)d_in[10];
    const float* kW=(const float*)d_in[11], *kA=(const float*)d_in[12], *kB=(const float*)d_in[13];
    const float* vW=(const float*)d_in[14], *vb=(const float*)d_in[15];
    const float* vA=(const float*)d_in[16], *vB=(const float*)d_in[17];
    const float* oW=(const float*)d_in[18], *ob=(const float*)d_in[19];
    const float* oA=(const float*)d_in[20], *oB=(const float*)d_in[21];

    float* out = (float*)d_out;
    float* qk  = out + OUT_OFF;

    float *xp,*q,*k,*v,*wv,*h,*xsh,*ctK,*AA,*Bt,*scores,*w,*pooled,*route,*rowmax,*rowsum;
    cudaGetSymbolAddress((void**)&xp, g_xp);
    cudaGetSymbolAddress((void**)&q,  g_q);
    cudaGetSymbolAddress((void**)&k,  g_k);
    cudaGetSymbolAddress((void**)&v,  g_v);
    cudaGetSymbolAddress((void**)&wv, g_wv);
    cudaGetSymbolAddress((void**)&h,  g_h);
    cudaGetSymbolAddress((void**)&xsh, g_xsh);
    cudaGetSymbolAddress((void**)&ctK, g_ctK);
    cudaGetSymbolAddress((void**)&AA,  g_AA);
    cudaGetSymbolAddress((void**)&Bt,  g_Bt);
    cudaGetSymbolAddress((void**)&scores, g_scores);
    cudaGetSymbolAddress((void**)&w,  g_wsm);
    cudaGetSymbolAddress((void**)&pooled, g_pooled);
    cudaGetSymbolAddress((void**)&route,  g_route);
    cudaGetSymbolAddress((void**)&rowmax, g_rowmax);
    cudaGetSymbolAddress((void**)&rowsum, g_rowsum);

    cudaFuncSetAttribute(mma_gemm, cudaFuncAttributeMaxDynamicSharedMemorySize, GEMM_SMEM);

    const long long SD = (long long)Sd*Dd;
    const long long SS = (long long)Sd*Sd;

    prep_xsh<<<(Md*768 + 255)/256, 256>>>(x, xsh);
    prep_ctK<<<(Dd*3072 + 255)/256, 256>>>(conv_w, ctK);
    cudaMemcpyAsync(AA,          qA, (size_t)64*Dd*4, cudaMemcpyDeviceToDevice);
    cudaMemcpyAsync(AA + 64*Dd,  kA, (size_t)64*Dd*4, cudaMemcpyDeviceToDevice);
    cudaMemcpyAsync(AA + 128*Dd, vA, (size_t)64*Dd*4, cudaMemcpyDeviceToDevice);

    // conv as GEMM (K=3072)
    mma_gemm<<<dim3(8,32,1), 256, GEMM_SMEM>>>(xsh, ctK, xp, Md, Dd, 3072, 3072, 3072, Dd,
        0,0,0,0,0,0,1, 1.f, conv_b, nullptr, 0);

    // router
    scores_k<<<Md, 128>>>(xp, pool_w, pool_b, scores);
    softmax_w<<<Bd, 256>>>(scores, w);
    pooled_k<<<dim3(8,Bd), 128>>>(xp, w, pooled);
    route_k<<<1, 256>>>(pooled, rlin_w, rlin_b, route);

    // base projections
    mma_gemm<<<dim3(8,32,1), 256, GEMM_SMEM>>>(x, qW, q, Md, Dd, Dd, Dd, Dd, Dd,
        0,0,0,0,0,0,1, 1.f, qb, nullptr, 0);
    mma_gemm<<<dim3(8,32,1), 256, GEMM_SMEM>>>(x, kW, k, Md, Dd, Dd, Dd, Dd, Dd,
        0,0,0,0,0,0,1, 1.f, nullptr, nullptr, 0);
    mma_gemm<<<dim3(8,32,1), 256, GEMM_SMEM>>>(x, vW, v, Md, Dd, Dd, Dd, Dd, Dd,
        0,0,0,0,0,0,1, 1.f, vb, nullptr, 0);

    // batched LoRA-A for q/k/v (route-scaled): h[4096,192]
    mma_gemm<<<dim3(2,32,1), 256, GEMM_SMEM>>>(x, AA, h, Md, 192, Dd, Dd, Dd, 192,
        0,0,0,0,0,0,1, 1.f, nullptr, route, 0);

    // LoRA-B adds
    const float* Bs_[3] = {qB, kB, vB};
    float* outs[3] = {q, k, v};
    for (int p = 0; p < 3; p++){
        tr_loraB<<<(Dd*64+255)/256, 256>>>(Bs_[p], Bt);
        mma_gemm<<<dim3(8,32,1), 256, GEMM_SMEM>>>(h + p*64, Bt, outs[p], Md, Dd, 64, 192, 64, Dd,
            0,0,0,0,0,0,1, 2.0f, nullptr, nullptr, 1);
    }

    // qk logits into d_out (scale 1/8)
    mma_gemm<<<dim3(8,8,Bd*Hd), 256, GEMM_SMEM>>>(q, k, qk, Sd, Sd, DHd, Dd, Dd, Sd,
        SD, 64, SD, 64, (long long)Hd*SS, SS, Hd, 0.125f, nullptr, nullptr, 0);

    // softmax + PV
    row_max_k<<<Bd*Hd*Sd, 128>>>(qk, rowmax);
    attn_pv<<<dim3(1, Sd/128, Bd*Hd), 256>>>(qk, v, rowmax, wv, rowsum);
    norm_wv<<<Md, 256>>>(wv, rowsum);

    // o projection
    mma_gemm<<<dim3(8,32,1), 256, GEMM_SMEM>>>(wv, oW, out, Md, Dd, Dd, Dd, Dd, Dd,
        0,0,0,0,0,0,1, 1.f, ob, nullptr, 0);
    mma_gemm<<<dim3(1,32,1), 256, GEMM_SMEM>>>(wv, oA, h, Md, 64, Dd, Dd, Dd, 192,
        0,0,0,0,0,0,1, 1.f, nullptr, route, 0);
    tr_loraB<<<(Dd*64+255)/256, 256>>>(oB, Bt);
    mma_gemm<<<dim3(8,32,1), 256, GEMM_SMEM>>>(h, Bt, out, Md, Dd, 64, 192, 64, Dd,
        0,0,0,0,0,0,1, 2.0f, nullptr, nullptr, 1);
}

// round 6
// speedup vs baseline: 2.7830x; 1.0952x over previous
#include <cuda_runtime.h>
#include <cstdint>
#include <cstddef>

#define Bd 4
#define Sd 1024
#define Dd 1024
#define Hd 16
#define DHd 64
#define Md (Bd*Sd)
#define OUT_OFF ((size_t)Bd*Sd*Dd)

__device__ float g_xp[Md*Dd];
__device__ float g_q[Md*Dd];
__device__ float g_k[Md*Dd];
__device__ float g_v[Md*Dd];
__device__ float g_wv[Md*Dd];
__device__ float g_h[Md*192];
__device__ float g_xsh[(size_t)Md*3072];
__device__ float g_ctK[(size_t)Dd*3072];
__device__ float g_AA[192*Dd];
__device__ float g_Bt[Dd*64];
__device__ float g_scores[Md];
__device__ float g_wsm[Md];
__device__ float g_pooled[Bd*Dd];
__device__ float g_route[Bd*8];
__device__ float g_rowmax[Bd*Hd*Sd];

__device__ __forceinline__ float warpRedSum(float v){
    #pragma unroll
    for (int o=16;o;o>>=1) v += __shfl_xor_sync(0xffffffffu, v, o);
    return v;
}
__device__ __forceinline__ float warpRedMax(float v){
    #pragma unroll
    for (int o=16;o;o>>=1) v = fmaxf(v, __shfl_xor_sync(0xffffffffu, v, o));
    return v;
}
__device__ __forceinline__ float fexp(float x){
    float t = x * 1.4426950408889634f;
    t = fmaxf(t, -126.0f);
    float ti = floorf(t);
    float f = t - ti;
    float p = 1.5403530393381608e-4f;
    p = fmaf(p, f, 1.3333558146428443e-3f);
    p = fmaf(p, f, 9.6181291076284770e-3f);
    p = fmaf(p, f, 5.5504108664821580e-2f);
    p = fmaf(p, f, 2.4022650695910070e-1f);
    p = fmaf(p, f, 6.9314718055994530e-1f);
    p = fmaf(p, f, 1.0f);
    return __int_as_float(((int)ti + 127) << 23) * p;
}
__device__ __forceinline__ uint32_t f2tf(float f){
    uint32_t r; asm("cvt.rna.tf32.f32 %0, %1;" : "=r"(r) : "f"(f)); return r;
}
__device__ __forceinline__ void mma8(float* d, const uint32_t* a, const uint32_t* b){
    asm volatile("mma.sync.aligned.m16n8k8.row.col.f32.tf32.tf32.f32 "
        "{%0,%1,%2,%3}, {%4,%5,%6,%7}, {%8,%9}, {%0,%1,%2,%3};"
        : "+f"(d[0]),"+f"(d[1]),"+f"(d[2]),"+f"(d[3])
        : "r"(a[0]),"r"(a[1]),"r"(a[2]),"r"(a[3]), "r"(b[0]),"r"(b[1]));
}

// ---- tf32 mma.sync GEMM: C = alpha*A(MxK)B(NxK)^T [*route][+bias][+C] ----
#define GSTRIDE 36
#define GEMM_SMEM (4*128*GSTRIDE*4)
__global__ __launch_bounds__(256,1)
void mma_gemm(const float* __restrict__ A, const float* __restrict__ B, float* __restrict__ C,
              int M, int N, int K, int lda, int ldb, int ldc,
              long long sAb, long long sAh, long long sBb, long long sBh,
              long long sCb, long long sCh, int ZH,
              float alpha, const float* __restrict__ bias, const float* __restrict__ route, int addC)
{
    extern __shared__ __align__(16) uint32_t sm[];
    uint32_t* As = sm;
    uint32_t* Bs = sm + 2*128*GSTRIDE;

    const int tid = threadIdx.x, wid = tid >> 5, lane = tid & 31;
    const int wm = wid >> 2, wn = wid & 3;
    const int lr = lane >> 2, lc = lane & 3;
    int z = blockIdx.z, zb = z / ZH, zh = z - zb*ZH;
    A += (size_t)zb*sAb + (size_t)zh*sAh;
    B += (size_t)zb*sBb + (size_t)zh*sBh;
    C += (size_t)zb*sCb + (size_t)zh*sCh;
    const int bm = blockIdx.y*128, bn = blockIdx.x*128;

    const int row = tid >> 3, c4 = (tid & 7) << 2;
    const float* Ab = A + (size_t)bm*lda;
    const float* Bb = B + (size_t)bn*ldb;
    const int nch = K >> 5;

    float acc[4][4][4];
    #pragma unroll
    for (int i=0;i<4;i++)
        #pragma unroll
        for (int j=0;j<4;j++)
            #pragma unroll
            for (int r=0;r<4;r++) acc[i][j][r]=0.f;

    {
        #pragma unroll
        for (int j=0;j<4;j++){
            int rr = row + j*32;
            float4 av = *(const float4*)(Ab + (size_t)rr*lda + c4);
            uint32_t* d = As + rr*GSTRIDE + c4;
            d[0]=f2tf(av.x); d[1]=f2tf(av.y); d[2]=f2tf(av.z); d[3]=f2tf(av.w);
            float4 bv = make_float4(0.f,0.f,0.f,0.f);
            if (bn + rr < N) bv = *(const float4*)(Bb + (size_t)rr*ldb + c4);
            uint32_t* e = Bs + rr*GSTRIDE + c4;
            e[0]=f2tf(bv.x); e[1]=f2tf(bv.y); e[2]=f2tf(bv.z); e[3]=f2tf(bv.w);
        }
    }
    __syncthreads();

    for (int c = 0; c < nch; c++){
        const uint32_t* Ac = As + (c&1)*128*GSTRIDE;
        const uint32_t* Bc = Bs + (c&1)*128*GSTRIDE;
        float4 pa[4], pb[4];
        if (c+1 < nch){
            int k0 = (c+1) << 5;
            #pragma unroll
            for (int j=0;j<4;j++){
                int rr = row + j*32;
                pa[j] = *(const float4*)(Ab + (size_t)rr*lda + k0 + c4);
                pb[j] = make_float4(0.f,0.f,0.f,0.f);
                if (bn + rr < N) pb[j] = *(const float4*)(Bb + (size_t)rr*ldb + k0 + c4);
            }
        }
        #pragma unroll
        for (int ks=0; ks<4; ks++){
            uint32_t af[4][4], bf[4][2];
            #pragma unroll
            for (int mt=0; mt<4; mt++){
                const uint32_t* p = Ac + (wm*64 + mt*16)*GSTRIDE + ks*8;
                af[mt][0] = p[lr*GSTRIDE + lc];
                af[mt][1] = p[(lr+8)*GSTRIDE + lc];
                af[mt][2] = p[lr*GSTRIDE + lc + 4];
                af[mt][3] = p[(lr+8)*GSTRIDE + lc + 4];
            }
            #pragma unroll
            for (int nt=0; nt<4; nt++){
                const uint32_t* p = Bc + (wn*32 + nt*8)*GSTRIDE + ks*8;
                bf[nt][0] = p[lr*GSTRIDE + lc];
                bf[nt][1] = p[lr*GSTRIDE + lc + 4];
            }
            #pragma unroll
            for (int mt=0; mt<4; mt++)
                #pragma unroll
                for (int nt=0; nt<4; nt++)
                    mma8(acc[mt][nt], af[mt], bf[nt]);
        }
        if (c+1 < nch){
            uint32_t* An = As + ((c+1)&1)*128*GSTRIDE;
            uint32_t* Bn = Bs + ((c+1)&1)*128*GSTRIDE;
            #pragma unroll
            for (int j=0;j<4;j++){
                int rr = row + j*32;
                uint32_t* d = An + rr*GSTRIDE + c4;
                d[0]=f2tf(pa[j].x); d[1]=f2tf(pa[j].y); d[2]=f2tf(pa[j].z); d[3]=f2tf(pa[j].w);
                uint32_t* e = Bn + rr*GSTRIDE + c4;
                e[0]=f2tf(pb[j].x); e[1]=f2tf(pb[j].y); e[2]=f2tf(pb[j].z); e[3]=f2tf(pb[j].w);
            }
        }
        __syncthreads();
    }

    #pragma unroll
    for (int mt=0; mt<4; mt++){
        #pragma unroll
        for (int nt=0; nt<4; nt++){
            int n = bn + wn*32 + nt*8 + 2*lc;
            if (n >= N) continue;
            int m0 = bm + wm*64 + mt*16 + lr;
            #pragma unroll
            for (int half=0; half<2; half++){
                int m = m0 + half*8;
                float v0 = alpha*acc[mt][nt][half*2+0];
                float v1 = alpha*acc[mt][nt][half*2+1];
                if (route){
                    float rs = route[((m >> 10) << 3) + ((n & 63) >> 3)];
                    v0 *= rs; v1 *= rs;
                }
                if (bias){ v0 += bias[n]; v1 += bias[n+1]; }
                float2* cp = (float2*)(C + (size_t)m*ldc + n);
                if (addC){ float2 o = *cp; v0 += o.x; v1 += o.y; }
                *cp = make_float2(v0, v1);
            }
        }
    }
}

// ---- tensor-core PV with fused softmax-normalize ----
#define PVS 36
#define VVS 72
__global__ __launch_bounds__(256,3) void attn_pv_mma(
    const float* __restrict__ qk, const float* __restrict__ v,
    const float* __restrict__ rowmax, float* __restrict__ wv)
{
    __shared__ __align__(16) uint32_t Ps[128*PVS];
    __shared__ __align__(16) uint32_t Vs[32*VVS];
    __shared__ float rsum[128];
    __shared__ float rinv[128];

    const int z = blockIdx.z;
    const int bq = z >> 4, h = z & 15;
    const int bm = blockIdx.y * 128;
    const float* Aq = qk + (size_t)z*Sd*Sd;
    const float* Vh = v + (size_t)bq*Sd*Dd + h*DHd;
    const int tid = threadIdx.x, wid = tid >> 5, lane = tid & 31;
    const int wm = wid >> 2, wn = wid & 3;
    const int lr = lane >> 2, lc = lane & 3;
    const int pr = tid >> 3, pc4 = (tid & 7) << 2;

    float rmax[4];
    #pragma unroll
    for (int j=0;j<4;j++) rmax[j] = rowmax[(size_t)z*Sd + bm + pr + 32*j];
    float psum[4] = {0.f,0.f,0.f,0.f};

    float acc[4][2][4];
    #pragma unroll
    for (int i=0;i<4;i++)
        #pragma unroll
        for (int j=0;j<2;j++)
            #pragma unroll
            for (int r=0;r<4;r++) acc[i][j][r]=0.f;

    for (int c=0;c<32;c++){
        const int k0 = c << 5;
        #pragma unroll
        for (int j=0;j<4;j++){
            float4 a = *(const float4*)(Aq + (size_t)(bm+pr+32*j)*Sd + k0 + pc4);
            float e0 = fexp(a.x - rmax[j]);
            float e1 = fexp(a.y - rmax[j]);
            float e2 = fexp(a.z - rmax[j]);
            float e3 = fexp(a.w - rmax[j]);
            psum[j] += (e0+e1)+(e2+e3);
            uint32_t* d = Ps + (pr+32*j)*PVS + pc4;
            d[0]=f2tf(e0); d[1]=f2tf(e1); d[2]=f2tf(e2); d[3]=f2tf(e3);
        }
        #pragma unroll
        for (int j=0;j<2;j++){
            int idx = tid + (j << 8);
            int vk = idx >> 4, vc4 = (idx & 15) << 2;
            float4 vv = *(const float4*)(Vh + (size_t)(k0+vk)*Dd + vc4);
            uint32_t* e = Vs + vk*VVS + vc4;
            e[0]=f2tf(vv.x); e[1]=f2tf(vv.y); e[2]=f2tf(vv.z); e[3]=f2tf(vv.w);
        }
        __syncthreads();
        #pragma unroll
        for (int ks=0;ks<4;ks++){
            uint32_t af[4][4], bf[2][2];
            #pragma unroll
            for (int mt=0;mt<4;mt++){
                const uint32_t* p = Ps + (wm*64 + mt*16)*PVS + ks*8;
                af[mt][0] = p[lr*PVS + lc];
                af[mt][1] = p[(lr+8)*PVS + lc];
                af[mt][2] = p[lr*PVS + lc + 4];
                af[mt][3] = p[(lr+8)*PVS + lc + 4];
            }
            #pragma unroll
            for (int nt=0;nt<2;nt++){
                const uint32_t* p = Vs + (ks*8)*VVS + wn*16 + nt*8;
                bf[nt][0] = p[lc*VVS + lr];
                bf[nt][1] = p[(lc+4)*VVS + lr];
            }
            #pragma unroll
            for (int mt=0;mt<4;mt++)
                #pragma unroll
                for (int nt=0;nt<2;nt++)
                    mma8(acc[mt][nt], af[mt], bf[nt]);
        }
        __syncthreads();
    }

    #pragma unroll
    for (int j=0;j<4;j++){
        float s = psum[j];
        s += __shfl_xor_sync(0xffffffffu, s, 1);
        s += __shfl_xor_sync(0xffffffffu, s, 2);
        s += __shfl_xor_sync(0xffffffffu, s, 4);
        if ((tid & 7) == 0) rsum[pr + 32*j] = s;
    }
    __syncthreads();
    if (tid < 128) rinv[tid] = 1.f / rsum[tid];
    __syncthreads();

    float* Cw = wv + (size_t)bq*Sd*Dd + h*DHd;
    #pragma unroll
    for (int mt=0;mt<4;mt++){
        #pragma unroll
        for (int nt=0;nt<2;nt++){
            int n = wn*16 + nt*8 + 2*lc;
            #pragma unroll
            for (int half=0;half<2;half++){
                int row = wm*64 + mt*16 + lr + half*8;
                float inv = rinv[row];
                float v0 = acc[mt][nt][half*2+0] * inv;
                float v1 = acc[mt][nt][half*2+1] * inv;
                *(float2*)(Cw + (size_t)(bm+row)*Dd + n) = make_float2(v0, v1);
            }
        }
    }
}

// ---- prep kernels ----
__global__ void prep_xsh(const float* __restrict__ x, float* __restrict__ xsh){
    int idx = blockIdx.x*blockDim.x + threadIdx.x;
    if (idx >= Md*768) return;
    int m = idx / 768, rem = idx - m*768;
    int t = rem >> 8, i4 = rem & 255;
    int b = m >> 10, s = m & 1023;
    int s2 = s + t - 1;
    float4 v = make_float4(0.f,0.f,0.f,0.f);
    if ((unsigned)s2 < 1024u) v = *(const float4*)(x + ((size_t)(b*1024+s2)*1024) + i4*4);
    *(float4*)(xsh + (size_t)m*3072 + t*1024 + i4*4) = v;
}
__global__ void prep_ctK(const float* __restrict__ cw, float* __restrict__ ctK){
    int idx = blockIdx.x*blockDim.x + threadIdx.x;
    if (idx >= Dd*3072) return;
    int o = idx / 3072, rem = idx - o*3072;
    int t = rem >> 10, i = rem & 1023;
    ctK[idx] = cw[(size_t)o*3072 + (size_t)i*3 + t];
}
__global__ void tr_loraB(const float* __restrict__ Bp, float* __restrict__ Bt){
    int idx = blockIdx.x*blockDim.x + threadIdx.x;
    if (idx >= Dd*64) return;
    int n = idx >> 6, e = (idx >> 3) & 7, r = idx & 7;
    Bt[idx] = Bp[(size_t)e*Dd*8 + (size_t)n*8 + r];
}

// ---- router ----
__global__ void scores_k(const float* __restrict__ xp, const float* __restrict__ pw,
                         const float* __restrict__ pb, float* __restrict__ scores){
    int row = blockIdx.x, tid = threadIdx.x;
    const float4* xr = (const float4*)(xp + (size_t)row*Dd);
    const float4* pr = (const float4*)pw;
    float s = 0.f;
    #pragma unroll
    for (int i=0;i<2;i++){
        float4 a = xr[tid*2+i], b = pr[tid*2+i];
        s += a.x*b.x + a.y*b.y + a.z*b.z + a.w*b.w;
    }
    s = warpRedSum(s);
    __shared__ float sm[4];
    if ((tid&31)==0) sm[tid>>5]=s;
    __syncthreads();
    if (tid==0) scores[row] = sm[0]+sm[1]+sm[2]+sm[3] + pb[0];
}
__global__ void softmax_w(const float* __restrict__ scores, float* __restrict__ w){
    int b = blockIdx.x, tid = threadIdx.x;
    float4 v = *(const float4*)(scores + (size_t)b*Sd + tid*4);
    float m = fmaxf(fmaxf(v.x,v.y), fmaxf(v.z,v.w));
    m = warpRedMax(m);
    __shared__ float sm[8];
    __shared__ float gmax, gisum;
    if ((tid&31)==0) sm[tid>>5]=m;
    __syncthreads();
    if (tid==0){ float mm=sm[0]; for(int i=1;i<8;i++) mm=fmaxf(mm,sm[i]); gmax=mm; }
    __syncthreads();
    float e0=expf(v.x-gmax), e1=expf(v.y-gmax), e2=expf(v.z-gmax), e3=expf(v.w-gmax);
    float s = e0+e1+e2+e3;
    s = warpRedSum(s);
    if ((tid&31)==0) sm[tid>>5]=s;
    __syncthreads();
    if (tid==0){ float ss=0; for(int i=0;i<8;i++) ss+=sm[i]; gisum = 1.f/ss; }
    __syncthreads();
    *(float4*)(w + (size_t)b*Sd + tid*4) = make_float4(e0*gisum, e1*gisum, e2*gisum, e3*gisum);
}
__global__ void pooled_k(const float* __restrict__ xp, const float* __restrict__ w,
                         float* __restrict__ pooled){
    int b = blockIdx.y;
    int d = blockIdx.x*128 + threadIdx.x;
    __shared__ float ws[Sd];
    for (int i = threadIdx.x; i < Sd; i += 128) ws[i] = w[(size_t)b*Sd + i];
    __syncthreads();
    float s = 0.f;
    const float* base = xp + (size_t)b*Sd*Dd + d;
    for (int i=0;i<Sd;i++) s = fmaf(ws[i], base[(size_t)i*Dd], s);
    pooled[b*Dd + d] = s;
}
__global__ void route_k(const float* __restrict__ pooled, const float* __restrict__ rw,
                        const float* __restrict__ rb, float* __restrict__ route){
    int tid = threadIdx.x;
    int e = tid >> 5, lane = tid & 31;
    __shared__ float lg[8];
    for (int b=0;b<Bd;b++){
        float s=0.f;
        for (int d=lane; d<Dd; d+=32) s += pooled[b*Dd+d]*rw[e*Dd+d];
        s = warpRedSum(s);
        if (lane==0) lg[e] = s + rb[e];
        __syncthreads();
        if (tid==0){
            float mm=lg[0];
            for (int i=1;i<8;i++) mm=fmaxf(mm,lg[i]);
            float ex[8]; float ss=0.f;
            for (int i=0;i<8;i++){ ex[i]=expf(lg[i]-mm); ss+=ex[i]; }
            float inv = 1.f/ss;
            for (int i=0;i<8;i++) route[b*8+i]=ex[i]*inv;
        }
        __syncthreads();
    }
}

// ---- row max: one warp per row ----
__global__ __launch_bounds__(256) void row_max_w(const float* __restrict__ qk, float* __restrict__ rowmax){
    int row = blockIdx.x*8 + (threadIdx.x >> 5);
    int lane = threadIdx.x & 31;
    const float4* p = (const float4*)(qk + (size_t)row*Sd);
    float m = -1e30f;
    #pragma unroll
    for (int i=0;i<8;i++){
        float4 a = p[lane + i*32];
        m = fmaxf(m, fmaxf(fmaxf(a.x,a.y), fmaxf(a.z,a.w)));
    }
    m = warpRedMax(m);
    if (lane == 0) rowmax[row] = m;
}

// ---- host launcher ----
extern "C" void kernel_launch(void* const* d_in, const int* in_sizes, int n_in,
                              void* d_out, int out_size)
{
    (void)in_sizes; (void)n_in; (void)out_size;
    const float* x      = (const float*)d_in[0];
    const float* conv_w = (const float*)d_in[1];
    const float* conv_b = (const float*)d_in[2];
    const float* pool_w = (const float*)d_in[3];
    const float* pool_b = (const float*)d_in[4];
    const float* rlin_w = (const float*)d_in[5];
    const float* rlin_b = (const float*)d_in[6];
    const float* qW=(const float*)d_in[7],  *qb=(const float*)d_in[8];
    const float* qA=(const float*)d_in[9],  *qB=(const float*)d_in[10];
    const float* kW=(const float*)d_in[11], *kA=(const float*)d_in[12], *kB=(const float*)d_in[13];
    const float* vW=(const float*)d_in[14], *vb=(const float*)d_in[15];
    const float* vA=(const float*)d_in[16], *vB=(const float*)d_in[17];
    const float* oW=(const float*)d_in[18], *ob=(const float*)d_in[19];
    const float* oA=(const float*)d_in[20], *oB=(const float*)d_in[21];

    float* out = (float*)d_out;
    float* qk  = out + OUT_OFF;

    float *xp,*q,*k,*v,*wv,*h,*xsh,*ctK,*AA,*Bt,*scores,*w,*pooled,*route,*rowmax;
    cudaGetSymbolAddress((void**)&xp, g_xp);
    cudaGetSymbolAddress((void**)&q,  g_q);
    cudaGetSymbolAddress((void**)&k,  g_k);
    cudaGetSymbolAddress((void**)&v,  g_v);
    cudaGetSymbolAddress((void**)&wv, g_wv);
    cudaGetSymbolAddress((void**)&h,  g_h);
    cudaGetSymbolAddress((void**)&xsh, g_xsh);
    cudaGetSymbolAddress((void**)&ctK, g_ctK);
    cudaGetSymbolAddress((void**)&AA,  g_AA);
    cudaGetSymbolAddress((void**)&Bt,  g_Bt);
    cudaGetSymbolAddress((void**)&scores, g_scores);
    cudaGetSymbolAddress((void**)&w,  g_wsm);
    cudaGetSymbolAddress((void**)&pooled, g_pooled);
    cudaGetSymbolAddress((void**)&route,  g_route);
    cudaGetSymbolAddress((void**)&rowmax, g_rowmax);

    cudaFuncSetAttribute(mma_gemm, cudaFuncAttributeMaxDynamicSharedMemorySize, GEMM_SMEM);

    const long long SD = (long long)Sd*Dd;
    const long long SS = (long long)Sd*Sd;

    prep_xsh<<<(Md*768 + 255)/256, 256>>>(x, xsh);
    prep_ctK<<<(Dd*3072 + 255)/256, 256>>>(conv_w, ctK);
    cudaMemcpyAsync(AA,          qA, (size_t)64*Dd*4, cudaMemcpyDeviceToDevice);
    cudaMemcpyAsync(AA + 64*Dd,  kA, (size_t)64*Dd*4, cudaMemcpyDeviceToDevice);
    cudaMemcpyAsync(AA + 128*Dd, vA, (size_t)64*Dd*4, cudaMemcpyDeviceToDevice);

    // conv as GEMM (K=3072)
    mma_gemm<<<dim3(8,32,1), 256, GEMM_SMEM>>>(xsh, ctK, xp, Md, Dd, 3072, 3072, 3072, Dd,
        0,0,0,0,0,0,1, 1.f, conv_b, nullptr, 0);

    // router
    scores_k<<<Md, 128>>>(xp, pool_w, pool_b, scores);
    softmax_w<<<Bd, 256>>>(scores, w);
    pooled_k<<<dim3(8,Bd), 128>>>(xp, w, pooled);
    route_k<<<1, 256>>>(pooled, rlin_w, rlin_b, route);

    // base projections
    mma_gemm<<<dim3(8,32,1), 256, GEMM_SMEM>>>(x, qW, q, Md, Dd, Dd, Dd, Dd, Dd,
        0,0,0,0,0,0,1, 1.f, qb, nullptr, 0);
    mma_gemm<<<dim3(8,32,1), 256, GEMM_SMEM>>>(x, kW, k, Md, Dd, Dd, Dd, Dd, Dd,
        0,0,0,0,0,0,1, 1.f, nullptr, nullptr, 0);
    mma_gemm<<<dim3(8,32,1), 256, GEMM_SMEM>>>(x, vW, v, Md, Dd, Dd, Dd, Dd, Dd,
        0,0,0,0,0,0,1, 1.f, vb, nullptr, 0);

    // batched LoRA-A for q/k/v (route-scaled): h[4096,192]
    mma_gemm<<<dim3(2,32,1), 256, GEMM_SMEM>>>(x, AA, h, Md, 192, Dd, Dd, Dd, 192,
        0,0,0,0,0,0,1, 1.f, nullptr, route, 0);

    // LoRA-B adds
    const float* Bs_[3] = {qB, kB, vB};
    float* outs[3] = {q, k, v};
    for (int p = 0; p < 3; p++){
        tr_loraB<<<(Dd*64+255)/256, 256>>>(Bs_[p], Bt);
        mma_gemm<<<dim3(8,32,1), 256, GEMM_SMEM>>>(h + p*64, Bt, outs[p], Md, Dd, 64, 192, 64, Dd,
            0,0,0,0,0,0,1, 2.0f, nullptr, nullptr, 1);
    }

    // qk logits into d_out (scale 1/8)
    mma_gemm<<<dim3(8,8,Bd*Hd), 256, GEMM_SMEM>>>(q, k, qk, Sd, Sd, DHd, Dd, Dd, Sd,
        SD, 64, SD, 64, (long long)Hd*SS, SS, Hd, 0.125f, nullptr, nullptr, 0);

    // softmax + PV (tensor cores, fused normalize)
    row_max_w<<<Bd*Hd*Sd/8, 256>>>(qk, rowmax);
    attn_pv_mma<<<dim3(1, Sd/128, Bd*Hd), 256>>>(qk, v, rowmax, wv);

    // o projection
    mma_gemm<<<dim3(8,32,1), 256, GEMM_SMEM>>>(wv, oW, out, Md, Dd, Dd, Dd, Dd, Dd,
        0,0,0,0,0,0,1, 1.f, ob, nullptr, 0);
    mma_gemm<<<dim3(1,32,1), 256, GEMM_SMEM>>>(wv, oA, h, Md, 64, Dd, Dd, Dd, 192,
        0,0,0,0,0,0,1, 1.f, nullptr, route, 0);
    tr_loraB<<<(Dd*64+255)/256, 256>>>(oB, Bt);
    mma_gemm<<<dim3(8,32,1), 256, GEMM_SMEM>>>(h, Bt, out, Md, Dd, 64, 192, 64, Dd,
        0,0,0,0,0,0,1, 2.0f, nullptr, nullptr, 1);
}

// round 7
// speedup vs baseline: 3.1141x; 1.1190x over previous
#include <cuda_runtime.h>
#include <cstdint>
#include <cstddef>

#define Bd 4
#define Sd 1024
#define Dd 1024
#define Hd 16
#define DHd 64
#define Md (Bd*Sd)
#define OUT_OFF ((size_t)Bd*Sd*Dd)

__device__ float g_xp[Md*Dd];
__device__ float g_qkv[(size_t)Md*3072];
__device__ float g_wv[Md*Dd];
__device__ float g_h[Md*192];
__device__ float g_xsh[(size_t)Md*3072];
__device__ float g_ctK[(size_t)Dd*3072];
__device__ float g_W3[(size_t)3072*Dd];
__device__ float g_b3[3072];
__device__ float g_AA[192*Dd];
__device__ float g_Bt3[3*Dd*64];
__device__ float g_Bt[Dd*64];
__device__ float g_scores[Md];
__device__ float g_wsm[Md];
__device__ float g_pooled[Bd*Dd];
__device__ float g_route[Bd*8];

__device__ __forceinline__ float warpRedSum(float v){
    #pragma unroll
    for (int o=16;o;o>>=1) v += __shfl_xor_sync(0xffffffffu, v, o);
    return v;
}
__device__ __forceinline__ float warpRedMax(float v){
    #pragma unroll
    for (int o=16;o;o>>=1) v = fmaxf(v, __shfl_xor_sync(0xffffffffu, v, o));
    return v;
}
__device__ __forceinline__ float fexp(float x){
    float t = x * 1.4426950408889634f;
    t = fmaxf(t, -126.0f);
    float ti = floorf(t);
    float f = t - ti;
    float p = 1.5403530393381608e-4f;
    p = fmaf(p, f, 1.3333558146428443e-3f);
    p = fmaf(p, f, 9.6181291076284770e-3f);
    p = fmaf(p, f, 5.5504108664821580e-2f);
    p = fmaf(p, f, 2.4022650695910070e-1f);
    p = fmaf(p, f, 6.9314718055994530e-1f);
    p = fmaf(p, f, 1.0f);
    return __int_as_float(((int)ti + 127) << 23) * p;
}
__device__ __forceinline__ uint32_t f2tf(float f){
    uint32_t r; asm("cvt.rna.tf32.f32 %0, %1;" : "=r"(r) : "f"(f)); return r;
}
__device__ __forceinline__ void mma8(float* d, const uint32_t* a, const uint32_t* b){
    asm volatile("mma.sync.aligned.m16n8k8.row.col.f32.tf32.tf32.f32 "
        "{%0,%1,%2,%3}, {%4,%5,%6,%7}, {%8,%9}, {%0,%1,%2,%3};"
        : "+f"(d[0]),"+f"(d[1]),"+f"(d[2]),"+f"(d[3])
        : "r"(a[0]),"r"(a[1]),"r"(a[2]),"r"(a[3]), "r"(b[0]),"r"(b[1]));
}

// ---- tf32 mma.sync GEMM: C = alpha*A(MxK)B(NxK)^T [*route][+bias][+C] ----
#define GSTRIDE 36
#define GEMM_SMEM (4*128*GSTRIDE*4)
__global__ __launch_bounds__(256,1)
void mma_gemm(const float* __restrict__ A, const float* __restrict__ B, float* __restrict__ C,
              int M, int N, int K, int lda, int ldb, int ldc,
              long long sAb, long long sAh, long long sBb, long long sBh,
              long long sCb, long long sCh, int ZH,
              float alpha, const float* __restrict__ bias, const float* __restrict__ route, int addC)
{
    extern __shared__ __align__(16) uint32_t sm[];
    uint32_t* As = sm;
    uint32_t* Bs = sm + 2*128*GSTRIDE;

    const int tid = threadIdx.x, wid = tid >> 5, lane = tid & 31;
    const int wm = wid >> 2, wn = wid & 3;
    const int lr = lane >> 2, lc = lane & 3;
    int z = blockIdx.z, zb = z / ZH, zh = z - zb*ZH;
    A += (size_t)zb*sAb + (size_t)zh*sAh;
    B += (size_t)zb*sBb + (size_t)zh*sBh;
    C += (size_t)zb*sCb + (size_t)zh*sCh;
    const int bm = blockIdx.y*128, bn = blockIdx.x*128;

    const int row = tid >> 3, c4 = (tid & 7) << 2;
    const float* Ab = A + (size_t)bm*lda;
    const float* Bb = B + (size_t)bn*ldb;
    const int nch = K >> 5;

    float acc[4][4][4];
    #pragma unroll
    for (int i=0;i<4;i++)
        #pragma unroll
        for (int j=0;j<4;j++)
            #pragma unroll
            for (int r=0;r<4;r++) acc[i][j][r]=0.f;

    {
        #pragma unroll
        for (int j=0;j<4;j++){
            int rr = row + j*32;
            float4 av = *(const float4*)(Ab + (size_t)rr*lda + c4);
            uint32_t* d = As + rr*GSTRIDE + c4;
            d[0]=f2tf(av.x); d[1]=f2tf(av.y); d[2]=f2tf(av.z); d[3]=f2tf(av.w);
            float4 bv = make_float4(0.f,0.f,0.f,0.f);
            if (bn + rr < N) bv = *(const float4*)(Bb + (size_t)rr*ldb + c4);
            uint32_t* e = Bs + rr*GSTRIDE + c4;
            e[0]=f2tf(bv.x); e[1]=f2tf(bv.y); e[2]=f2tf(bv.z); e[3]=f2tf(bv.w);
        }
    }
    __syncthreads();

    for (int c = 0; c < nch; c++){
        const uint32_t* Ac = As + (c&1)*128*GSTRIDE;
        const uint32_t* Bc = Bs + (c&1)*128*GSTRIDE;
        float4 pa[4], pb[4];
        if (c+1 < nch){
            int k0 = (c+1) << 5;
            #pragma unroll
            for (int j=0;j<4;j++){
                int rr = row + j*32;
                pa[j] = *(const float4*)(Ab + (size_t)rr*lda + k0 + c4);
                pb[j] = make_float4(0.f,0.f,0.f,0.f);
                if (bn + rr < N) pb[j] = *(const float4*)(Bb + (size_t)rr*ldb + k0 + c4);
            }
        }
        #pragma unroll
        for (int ks=0; ks<4; ks++){
            uint32_t af[4][4], bf[4][2];
            #pragma unroll
            for (int mt=0; mt<4; mt++){
                const uint32_t* p = Ac + (wm*64 + mt*16)*GSTRIDE + ks*8;
                af[mt][0] = p[lr*GSTRIDE + lc];
                af[mt][1] = p[(lr+8)*GSTRIDE + lc];
                af[mt][2] = p[lr*GSTRIDE + lc + 4];
                af[mt][3] = p[(lr+8)*GSTRIDE + lc + 4];
            }
            #pragma unroll
            for (int nt=0; nt<4; nt++){
                const uint32_t* p = Bc + (wn*32 + nt*8)*GSTRIDE + ks*8;
                bf[nt][0] = p[lr*GSTRIDE + lc];
                bf[nt][1] = p[lr*GSTRIDE + lc + 4];
            }
            #pragma unroll
            for (int mt=0; mt<4; mt++)
                #pragma unroll
                for (int nt=0; nt<4; nt++)
                    mma8(acc[mt][nt], af[mt], bf[nt]);
        }
        if (c+1 < nch){
            uint32_t* An = As + ((c+1)&1)*128*GSTRIDE;
            uint32_t* Bn = Bs + ((c+1)&1)*128*GSTRIDE;
            #pragma unroll
            for (int j=0;j<4;j++){
                int rr = row + j*32;
                uint32_t* d = An + rr*GSTRIDE + c4;
                d[0]=f2tf(pa[j].x); d[1]=f2tf(pa[j].y); d[2]=f2tf(pa[j].z); d[3]=f2tf(pa[j].w);
                uint32_t* e = Bn + rr*GSTRIDE + c4;
                e[0]=f2tf(pb[j].x); e[1]=f2tf(pb[j].y); e[2]=f2tf(pb[j].z); e[3]=f2tf(pb[j].w);
            }
        }
        __syncthreads();
    }

    #pragma unroll
    for (int mt=0; mt<4; mt++){
        #pragma unroll
        for (int nt=0; nt<4; nt++){
            int n = bn + wn*32 + nt*8 + 2*lc;
            if (n >= N) continue;
            int m0 = bm + wm*64 + mt*16 + lr;
            #pragma unroll
            for (int half=0; half<2; half++){
                int m = m0 + half*8;
                float v0 = alpha*acc[mt][nt][half*2+0];
                float v1 = alpha*acc[mt][nt][half*2+1];
                if (route){
                    float rs = route[((m >> 10) << 3) + ((n & 63) >> 3)];
                    v0 *= rs; v1 *= rs;
                }
                if (bias){ v0 += bias[n]; v1 += bias[n+1]; }
                float2* cp = (float2*)(C + (size_t)m*ldc + n);
                if (addC){ float2 o = *cp; v0 += o.x; v1 += o.y; }
                *cp = make_float2(v0, v1);
            }
        }
    }
}

// ---- fused flash attention: qk logits out + online softmax + PV ----
#define AQS 36
#define AVS 72
#define AFS_QS 0
#define AFS_KS (2*128*AQS)
#define AFS_VS (AFS_KS + 2*128*AQS)
#define AFS_PS (AFS_VS + 4*32*AVS)
#define AFS_SM (AFS_PS + 128*132)
#define ATTN_SMEM ((AFS_SM + 1024)*4)
__global__ __launch_bounds__(256,1) void attn_fused(
    const float* __restrict__ qkv, float* __restrict__ qk, float* __restrict__ wv)
{
    extern __shared__ __align__(16) uint32_t dsm[];
    uint32_t* Qs = dsm + AFS_QS;
    uint32_t* Ks = dsm + AFS_KS;
    uint32_t* Vs = dsm + AFS_VS;
    uint32_t* Ps = dsm + AFS_PS;
    float* Smax = (float*)(dsm + AFS_SM);
    float* Ssum = Smax + 512;

    const int z = blockIdx.y;
    const int bq = z >> 4, h = z & 15;
    const int bm = blockIdx.x * 128;
    const float* Qg = qkv + (size_t)bq*Sd*3072 + h*64;
    const float* Kg = Qg + 1024;
    const float* Vg = Qg + 2048;
    float* qko = qk + (size_t)z*Sd*Sd;

    const int tid = threadIdx.x, wid = tid >> 5, lane = tid & 31;
    const int wm = wid >> 5 ? 0 : (wid >> 2), wn = wid & 3;
    const int lr = lane >> 2, lc = lane & 3;
    const int rr0 = tid >> 3, c4 = (tid & 7) << 2;

    // load Q tile [128 x 64] as 2 chunks of 32 cols
    #pragma unroll
    for (int j=0;j<4;j++){
        int rr = rr0 + j*32;
        #pragma unroll
        for (int ch=0;ch<2;ch++){
            float4 qv = *(const float4*)(Qg + (size_t)(bm+rr)*3072 + ch*32 + c4);
            uint32_t* d = Qs + ch*128*AQS + rr*AQS + c4;
            d[0]=f2tf(qv.x); d[1]=f2tf(qv.y); d[2]=f2tf(qv.z); d[3]=f2tf(qv.w);
        }
    }

    float runmax[4][2], runsum[4][2];
    #pragma unroll
    for (int i=0;i<4;i++){ runmax[i][0]=-1e30f; runmax[i][1]=-1e30f; runsum[i][0]=0.f; runsum[i][1]=0.f; }
    float pvacc[4][2][4];
    #pragma unroll
    for (int i=0;i<4;i++)
        #pragma unroll
        for (int j=0;j<2;j++)
            #pragma unroll
            for (int r=0;r<4;r++) pvacc[i][j][r]=0.f;

    for (int ct=0; ct<8; ct++){
        const int kb = ct*128;
        // load K tile
        #pragma unroll
        for (int j=0;j<4;j++){
            int rr = rr0 + j*32;
            #pragma unroll
            for (int ch=0;ch<2;ch++){
                float4 kv = *(const float4*)(Kg + (size_t)(kb+rr)*3072 + ch*32 + c4);
                uint32_t* d = Ks + ch*128*AQS + rr*AQS + c4;
                d[0]=f2tf(kv.x); d[1]=f2tf(kv.y); d[2]=f2tf(kv.z); d[3]=f2tf(kv.w);
            }
        }
        // load V tile [128k x 64n] into 4 chunks [32][72]
        #pragma unroll
        for (int j=0;j<8;j++){
            int idx = tid + (j << 8);
            int vk = idx >> 4, vc4 = (idx & 15) << 2;
            float4 vv = *(const float4*)(Vg + (size_t)(kb+vk)*3072 + vc4);
            uint32_t* e = Vs + (vk>>5)*32*AVS + (vk&31)*AVS + vc4;
            e[0]=f2tf(vv.x); e[1]=f2tf(vv.y); e[2]=f2tf(vv.z); e[3]=f2tf(vv.w);
        }
        __syncthreads();

        // S = Q K^T
        float sacc[4][4][4];
        #pragma unroll
        for (int i=0;i<4;i++)
            #pragma unroll
            for (int j=0;j<4;j++)
                #pragma unroll
                for (int r=0;r<4;r++) sacc[i][j][r]=0.f;
        #pragma unroll
        for (int ch=0;ch<2;ch++){
            const uint32_t* Qc = Qs + ch*128*AQS;
            const uint32_t* Kc = Ks + ch*128*AQS;
            #pragma unroll
            for (int ks=0;ks<4;ks++){
                uint32_t af[4][4], bf[4][2];
                #pragma unroll
                for (int mt=0;mt<4;mt++){
                    const uint32_t* p = Qc + (wm*64 + mt*16)*AQS + ks*8;
                    af[mt][0] = p[lr*AQS + lc];
                    af[mt][1] = p[(lr+8)*AQS + lc];
                    af[mt][2] = p[lr*AQS + lc + 4];
                    af[mt][3] = p[(lr+8)*AQS + lc + 4];
                }
                #pragma unroll
                for (int nt=0;nt<4;nt++){
                    const uint32_t* p = Kc + (wn*32 + nt*8)*AQS + ks*8;
                    bf[nt][0] = p[lr*AQS + lc];
                    bf[nt][1] = p[lr*AQS + lc + 4];
                }
                #pragma unroll
                for (int mt=0;mt<4;mt++)
                    #pragma unroll
                    for (int nt=0;nt<4;nt++)
                        mma8(sacc[mt][nt], af[mt], bf[nt]);
            }
        }
        // scale + write qk logits
        #pragma unroll
        for (int mt=0;mt<4;mt++)
            #pragma unroll
            for (int nt=0;nt<4;nt++){
                #pragma unroll
                for (int r=0;r<4;r++) sacc[mt][nt][r] *= 0.125f;
                int n = kb + wn*32 + nt*8 + 2*lc;
                int m0 = bm + wm*64 + mt*16 + lr;
                *(float2*)(qko + (size_t)m0*Sd + n)     = make_float2(sacc[mt][nt][0], sacc[mt][nt][1]);
                *(float2*)(qko + (size_t)(m0+8)*Sd + n) = make_float2(sacc[mt][nt][2], sacc[mt][nt][3]);
            }
        // tile row max -> smem
        #pragma unroll
        for (int mt=0;mt<4;mt++)
            #pragma unroll
            for (int half=0;half<2;half++){
                float tm = -1e30f;
                #pragma unroll
                for (int nt=0;nt<4;nt++)
                    tm = fmaxf(tm, fmaxf(sacc[mt][nt][half*2], sacc[mt][nt][half*2+1]));
                tm = fmaxf(tm, __shfl_xor_sync(0xffffffffu, tm, 1));
                tm = fmaxf(tm, __shfl_xor_sync(0xffffffffu, tm, 2));
                if (lc == 0) Smax[(wm*64 + mt*16 + half*8 + lr)*4 + wn] = tm;
            }
        __syncthreads();
        // online softmax update, P into Ps
        #pragma unroll
        for (int mt=0;mt<4;mt++)
            #pragma unroll
            for (int half=0;half<2;half++){
                int row = wm*64 + mt*16 + half*8 + lr;
                const float* sp = Smax + row*4;
                float tm = fmaxf(fmaxf(sp[0],sp[1]), fmaxf(sp[2],sp[3]));
                float mn = fmaxf(runmax[mt][half], tm);
                float f = fexp(runmax[mt][half] - mn);
                runmax[mt][half] = mn;
                runsum[mt][half] *= f;
                #pragma unroll
                for (int nt=0;nt<2;nt++){
                    pvacc[mt][nt][half*2+0] *= f;
                    pvacc[mt][nt][half*2+1] *= f;
                }
                float s = 0.f;
                #pragma unroll
                for (int nt=0;nt<4;nt++){
                    float p0 = fexp(sacc[mt][nt][half*2+0] - mn);
                    float p1 = fexp(sacc[mt][nt][half*2+1] - mn);
                    s += p0 + p1;
                    sacc[mt][nt][half*2+0] = p0;
                    sacc[mt][nt][half*2+1] = p1;
                    uint32_t* pp = Ps + row*132 + wn*32 + nt*8 + 2*lc;
                    pp[0] = f2tf(p0); pp[1] = f2tf(p1);
                }
                s += __shfl_xor_sync(0xffffffffu, s, 1);
                s += __shfl_xor_sync(0xffffffffu, s, 2);
                if (lc == 0) Ssum[row*4 + wn] = s;
            }
        __syncthreads();
        #pragma unroll
        for (int mt=0;mt<4;mt++)
            #pragma unroll
            for (int half=0;half<2;half++){
                int row = wm*64 + mt*16 + half*8 + lr;
                const float* sp = Ssum + row*4;
                runsum[mt][half] += sp[0]+sp[1]+sp[2]+sp[3];
            }
        // PV: pvacc += P[128x128] * V[128x64]
        #pragma unroll
        for (int ks=0;ks<16;ks++){
            uint32_t af[4][4], bf[2][2];
            #pragma unroll
            for (int mt=0;mt<4;mt++){
                const uint32_t* p = Ps + (wm*64 + mt*16)*132 + ks*8;
                af[mt][0] = p[lr*132 + lc];
                af[mt][1] = p[(lr+8)*132 + lc];
                af[mt][2] = p[lr*132 + lc + 4];
                af[mt][3] = p[(lr+8)*132 + lc + 4];
            }
            #pragma unroll
            for (int nt=0;nt<2;nt++){
                const uint32_t* p = Vs + (ks>>2)*32*AVS + ((ks&3)*8)*AVS + wn*16 + nt*8;
                bf[nt][0] = p[lc*AVS + lr];
                bf[nt][1] = p[(lc+4)*AVS + lr];
            }
            #pragma unroll
            for (int mt=0;mt<4;mt++)
                #pragma unroll
                for (int nt=0;nt<2;nt++)
                    mma8(pvacc[mt][nt], af[mt], bf[nt]);
        }
        __syncthreads();
    }

    // normalize + write wv
    float* Cw = wv + (size_t)bq*Sd*Dd + h*DHd;
    #pragma unroll
    for (int mt=0;mt<4;mt++)
        #pragma unroll
        for (int half=0;half<2;half++){
            int row = wm*64 + mt*16 + half*8 + lr;
            float inv = 1.f / runsum[mt][half];
            #pragma unroll
            for (int nt=0;nt<2;nt++){
                int n = wn*16 + nt*8 + 2*lc;
                *(float2*)(Cw + (size_t)(bm+row)*Dd + n) =
                    make_float2(pvacc[mt][nt][half*2]*inv, pvacc[mt][nt][half*2+1]*inv);
            }
        }
}

// ---- prep kernels ----
__global__ void prep_xsh(const float* __restrict__ x, float* __restrict__ xsh){
    int idx = blockIdx.x*blockDim.x + threadIdx.x;
    if (idx >= Md*768) return;
    int m = idx / 768, rem = idx - m*768;
    int t = rem >> 8, i4 = rem & 255;
    int b = m >> 10, s = m & 1023;
    int s2 = s + t - 1;
    float4 v = make_float4(0.f,0.f,0.f,0.f);
    if ((unsigned)s2 < 1024u) v = *(const float4*)(x + ((size_t)(b*1024+s2)*1024) + i4*4);
    *(float4*)(xsh + (size_t)m*3072 + t*1024 + i4*4) = v;
}
__global__ void prep_ctK(const float* __restrict__ cw, float* __restrict__ ctK){
    int idx = blockIdx.x*blockDim.x + threadIdx.x;
    if (idx >= Dd*3072) return;
    int o = idx / 3072, rem = idx - o*3072;
    int t = rem >> 10, i = rem & 1023;
    ctK[idx] = cw[(size_t)o*3072 + (size_t)i*3 + t];
}
__global__ void tr_loraB3(const float* __restrict__ B0, const float* __restrict__ B1,
                          const float* __restrict__ B2, float* __restrict__ Bt){
    int idx = blockIdx.x*blockDim.x + threadIdx.x;
    if (idx >= 3*Dd*64) return;
    int zz = idx >> 16, rem = idx & 65535;
    int n = rem >> 6, e = (rem >> 3) & 7, r = rem & 7;
    const float* Bp = (zz==0) ? B0 : (zz==1 ? B1 : B2);
    Bt[idx] = Bp[(size_t)e*Dd*8 + (size_t)n*8 + r];
}
__global__ void tr_loraB(const float* __restrict__ Bp, float* __restrict__ Bt){
    int idx = blockIdx.x*blockDim.x + threadIdx.x;
    if (idx >= Dd*64) return;
    int n = idx >> 6, e = (idx >> 3) & 7, r = idx & 7;
    Bt[idx] = Bp[(size_t)e*Dd*8 + (size_t)n*8 + r];
}
__global__ void fill_b3(const float* __restrict__ qb, const float* __restrict__ vb,
                        float* __restrict__ b3){
    int i = blockIdx.x*blockDim.x + threadIdx.x;
    if (i >= 3072) return;
    b3[i] = (i < 1024) ? qb[i] : (i < 2048 ? 0.f : vb[i-2048]);
}

// ---- router ----
__global__ void scores_k(const float* __restrict__ xp, const float* __restrict__ pw,
                         const float* __restrict__ pb, float* __restrict__ scores){
    int row = blockIdx.x, tid = threadIdx.x;
    const float4* xr = (const float4*)(xp + (size_t)row*Dd);
    const float4* pr = (const float4*)pw;
    float s = 0.f;
    #pragma unroll
    for (int i=0;i<2;i++){
        float4 a = xr[tid*2+i], b = pr[tid*2+i];
        s += a.x*b.x + a.y*b.y + a.z*b.z + a.w*b.w;
    }
    s = warpRedSum(s);
    __shared__ float sm[4];
    if ((tid&31)==0) sm[tid>>5]=s;
    __syncthreads();
    if (tid==0) scores[row] = sm[0]+sm[1]+sm[2]+sm[3] + pb[0];
}
__global__ void softmax_w(const float* __restrict__ scores, float* __restrict__ w){
    int b = blockIdx.x, tid = threadIdx.x;
    float4 v = *(const float4*)(scores + (size_t)b*Sd + tid*4);
    float m = fmaxf(fmaxf(v.x,v.y), fmaxf(v.z,v.w));
    m = warpRedMax(m);
    __shared__ float sm[8];
    __shared__ float gmax, gisum;
    if ((tid&31)==0) sm[tid>>5]=m;
    __syncthreads();
    if (tid==0){ float mm=sm[0]; for(int i=1;i<8;i++) mm=fmaxf(mm,sm[i]); gmax=mm; }
    __syncthreads();
    float e0=expf(v.x-gmax), e1=expf(v.y-gmax), e2=expf(v.z-gmax), e3=expf(v.w-gmax);
    float s = e0+e1+e2+e3;
    s = warpRedSum(s);
    if ((tid&31)==0) sm[tid>>5]=s;
    __syncthreads();
    if (tid==0){ float ss=0; for(int i=0;i<8;i++) ss+=sm[i]; gisum = 1.f/ss; }
    __syncthreads();
    *(float4*)(w + (size_t)b*Sd + tid*4) = make_float4(e0*gisum, e1*gisum, e2*gisum, e3*gisum);
}
__global__ void pooled_k(const float* __restrict__ xp, const float* __restrict__ w,
                         float* __restrict__ pooled){
    int b = blockIdx.y;
    int d = blockIdx.x*128 + threadIdx.x;
    __shared__ float ws[Sd];
    for (int i = threadIdx.x; i < Sd; i += 128) ws[i] = w[(size_t)b*Sd + i];
    __syncthreads();
    float s = 0.f;
    const float* base = xp + (size_t)b*Sd*Dd + d;
    for (int i=0;i<Sd;i++) s = fmaf(ws[i], base[(size_t)i*Dd], s);
    pooled[b*Dd + d] = s;
}
__global__ void route_k(const float* __restrict__ pooled, const float* __restrict__ rw,
                        const float* __restrict__ rb, float* __restrict__ route){
    int tid = threadIdx.x;
    int e = tid >> 5, lane = tid & 31;
    __shared__ float lg[8];
    for (int b=0;b<Bd;b++){
        float s=0.f;
        for (int d=lane; d<Dd; d+=32) s += pooled[b*Dd+d]*rw[e*Dd+d];
        s = warpRedSum(s);
        if (lane==0) lg[e] = s + rb[e];
        __syncthreads();
        if (tid==0){
            float mm=lg[0];
            for (int i=1;i<8;i++) mm=fmaxf(mm,lg[i]);
            float ex[8]; float ss=0.f;
            for (int i=0;i<8;i++){ ex[i]=expf(lg[i]-mm); ss+=ex[i]; }
            float inv = 1.f/ss;
            for (int i=0;i<8;i++) route[b*8+i]=ex[i]*inv;
        }
        __syncthreads();
    }
}

// ---- host launcher ----
extern "C" void kernel_launch(void* const* d_in, const int* in_sizes, int n_in,
                              void* d_out, int out_size)
{
    (void)in_sizes; (void)n_in; (void)out_size;
    const float* x      = (const float*)d_in[0];
    const float* conv_w = (const float*)d_in[1];
    const float* conv_b = (const float*)d_in[2];
    const float* pool_w = (const float*)d_in[3];
    const float* pool_b = (const float*)d_in[4];
    const float* rlin_w = (const float*)d_in[5];
    const float* rlin_b = (const float*)d_in[6];
    const float* qW=(const float*)d_in[7],  *qb=(const float*)d_in[8];
    const float* qA=(const float*)d_in[9],  *qB=(const float*)d_in[10];
    const float* kW=(const float*)d_in[11], *kA=(const float*)d_in[12], *kB=(const float*)d_in[13];
    const float* vW=(const float*)d_in[14], *vb=(const float*)d_in[15];
    const float* vA=(const float*)d_in[16], *vB=(const float*)d_in[17];
    const float* oW=(const float*)d_in[18], *ob=(const float*)d_in[19];
    const float* oA=(const float*)d_in[20], *oB=(const float*)d_in[21];

    float* out = (float*)d_out;
    float* qk  = out + OUT_OFF;

    float *xp,*qkv,*wv,*h,*xsh,*ctK,*W3,*b3,*AA,*Bt3,*Bt,*scores,*w,*pooled,*route;
    cudaGetSymbolAddress((void**)&xp, g_xp);
    cudaGetSymbolAddress((void**)&qkv, g_qkv);
    cudaGetSymbolAddress((void**)&wv, g_wv);
    cudaGetSymbolAddress((void**)&h,  g_h);
    cudaGetSymbolAddress((void**)&xsh, g_xsh);
    cudaGetSymbolAddress((void**)&ctK, g_ctK);
    cudaGetSymbolAddress((void**)&W3,  g_W3);
    cudaGetSymbolAddress((void**)&b3,  g_b3);
    cudaGetSymbolAddress((void**)&AA,  g_AA);
    cudaGetSymbolAddress((void**)&Bt3, g_Bt3);
    cudaGetSymbolAddress((void**)&Bt,  g_Bt);
    cudaGetSymbolAddress((void**)&scores, g_scores);
    cudaGetSymbolAddress((void**)&w,  g_wsm);
    cudaGetSymbolAddress((void**)&pooled, g_pooled);
    cudaGetSymbolAddress((void**)&route,  g_route);

    cudaFuncSetAttribute(mma_gemm, cudaFuncAttributeMaxDynamicSharedMemorySize, GEMM_SMEM);
    cudaFuncSetAttribute(attn_fused, cudaFuncAttributeMaxDynamicSharedMemorySize, ATTN_SMEM);

    prep_xsh<<<(Md*768 + 255)/256, 256>>>(x, xsh);
    prep_ctK<<<(Dd*3072 + 255)/256, 256>>>(conv_w, ctK);
    cudaMemcpyAsync(W3,            qW, (size_t)Dd*Dd*4, cudaMemcpyDeviceToDevice);
    cudaMemcpyAsync(W3 + Dd*Dd,    kW, (size_t)Dd*Dd*4, cudaMemcpyDeviceToDevice);
    cudaMemcpyAsync(W3 + 2*Dd*Dd,  vW, (size_t)Dd*Dd*4, cudaMemcpyDeviceToDevice);
    cudaMemcpyAsync(AA,            qA, (size_t)64*Dd*4, cudaMemcpyDeviceToDevice);
    cudaMemcpyAsync(AA + 64*Dd,    kA, (size_t)64*Dd*4, cudaMemcpyDeviceToDevice);
    cudaMemcpyAsync(AA + 128*Dd,   vA, (size_t)64*Dd*4, cudaMemcpyDeviceToDevice);
    fill_b3<<<12, 256>>>(qb, vb, b3);
    tr_loraB3<<<(3*Dd*64 + 255)/256, 256>>>(qB, kB, vB, Bt3);

    // conv as GEMM (K=3072)
    mma_gemm<<<dim3(8,32,1), 256, GEMM_SMEM>>>(xsh, ctK, xp, Md, Dd, 3072, 3072, 3072, Dd,
        0,0,0,0,0,0,1, 1.f, conv_b, nullptr, 0);

    // router
    scores_k<<<Md, 128>>>(xp, pool_w, pool_b, scores);
    softmax_w<<<Bd, 256>>>(scores, w);
    pooled_k<<<dim3(8,Bd), 128>>>(xp, w, pooled);
    route_k<<<1, 256>>>(pooled, rlin_w, rlin_b, route);

    // batched qkv base projection: [M,3072]
    mma_gemm<<<dim3(24,32,1), 256, GEMM_SMEM>>>(x, W3, qkv, Md, 3072, Dd, Dd, Dd, 3072,
        0,0,0,0,0,0,1, 1.f, b3, nullptr, 0);

    // batched LoRA-A (route-scaled): h[4096,192]
    mma_gemm<<<dim3(2,32,1), 256, GEMM_SMEM>>>(x, AA, h, Md, 192, Dd, Dd, Dd, 192,
        0,0,0,0,0,0,1, 1.f, nullptr, route, 0);

    // z-batched LoRA-B adds into qkv
    mma_gemm<<<dim3(8,32,3), 256, GEMM_SMEM>>>(h, Bt3, qkv, Md, Dd, 64, 192, 64, 3072,
        0,64, 0,(long long)Dd*64, 0,1024, 3, 2.0f, nullptr, nullptr, 1);

    // fused qk + softmax + PV
    attn_fused<<<dim3(8,64), 256, ATTN_SMEM>>>(qkv, qk, wv);

    // o projection
    mma_gemm<<<dim3(8,32,1), 256, GEMM_SMEM>>>(wv, oW, out, Md, Dd, Dd, Dd, Dd, Dd,
        0,0,0,0,0,0,1, 1.f, ob, nullptr, 0);
    mma_gemm<<<dim3(1,32,1), 256, GEMM_SMEM>>>(wv, oA, h, Md, 64, Dd, Dd, Dd, 192,
        0,0,0,0,0,0,1, 1.f, nullptr, route, 0);
    tr_loraB<<<(Dd*64+255)/256, 256>>>(oB, Bt);
    mma_gemm<<<dim3(8,32,1), 256, GEMM_SMEM>>>(h, Bt, out, Md, Dd, 64, 192, 64, Dd,
        0,0,0,0,0,0,1, 2.0f, nullptr, nullptr, 1);
}

// round 8
// speedup vs baseline: 3.9270x; 1.2610x over previous
#include <cuda_runtime.h>
#include <cstdint>
#include <cstddef>

#define Bd 4
#define Sd 1024
#define Dd 1024
#define Hd 16
#define DHd 64
#define Md (Bd*Sd)
#define OUT_OFF ((size_t)Bd*Sd*Dd)

__device__ float g_qkv[(size_t)Md*3072];
__device__ float g_wv[Md*Dd];
__device__ float g_h[Md*192];
__device__ float g_W3[(size_t)3072*Dd];
__device__ float g_b3[3072];
__device__ float g_AA[192*Dd];
__device__ float g_Bt3[3*Dd*64];
__device__ float g_Bt[Dd*64];
__device__ float g_g[3072];
__device__ float g_xw[Bd*3072];
__device__ float g_scores[Md];
__device__ float g_wsm[Md];
__device__ float g_pooled[Bd*Dd];
__device__ float g_route[Bd*8];

__device__ __forceinline__ float warpRedSum(float v){
    #pragma unroll
    for (int o=16;o;o>>=1) v += __shfl_xor_sync(0xffffffffu, v, o);
    return v;
}
__device__ __forceinline__ float warpRedMax(float v){
    #pragma unroll
    for (int o=16;o;o>>=1) v = fmaxf(v, __shfl_xor_sync(0xffffffffu, v, o));
    return v;
}
__device__ __forceinline__ float fexp(float x){
    float t = x * 1.4426950408889634f;
    t = fmaxf(t, -126.0f);
    float ti = floorf(t);
    float f = t - ti;
    float p = 1.5403530393381608e-4f;
    p = fmaf(p, f, 1.3333558146428443e-3f);
    p = fmaf(p, f, 9.6181291076284770e-3f);
    p = fmaf(p, f, 5.5504108664821580e-2f);
    p = fmaf(p, f, 2.4022650695910070e-1f);
    p = fmaf(p, f, 6.9314718055994530e-1f);
    p = fmaf(p, f, 1.0f);
    return __int_as_float(((int)ti + 127) << 23) * p;
}
__device__ __forceinline__ uint32_t f2tf(float f){
    uint32_t r; asm("cvt.rna.tf32.f32 %0, %1;" : "=r"(r) : "f"(f)); return r;
}
__device__ __forceinline__ void mma8(float* d, const uint32_t* a, const uint32_t* b){
    asm volatile("mma.sync.aligned.m16n8k8.row.col.f32.tf32.tf32.f32 "
        "{%0,%1,%2,%3}, {%4,%5,%6,%7}, {%8,%9}, {%0,%1,%2,%3};"
        : "+f"(d[0]),"+f"(d[1]),"+f"(d[2]),"+f"(d[3])
        : "r"(a[0]),"r"(a[1]),"r"(a[2]),"r"(a[3]), "r"(b[0]),"r"(b[1]));
}

// ---- tf32 mma.sync GEMM: C = alpha*A(MxK)B(NxK)^T [*route][+bias][+C] ----
#define GSTRIDE 36
#define GEMM_SMEM (4*128*GSTRIDE*4)
__global__ __launch_bounds__(256,1)
void mma_gemm(const float* __restrict__ A, const float* __restrict__ B, float* __restrict__ C,
              int M, int N, int K, int lda, int ldb, int ldc,
              long long sAb, long long sAh, long long sBb, long long sBh,
              long long sCb, long long sCh, int ZH,
              float alpha, const float* __restrict__ bias, const float* __restrict__ route, int addC)
{
    extern __shared__ __align__(16) uint32_t sm[];
    uint32_t* As = sm;
    uint32_t* Bs = sm + 2*128*GSTRIDE;

    const int tid = threadIdx.x, wid = tid >> 5, lane = tid & 31;
    const int wm = wid >> 2, wn = wid & 3;
    const int lr = lane >> 2, lc = lane & 3;
    int z = blockIdx.z, zb = z / ZH, zh = z - zb*ZH;
    A += (size_t)zb*sAb + (size_t)zh*sAh;
    B += (size_t)zb*sBb + (size_t)zh*sBh;
    C += (size_t)zb*sCb + (size_t)zh*sCh;
    const int bm = blockIdx.y*128, bn = blockIdx.x*128;

    const int row = tid >> 3, c4 = (tid & 7) << 2;
    const float* Ab = A + (size_t)bm*lda;
    const float* Bb = B + (size_t)bn*ldb;
    const int nch = K >> 5;

    float acc[4][4][4];
    #pragma unroll
    for (int i=0;i<4;i++)
        #pragma unroll
        for (int j=0;j<4;j++)
            #pragma unroll
            for (int r=0;r<4;r++) acc[i][j][r]=0.f;

    {
        #pragma unroll
        for (int j=0;j<4;j++){
            int rr = row + j*32;
            float4 av = *(const float4*)(Ab + (size_t)rr*lda + c4);
            uint32_t* d = As + rr*GSTRIDE + c4;
            d[0]=f2tf(av.x); d[1]=f2tf(av.y); d[2]=f2tf(av.z); d[3]=f2tf(av.w);
            float4 bv = make_float4(0.f,0.f,0.f,0.f);
            if (bn + rr < N) bv = *(const float4*)(Bb + (size_t)rr*ldb + c4);
            uint32_t* e = Bs + rr*GSTRIDE + c4;
            e[0]=f2tf(bv.x); e[1]=f2tf(bv.y); e[2]=f2tf(bv.z); e[3]=f2tf(bv.w);
        }
    }
    __syncthreads();

    for (int c = 0; c < nch; c++){
        const uint32_t* Ac = As + (c&1)*128*GSTRIDE;
        const uint32_t* Bc = Bs + (c&1)*128*GSTRIDE;
        float4 pa[4], pb[4];
        if (c+1 < nch){
            int k0 = (c+1) << 5;
            #pragma unroll
            for (int j=0;j<4;j++){
                int rr = row + j*32;
                pa[j] = *(const float4*)(Ab + (size_t)rr*lda + k0 + c4);
                pb[j] = make_float4(0.f,0.f,0.f,0.f);
                if (bn + rr < N) pb[j] = *(const float4*)(Bb + (size_t)rr*ldb + k0 + c4);
            }
        }
        #pragma unroll
        for (int ks=0; ks<4; ks++){
            uint32_t af[4][4], bf[4][2];
            #pragma unroll
            for (int mt=0; mt<4; mt++){
                const uint32_t* p = Ac + (wm*64 + mt*16)*GSTRIDE + ks*8;
                af[mt][0] = p[lr*GSTRIDE + lc];
                af[mt][1] = p[(lr+8)*GSTRIDE + lc];
                af[mt][2] = p[lr*GSTRIDE + lc + 4];
                af[mt][3] = p[(lr+8)*GSTRIDE + lc + 4];
            }
            #pragma unroll
            for (int nt=0; nt<4; nt++){
                const uint32_t* p = Bc + (wn*32 + nt*8)*GSTRIDE + ks*8;
                bf[nt][0] = p[lr*GSTRIDE + lc];
                bf[nt][1] = p[lr*GSTRIDE + lc + 4];
            }
            #pragma unroll
            for (int mt=0; mt<4; mt++)
                #pragma unroll
                for (int nt=0; nt<4; nt++)
                    mma8(acc[mt][nt], af[mt], bf[nt]);
        }
        if (c+1 < nch){
            uint32_t* An = As + ((c+1)&1)*128*GSTRIDE;
            uint32_t* Bn = Bs + ((c+1)&1)*128*GSTRIDE;
            #pragma unroll
            for (int j=0;j<4;j++){
                int rr = row + j*32;
                uint32_t* d = An + rr*GSTRIDE + c4;
                d[0]=f2tf(pa[j].x); d[1]=f2tf(pa[j].y); d[2]=f2tf(pa[j].z); d[3]=f2tf(pa[j].w);
                uint32_t* e = Bn + rr*GSTRIDE + c4;
                e[0]=f2tf(pb[j].x); e[1]=f2tf(pb[j].y); e[2]=f2tf(pb[j].z); e[3]=f2tf(pb[j].w);
            }
        }
        __syncthreads();
    }

    #pragma unroll
    for (int mt=0; mt<4; mt++){
        #pragma unroll
        for (int nt=0; nt<4; nt++){
            int n = bn + wn*32 + nt*8 + 2*lc;
            if (n >= N) continue;
            int m0 = bm + wm*64 + mt*16 + lr;
            #pragma unroll
            for (int half=0; half<2; half++){
                int m = m0 + half*8;
                float v0 = alpha*acc[mt][nt][half*2+0];
                float v1 = alpha*acc[mt][nt][half*2+1];
                if (route){
                    float rs = route[((m >> 10) << 3) + ((n & 63) >> 3)];
                    v0 *= rs; v1 *= rs;
                }
                if (bias){ v0 += bias[n]; v1 += bias[n+1]; }
                float2* cp = (float2*)(C + (size_t)m*ldc + n);
                if (addC){ float2 o = *cp; v0 += o.x; v1 += o.y; }
                *cp = make_float2(v0, v1);
            }
        }
    }
}

// ---- fused flash attention: qk logits out + online softmax + PV ----
#define AQS 36
#define AVS 72
#define AFS_QS 0
#define AFS_KS (2*128*AQS)
#define AFS_VS (AFS_KS + 2*128*AQS)
#define AFS_PS (AFS_VS + 4*32*AVS)
#define AFS_SM (AFS_PS + 128*132)
#define ATTN_SMEM ((AFS_SM + 1024)*4)
__global__ __launch_bounds__(256,1) void attn_fused(
    const float* __restrict__ qkv, float* __restrict__ qk, float* __restrict__ wv)
{
    extern __shared__ __align__(16) uint32_t dsm[];
    uint32_t* Qs = dsm + AFS_QS;
    uint32_t* Ks = dsm + AFS_KS;
    uint32_t* Vs = dsm + AFS_VS;
    uint32_t* Ps = dsm + AFS_PS;
    float* Smax = (float*)(dsm + AFS_SM);
    float* Ssum = Smax + 512;

    const int z = blockIdx.y;
    const int bq = z >> 4, h = z & 15;
    const int bm = blockIdx.x * 128;
    const float* Qg = qkv + (size_t)bq*Sd*3072 + h*64;
    const float* Kg = Qg + 1024;
    const float* Vg = Qg + 2048;
    float* qko = qk + (size_t)z*Sd*Sd;

    const int tid = threadIdx.x, wid = tid >> 5, lane = tid & 31;
    const int wm = wid >> 2, wn = wid & 3;
    const int lr = lane >> 2, lc = lane & 3;
    const int rr0 = tid >> 3, c4 = (tid & 7) << 2;

    #pragma unroll
    for (int j=0;j<4;j++){
        int rr = rr0 + j*32;
        #pragma unroll
        for (int ch=0;ch<2;ch++){
            float4 qv = *(const float4*)(Qg + (size_t)(bm+rr)*3072 + ch*32 + c4);
            uint32_t* d = Qs + ch*128*AQS + rr*AQS + c4;
            d[0]=f2tf(qv.x); d[1]=f2tf(qv.y); d[2]=f2tf(qv.z); d[3]=f2tf(qv.w);
        }
    }

    float runmax[4][2], runsum[4][2];
    #pragma unroll
    for (int i=0;i<4;i++){ runmax[i][0]=-1e30f; runmax[i][1]=-1e30f; runsum[i][0]=0.f; runsum[i][1]=0.f; }
    float pvacc[4][2][4];
    #pragma unroll
    for (int i=0;i<4;i++)
        #pragma unroll
        for (int j=0;j<2;j++)
            #pragma unroll
            for (int r=0;r<4;r++) pvacc[i][j][r]=0.f;

    for (int ct=0; ct<8; ct++){
        const int kb = ct*128;
        #pragma unroll
        for (int j=0;j<4;j++){
            int rr = rr0 + j*32;
            #pragma unroll
            for (int ch=0;ch<2;ch++){
                float4 kv = *(const float4*)(Kg + (size_t)(kb+rr)*3072 + ch*32 + c4);
                uint32_t* d = Ks + ch*128*AQS + rr*AQS + c4;
                d[0]=f2tf(kv.x); d[1]=f2tf(kv.y); d[2]=f2tf(kv.z); d[3]=f2tf(kv.w);
            }
        }
        #pragma unroll
        for (int j=0;j<8;j++){
            int idx = tid + (j << 8);
            int vk = idx >> 4, vc4 = (idx & 15) << 2;
            float4 vv = *(const float4*)(Vg + (size_t)(kb+vk)*3072 + vc4);
            uint32_t* e = Vs + (vk>>5)*32*AVS + (vk&31)*AVS + vc4;
            e[0]=f2tf(vv.x); e[1]=f2tf(vv.y); e[2]=f2tf(vv.z); e[3]=f2tf(vv.w);
        }
        __syncthreads();

        float sacc[4][4][4];
        #pragma unroll
        for (int i=0;i<4;i++)
            #pragma unroll
            for (int j=0;j<4;j++)
                #pragma unroll
                for (int r=0;r<4;r++) sacc[i][j][r]=0.f;
        #pragma unroll
        for (int ch=0;ch<2;ch++){
            const uint32_t* Qc = Qs + ch*128*AQS;
            const uint32_t* Kc = Ks + ch*128*AQS;
            #pragma unroll
            for (int ks=0;ks<4;ks++){
                uint32_t af[4][4], bf[4][2];
                #pragma unroll
                for (int mt=0;mt<4;mt++){
                    const uint32_t* p = Qc + (wm*64 + mt*16)*AQS + ks*8;
                    af[mt][0] = p[lr*AQS + lc];
                    af[mt][1] = p[(lr+8)*AQS + lc];
                    af[mt][2] = p[lr*AQS + lc + 4];
                    af[mt][3] = p[(lr+8)*AQS + lc + 4];
                }
                #pragma unroll
                for (int nt=0;nt<4;nt++){
                    const uint32_t* p = Kc + (wn*32 + nt*8)*AQS + ks*8;
                    bf[nt][0] = p[lr*AQS + lc];
                    bf[nt][1] = p[lr*AQS + lc + 4];
                }
                #pragma unroll
                for (int mt=0;mt<4;mt++)
                    #pragma unroll
                    for (int nt=0;nt<4;nt++)
                        mma8(sacc[mt][nt], af[mt], bf[nt]);
            }
        }
        #pragma unroll
        for (int mt=0;mt<4;mt++)
            #pragma unroll
            for (int nt=0;nt<4;nt++){
                #pragma unroll
                for (int r=0;r<4;r++) sacc[mt][nt][r] *= 0.125f;
                int n = kb + wn*32 + nt*8 + 2*lc;
                int m0 = bm + wm*64 + mt*16 + lr;
                *(float2*)(qko + (size_t)m0*Sd + n)     = make_float2(sacc[mt][nt][0], sacc[mt][nt][1]);
                *(float2*)(qko + (size_t)(m0+8)*Sd + n) = make_float2(sacc[mt][nt][2], sacc[mt][nt][3]);
            }
        #pragma unroll
        for (int mt=0;mt<4;mt++)
            #pragma unroll
            for (int half=0;half<2;half++){
                float tm = -1e30f;
                #pragma unroll
                for (int nt=0;nt<4;nt++)
                    tm = fmaxf(tm, fmaxf(sacc[mt][nt][half*2], sacc[mt][nt][half*2+1]));
                tm = fmaxf(tm, __shfl_xor_sync(0xffffffffu, tm, 1));
                tm = fmaxf(tm, __shfl_xor_sync(0xffffffffu, tm, 2));
                if (lc == 0) Smax[(wm*64 + mt*16 + half*8 + lr)*4 + wn] = tm;
            }
        __syncthreads();
        #pragma unroll
        for (int mt=0;mt<4;mt++)
            #pragma unroll
            for (int half=0;half<2;half++){
                int row = wm*64 + mt*16 + half*8 + lr;
                const float* sp = Smax + row*4;
                float tm = fmaxf(fmaxf(sp[0],sp[1]), fmaxf(sp[2],sp[3]));
                float mn = fmaxf(runmax[mt][half], tm);
                float f = fexp(runmax[mt][half] - mn);
                runmax[mt][half] = mn;
                runsum[mt][half] *= f;
                #pragma unroll
                for (int nt=0;nt<2;nt++){
                    pvacc[mt][nt][half*2+0] *= f;
                    pvacc[mt][nt][half*2+1] *= f;
                }
                float s = 0.f;
                #pragma unroll
                for (int nt=0;nt<4;nt++){
                    float p0 = fexp(sacc[mt][nt][half*2+0] - mn);
                    float p1 = fexp(sacc[mt][nt][half*2+1] - mn);
                    s += p0 + p1;
                    uint32_t* pp = Ps + row*132 + wn*32 + nt*8 + 2*lc;
                    pp[0] = f2tf(p0); pp[1] = f2tf(p1);
                }
                s += __shfl_xor_sync(0xffffffffu, s, 1);
                s += __shfl_xor_sync(0xffffffffu, s, 2);
                if (lc == 0) Ssum[row*4 + wn] = s;
            }
        __syncthreads();
        #pragma unroll
        for (int mt=0;mt<4;mt++)
            #pragma unroll
            for (int half=0;half<2;half++){
                int row = wm*64 + mt*16 + half*8 + lr;
                const float* sp = Ssum + row*4;
                runsum[mt][half] += sp[0]+sp[1]+sp[2]+sp[3];
            }
        #pragma unroll
        for (int ks=0;ks<16;ks++){
            uint32_t af[4][4], bf[2][2];
            #pragma unroll
            for (int mt=0;mt<4;mt++){
                const uint32_t* p = Ps + (wm*64 + mt*16)*132 + ks*8;
                af[mt][0] = p[lr*132 + lc];
                af[mt][1] = p[(lr+8)*132 + lc];
                af[mt][2] = p[lr*132 + lc + 4];
                af[mt][3] = p[(lr+8)*132 + lc + 4];
            }
            #pragma unroll
            for (int nt=0;nt<2;nt++){
                const uint32_t* p = Vs + (ks>>2)*32*AVS + ((ks&3)*8)*AVS + wn*16 + nt*8;
                bf[nt][0] = p[lc*AVS + lr];
                bf[nt][1] = p[(lc+4)*AVS + lr];
            }
            #pragma unroll
            for (int mt=0;mt<4;mt++)
                #pragma unroll
                for (int nt=0;nt<2;nt++)
                    mma8(pvacc[mt][nt], af[mt], bf[nt]);
        }
        __syncthreads();
    }

    float* Cw = wv + (size_t)bq*Sd*Dd + h*DHd;
    #pragma unroll
    for (int mt=0;mt<4;mt++)
        #pragma unroll
        for (int half=0;half<2;half++){
            int row = wm*64 + mt*16 + half*8 + lr;
            float inv = 1.f / runsum[mt][half];
            #pragma unroll
            for (int nt=0;nt<2;nt++){
                int n = wn*16 + nt*8 + 2*lc;
                *(float2*)(Cw + (size_t)(bm+row)*Dd + n) =
                    make_float2(pvacc[mt][nt][half*2]*inv, pvacc[mt][nt][half*2+1]*inv);
            }
        }
}

// ---- router (conv folded out algebraically) ----
// g[i*3+t] = sum_o pool_w[o]*conv_w[o,i,t]
__global__ __launch_bounds__(256) void r_g(const float* __restrict__ cw,
                                           const float* __restrict__ pw, float* __restrict__ g){
    int idx = blockIdx.x*8 + (threadIdx.x >> 5);
    int lane = threadIdx.x & 31;
    float acc = 0.f;
    for (int o = lane; o < Dd; o += 32)
        acc = fmaf(pw[o], cw[(size_t)o*3072 + idx], acc);
    acc = warpRedSum(acc);
    if (lane == 0) g[idx] = acc;
}
// scores[b,s] = sum_{i,t} g[i,t]*x[b,s+t-1,i]  (constants dropped: softmax-invariant)
__global__ __launch_bounds__(128) void r_scores(const float* __restrict__ x,
                                                const float* __restrict__ g, float* __restrict__ scores){
    int m = blockIdx.x;
    int b = m >> 10, s = m & 1023;
    int tid = threadIdx.x;
    __shared__ float gs[3072];
    #pragma unroll
    for (int j=0;j<24;j++) gs[tid + j*128] = g[tid + j*128];
    __syncthreads();
    const float* x0 = x + (size_t)m*Dd;
    const float* xm = x0 - Dd;
    const float* xp1 = x0 + Dd;
    bool okm = (s > 0), okp = (s < 1023);
    float acc = 0.f;
    #pragma unroll
    for (int j=0;j<8;j++){
        int i = tid + j*128;
        float vm = okm ? xm[i] : 0.f;
        float v0 = x0[i];
        float vp = okp ? xp1[i] : 0.f;
        const float* gg = gs + i*3;
        acc = fmaf(gg[0], vm, acc);
        acc = fmaf(gg[1], v0, acc);
        acc = fmaf(gg[2], vp, acc);
    }
    acc = warpRedSum(acc);
    __shared__ float sm[4];
    if ((tid&31)==0) sm[tid>>5]=acc;
    __syncthreads();
    if (tid==0) scores[m] = sm[0]+sm[1]+sm[2]+sm[3];
}
__global__ void softmax_w(const float* __restrict__ scores, float* __restrict__ w){
    int b = blockIdx.x, tid = threadIdx.x;
    float4 v = *(const float4*)(scores + (size_t)b*Sd + tid*4);
    float m = fmaxf(fmaxf(v.x,v.y), fmaxf(v.z,v.w));
    m = warpRedMax(m);
    __shared__ float sm[8];
    __shared__ float gmax, gisum;
    if ((tid&31)==0) sm[tid>>5]=m;
    __syncthreads();
    if (tid==0){ float mm=sm[0]; for(int i=1;i<8;i++) mm=fmaxf(mm,sm[i]); gmax=mm; }
    __syncthreads();
    float e0=expf(v.x-gmax), e1=expf(v.y-gmax), e2=expf(v.z-gmax), e3=expf(v.w-gmax);
    float s = e0+e1+e2+e3;
    s = warpRedSum(s);
    if ((tid&31)==0) sm[tid>>5]=s;
    __syncthreads();
    if (tid==0){ float ss=0; for(int i=0;i<8;i++) ss+=sm[i]; gisum = 1.f/ss; }
    __syncthreads();
    *(float4*)(w + (size_t)b*Sd + tid*4) = make_float4(e0*gisum, e1*gisum, e2*gisum, e3*gisum);
}
// xw[b][i*3+t] = sum_s w[b,s]*x[b,s+t-1,i]
__global__ __launch_bounds__(128) void r_xw(const float* __restrict__ x,
                                            const float* __restrict__ w, float* __restrict__ xw){
    int b = blockIdx.y;
    int i = blockIdx.x*128 + threadIdx.x;
    __shared__ float ws[Sd];
    for (int j = threadIdx.x; j < Sd; j += 128) ws[j] = w[(size_t)b*Sd + j];
    __syncthreads();
    const float* xb = x + (size_t)b*Sd*Dd + i;
    float a0=0.f, a1=0.f, a2=0.f;
    for (int j=0;j<Sd;j++){
        float v = xb[(size_t)j*Dd];
        if (j <= 1022) a0 = fmaf(ws[j+1], v, a0);
        a1 = fmaf(ws[j], v, a1);
        if (j >= 1) a2 = fmaf(ws[j-1], v, a2);
    }
    float* o = xw + (size_t)b*3072 + i*3;
    o[0]=a0; o[1]=a1; o[2]=a2;
}
// pooled[b,d] = conv_b[d] + dot(conv_w[d,:,:], xw[b,:,:])
__global__ __launch_bounds__(256) void r_pooled(const float* __restrict__ cw,
                                                const float* __restrict__ cb,
                                                const float* __restrict__ xw, float* __restrict__ pooled){
    int b = blockIdx.y;
    int d = blockIdx.x*8 + (threadIdx.x >> 5);
    int lane = threadIdx.x & 31;
    __shared__ float sx[3072];
    for (int j = threadIdx.x; j < 3072; j += 256) sx[j] = xw[(size_t)b*3072 + j];
    __syncthreads();
    const float4* cr = (const float4*)(cw + (size_t)d*3072);
    float acc = 0.f;
    #pragma unroll
    for (int j=0;j<24;j++){
        float4 c = cr[lane + j*32];
        const float* s = sx + (lane + j*32)*4;
        acc += c.x*s[0] + c.y*s[1] + c.z*s[2] + c.w*s[3];
    }
    acc = warpRedSum(acc);
    if (lane == 0) pooled[b*Dd + d] = acc + cb[d];
}
__global__ void route_k(const float* __restrict__ pooled, const float* __restrict__ rw,
                        const float* __restrict__ rb, float* __restrict__ route){
    int tid = threadIdx.x;
    int e = tid >> 5, lane = tid & 31;
    __shared__ float lg[8];
    for (int b=0;b<Bd;b++){
        float s=0.f;
        for (int d=lane; d<Dd; d+=32) s += pooled[b*Dd+d]*rw[e*Dd+d];
        s = warpRedSum(s);
        if (lane==0) lg[e] = s + rb[e];
        __syncthreads();
        if (tid==0){
            float mm=lg[0];
            for (int i=1;i<8;i++) mm=fmaxf(mm,lg[i]);
            float ex[8]; float ss=0.f;
            for (int i=0;i<8;i++){ ex[i]=expf(lg[i]-mm); ss+=ex[i]; }
            float inv = 1.f/ss;
            for (int i=0;i<8;i++) route[b*8+i]=ex[i]*inv;
        }
        __syncthreads();
    }
}

// ---- prep ----
__global__ void tr_loraB3(const float* __restrict__ B0, const float* __restrict__ B1,
                          const float* __restrict__ B2, float* __restrict__ Bt){
    int idx = blockIdx.x*blockDim.x + threadIdx.x;
    if (idx >= 3*Dd*64) return;
    int zz = idx >> 16, rem = idx & 65535;
    int n = rem >> 6, e = (rem >> 3) & 7, r = rem & 7;
    const float* Bp = (zz==0) ? B0 : (zz==1 ? B1 : B2);
    Bt[idx] = Bp[(size_t)e*Dd*8 + (size_t)n*8 + r];
}
__global__ void tr_loraB(const float* __restrict__ Bp, float* __restrict__ Bt){
    int idx = blockIdx.x*blockDim.x + threadIdx.x;
    if (idx >= Dd*64) return;
    int n = idx >> 6, e = (idx >> 3) & 7, r = idx & 7;
    Bt[idx] = Bp[(size_t)e*Dd*8 + (size_t)n*8 + r];
}
__global__ void fill_b3(const float* __restrict__ qb, const float* __restrict__ vb,
                        float* __restrict__ b3){
    int i = blockIdx.x*blockDim.x + threadIdx.x;
    if (i >= 3072) return;
    b3[i] = (i < 1024) ? qb[i] : (i < 2048 ? 0.f : vb[i-2048]);
}

// ---- host launcher ----
extern "C" void kernel_launch(void* const* d_in, const int* in_sizes, int n_in,
                              void* d_out, int out_size)
{
    (void)in_sizes; (void)n_in; (void)out_size;
    const float* x      = (const float*)d_in[0];
    const float* conv_w = (const float*)d_in[1];
    const float* conv_b = (const float*)d_in[2];
    const float* pool_w = (const float*)d_in[3];
    const float* pool_b = (const float*)d_in[4];
    const float* rlin_w = (const float*)d_in[5];
    const float* rlin_b = (const float*)d_in[6];
    const float* qW=(const float*)d_in[7],  *qb=(const float*)d_in[8];
    const float* qA=(const float*)d_in[9],  *qB=(const float*)d_in[10];
    const float* kW=(const float*)d_in[11], *kA=(const float*)d_in[12], *kB=(const float*)d_in[13];
    const float* vW=(const float*)d_in[14], *vb=(const float*)d_in[15];
    const float* vA=(const float*)d_in[16], *vB=(const float*)d_in[17];
    const float* oW=(const float*)d_in[18], *ob=(const float*)d_in[19];
    const float* oA=(const float*)d_in[20], *oB=(const float*)d_in[21];
    (void)pool_b;

    float* out = (float*)d_out;
    float* qk  = out + OUT_OFF;

    float *qkv,*wv,*h,*W3,*b3,*AA,*Bt3,*Bt,*gv,*xw,*scores,*w,*pooled,*route;
    cudaGetSymbolAddress((void**)&qkv, g_qkv);
    cudaGetSymbolAddress((void**)&wv, g_wv);
    cudaGetSymbolAddress((void**)&h,  g_h);
    cudaGetSymbolAddress((void**)&W3,  g_W3);
    cudaGetSymbolAddress((void**)&b3,  g_b3);
    cudaGetSymbolAddress((void**)&AA,  g_AA);
    cudaGetSymbolAddress((void**)&Bt3, g_Bt3);
    cudaGetSymbolAddress((void**)&Bt,  g_Bt);
    cudaGetSymbolAddress((void**)&gv,  g_g);
    cudaGetSymbolAddress((void**)&xw,  g_xw);
    cudaGetSymbolAddress((void**)&scores, g_scores);
    cudaGetSymbolAddress((void**)&w,  g_wsm);
    cudaGetSymbolAddress((void**)&pooled, g_pooled);
    cudaGetSymbolAddress((void**)&route,  g_route);

    cudaFuncSetAttribute(mma_gemm, cudaFuncAttributeMaxDynamicSharedMemorySize, GEMM_SMEM);
    cudaFuncSetAttribute(attn_fused, cudaFuncAttributeMaxDynamicSharedMemorySize, ATTN_SMEM);

    cudaMemcpyAsync(W3,            qW, (size_t)Dd*Dd*4, cudaMemcpyDeviceToDevice);
    cudaMemcpyAsync(W3 + Dd*Dd,    kW, (size_t)Dd*Dd*4, cudaMemcpyDeviceToDevice);
    cudaMemcpyAsync(W3 + 2*Dd*Dd,  vW, (size_t)Dd*Dd*4, cudaMemcpyDeviceToDevice);
    cudaMemcpyAsync(AA,            qA, (size_t)64*Dd*4, cudaMemcpyDeviceToDevice);
    cudaMemcpyAsync(AA + 64*Dd,    kA, (size_t)64*Dd*4, cudaMemcpyDeviceToDevice);
    cudaMemcpyAsync(AA + 128*Dd,   vA, (size_t)64*Dd*4, cudaMemcpyDeviceToDevice);
    fill_b3<<<12, 256>>>(qb, vb, b3);
    tr_loraB3<<<(3*Dd*64 + 255)/256, 256>>>(qB, kB, vB, Bt3);

    // router (conv algebraically folded)
    r_g<<<384, 256>>>(conv_w, pool_w, gv);
    r_scores<<<Md, 128>>>(x, gv, scores);
    softmax_w<<<Bd, 256>>>(scores, w);
    r_xw<<<dim3(8,Bd), 128>>>(x, w, xw);
    r_pooled<<<dim3(128,Bd), 256>>>(conv_w, conv_b, xw, pooled);
    route_k<<<1, 256>>>(pooled, rlin_w, rlin_b, route);

    // batched qkv base projection: [M,3072]
    mma_gemm<<<dim3(24,32,1), 256, GEMM_SMEM>>>(x, W3, qkv, Md, 3072, Dd, Dd, Dd, 3072,
        0,0,0,0,0,0,1, 1.f, b3, nullptr, 0);

    // batched LoRA-A (route-scaled): h[4096,192]
    mma_gemm<<<dim3(2,32,1), 256, GEMM_SMEM>>>(x, AA, h, Md, 192, Dd, Dd, Dd, 192,
        0,0,0,0,0,0,1, 1.f, nullptr, route, 0);

    // z-batched LoRA-B adds into qkv
    mma_gemm<<<dim3(8,32,3), 256, GEMM_SMEM>>>(h, Bt3, qkv, Md, Dd, 64, 192, 64, 3072,
        0,64, 0,(long long)Dd*64, 0,1024, 3, 2.0f, nullptr, nullptr, 1);

    // fused qk + softmax + PV
    attn_fused<<<dim3(8,64), 256, ATTN_SMEM>>>(qkv, qk, wv);

    // o projection
    mma_gemm<<<dim3(8,32,1), 256, GEMM_SMEM>>>(wv, oW, out, Md, Dd, Dd, Dd, Dd, Dd,
        0,0,0,0,0,0,1, 1.f, ob, nullptr, 0);
    mma_gemm<<<dim3(1,32,1), 256, GEMM_SMEM>>>(wv, oA, h, Md, 64, Dd, Dd, Dd, 192,
        0,0,0,0,0,0,1, 1.f, nullptr, route, 0);
    tr_loraB<<<(Dd*64+255)/256, 256>>>(oB, Bt);
    mma_gemm<<<dim3(8,32,1), 256, GEMM_SMEM>>>(h, Bt, out, Md, Dd, 64, 192, 64, Dd,
        0,0,0,0,0,0,1, 2.0f, nullptr, nullptr, 1);
}

// round 9
// speedup vs baseline: 4.4468x; 1.1324x over previous
#include <cuda_runtime.h>
#include <cstdint>
#include <cstddef>

#define Bd 4
#define Sd 1024
#define Dd 1024
#define Hd 16
#define DHd 64
#define Md (Bd*Sd)
#define OUT_OFF ((size_t)Bd*Sd*Dd)

__device__ float g_qkv[(size_t)Md*3072];
__device__ float g_wv[Md*Dd];
__device__ float g_h[Md*192];
__device__ float g_W3[(size_t)3072*Dd];
__device__ float g_b3[3072];
__device__ float g_AA[192*Dd];
__device__ float g_Bt3[3*Dd*64];
__device__ float g_Bt[Dd*64];
__device__ float g_g[3072];
__device__ float g_xw[Bd*3072];
__device__ float g_scores[Md];
__device__ float g_wsm[Md];
__device__ float g_pooled[Bd*Dd];
__device__ float g_route[Bd*8];

__device__ __forceinline__ float warpRedSum(float v){
    #pragma unroll
    for (int o=16;o;o>>=1) v += __shfl_xor_sync(0xffffffffu, v, o);
    return v;
}
__device__ __forceinline__ float warpRedMax(float v){
    #pragma unroll
    for (int o=16;o;o>>=1) v = fmaxf(v, __shfl_xor_sync(0xffffffffu, v, o));
    return v;
}
__device__ __forceinline__ float fexp(float x){
    float t = x * 1.4426950408889634f;
    t = fmaxf(t, -126.0f);
    float ti = floorf(t);
    float f = t - ti;
    float p = 1.5403530393381608e-4f;
    p = fmaf(p, f, 1.3333558146428443e-3f);
    p = fmaf(p, f, 9.6181291076284770e-3f);
    p = fmaf(p, f, 5.5504108664821580e-2f);
    p = fmaf(p, f, 2.4022650695910070e-1f);
    p = fmaf(p, f, 6.9314718055994530e-1f);
    p = fmaf(p, f, 1.0f);
    return __int_as_float(((int)ti + 127) << 23) * p;
}
__device__ __forceinline__ uint32_t f2tf(float f){
    uint32_t r; asm("cvt.rna.tf32.f32 %0, %1;" : "=r"(r) : "f"(f)); return r;
}
__device__ __forceinline__ void mma8(float* d, const uint32_t* a, const uint32_t* b){
    asm volatile("mma.sync.aligned.m16n8k8.row.col.f32.tf32.tf32.f32 "
        "{%0,%1,%2,%3}, {%4,%5,%6,%7}, {%8,%9}, {%0,%1,%2,%3};"
        : "+f"(d[0]),"+f"(d[1]),"+f"(d[2]),"+f"(d[3])
        : "r"(a[0]),"r"(a[1]),"r"(a[2]),"r"(a[3]), "r"(b[0]),"r"(b[1]));
}
__device__ __forceinline__ uint32_t smem_u32(const void* p){
    uint32_t a; asm("{ .reg .u64 t; cvta.to.shared.u64 t, %1; cvt.u32.u64 %0, t; }" : "=r"(a) : "l"(p));
    return a;
}
__device__ __forceinline__ void cpa16(uint32_t dst, const void* src, int ok){
    asm volatile("cp.async.cg.shared.global [%0], [%1], 16, %2;"
        :: "r"(dst), "l"(src), "r"(ok ? 16 : 0));
}
#define CPA_COMMIT asm volatile("cp.async.commit_group;" ::: "memory")
#define CPA_WAIT(n) asm volatile("cp.async.wait_group %0;" :: "n"(n) : "memory")

// ---- tf32 mma.sync GEMM: C = alpha*A(MxK)B(NxK)^T [*route][+bias][+C] ----
// raw-f32 smem via cp.async double-buffer; cvt.rna at fragment load.
#define GSTRIDE 36
#define GEMM_SMEM (4*128*GSTRIDE*4)
__global__ __launch_bounds__(256,2)
void mma_gemm(const float* __restrict__ A, const float* __restrict__ B, float* __restrict__ C,
              int M, int N, int K, int lda, int ldb, int ldc,
              long long sAb, long long sAh, long long sBb, long long sBh,
              long long sCb, long long sCh, int ZH,
              float alpha, const float* __restrict__ bias, const float* __restrict__ route, int addC)
{
    extern __shared__ __align__(16) float sm[];
    float* As = sm;
    float* Bs = sm + 2*128*GSTRIDE;

    const int tid = threadIdx.x, wid = tid >> 5, lane = tid & 31;
    const int wm = wid >> 2, wn = wid & 3;
    const int lr = lane >> 2, lc = lane & 3;
    int z = blockIdx.z, zb = z / ZH, zh = z - zb*ZH;
    A += (size_t)zb*sAb + (size_t)zh*sAh;
    B += (size_t)zb*sBb + (size_t)zh*sBh;
    C += (size_t)zb*sCb + (size_t)zh*sCh;
    const int bm = blockIdx.y*128, bn = blockIdx.x*128;

    const int row = tid >> 3, c4 = (tid & 7) << 2;
    const float* Ab = A + (size_t)bm*lda;
    const float* Bb = B + (size_t)bn*ldb;
    const int nch = K >> 5;
    const uint32_t sA = smem_u32(As), sB = smem_u32(Bs);

    auto issue = [&](int c){
        int buf = c & 1;
        int k0 = (c << 5) + c4;
        #pragma unroll
        for (int j=0;j<4;j++){
            int rr = row + j*32;
            int bok = (bn + rr) < N;
            cpa16(sA + (uint32_t)((buf*128 + rr)*GSTRIDE + c4)*4,
                  Ab + (size_t)rr*lda + k0, 1);
            cpa16(sB + (uint32_t)((buf*128 + rr)*GSTRIDE + c4)*4,
                  Bb + (size_t)(bok ? rr : 0)*ldb + k0, bok);
        }
        CPA_COMMIT;
    };

    float acc[4][4][4];
    #pragma unroll
    for (int i=0;i<4;i++)
        #pragma unroll
        for (int j=0;j<4;j++)
            #pragma unroll
            for (int r=0;r<4;r++) acc[i][j][r]=0.f;

    issue(0);
    if (nch > 1){ issue(1); CPA_WAIT(1); } else CPA_WAIT(0);
    __syncthreads();

    for (int c = 0; c < nch; c++){
        const float* Ac = As + (c&1)*128*GSTRIDE;
        const float* Bc = Bs + (c&1)*128*GSTRIDE;
        #pragma unroll
        for (int ks=0; ks<4; ks++){
            uint32_t af[4][4], bf[4][2];
            #pragma unroll
            for (int mt=0; mt<4; mt++){
                const float* p = Ac + (wm*64 + mt*16)*GSTRIDE + ks*8;
                af[mt][0] = f2tf(p[lr*GSTRIDE + lc]);
                af[mt][1] = f2tf(p[(lr+8)*GSTRIDE + lc]);
                af[mt][2] = f2tf(p[lr*GSTRIDE + lc + 4]);
                af[mt][3] = f2tf(p[(lr+8)*GSTRIDE + lc + 4]);
            }
            #pragma unroll
            for (int nt=0; nt<4; nt++){
                const float* p = Bc + (wn*32 + nt*8)*GSTRIDE + ks*8;
                bf[nt][0] = f2tf(p[lr*GSTRIDE + lc]);
                bf[nt][1] = f2tf(p[lr*GSTRIDE + lc + 4]);
            }
            #pragma unroll
            for (int mt=0; mt<4; mt++)
                #pragma unroll
                for (int nt=0; nt<4; nt++)
                    mma8(acc[mt][nt], af[mt], bf[nt]);
        }
        __syncthreads();
        if (c+2 < nch) issue(c+2);
        if (c+1 < nch){
            if (c+2 < nch) CPA_WAIT(1); else CPA_WAIT(0);
            __syncthreads();
        }
    }

    #pragma unroll
    for (int mt=0; mt<4; mt++){
        #pragma unroll
        for (int nt=0; nt<4; nt++){
            int n = bn + wn*32 + nt*8 + 2*lc;
            if (n >= N) continue;
            int m0 = bm + wm*64 + mt*16 + lr;
            #pragma unroll
            for (int half=0; half<2; half++){
                int m = m0 + half*8;
                float v0 = alpha*acc[mt][nt][half*2+0];
                float v1 = alpha*acc[mt][nt][half*2+1];
                if (route){
                    float rs = route[((m >> 10) << 3) + ((n & 63) >> 3)];
                    v0 *= rs; v1 *= rs;
                }
                if (bias){ v0 += bias[n]; v1 += bias[n+1]; }
                float2* cp = (float2*)(C + (size_t)m*ldc + n);
                if (addC){ float2 o = *cp; v0 += o.x; v1 += o.y; }
                *cp = make_float2(v0, v1);
            }
        }
    }
}

// ---- fused flash attention: qk logits out + online softmax + PV ----
// raw-f32 K/V/Q smem via cp.async; K(ct+1) flies during softmax, V(ct+1) during next S.
#define AQS 36
#define AVS 72
#define ATTN_SMEM ((2*128*AQS + 2*128*AQS + 4*32*AVS + 128*132 + 1024)*4)
__global__ __launch_bounds__(256,1) void attn_fused(
    const float* __restrict__ qkv, float* __restrict__ qk, float* __restrict__ wv)
{
    extern __shared__ __align__(16) float dsm[];
    float* Qs = dsm;
    float* Ks = dsm + 2*128*AQS;
    float* Vs = Ks + 2*128*AQS;
    uint32_t* Ps = (uint32_t*)(Vs + 4*32*AVS);
    float* Smax = (float*)(Ps + 128*132);
    float* Ssum = Smax + 512;

    const int z = blockIdx.y;
    const int bq = z >> 4, h = z & 15;
    const int bm = blockIdx.x * 128;
    const float* Qg = qkv + (size_t)bq*Sd*3072 + h*64;
    const float* Kg = Qg + 1024;
    const float* Vg = Qg + 2048;
    float* qko = qk + (size_t)z*Sd*Sd;

    const int tid = threadIdx.x, wid = tid >> 5, lane = tid & 31;
    const int wm = wid >> 2, wn = wid & 3;
    const int lr = lane >> 2, lc = lane & 3;
    const int rr0 = tid >> 3, c4 = (tid & 7) << 2;
    const uint32_t sQ = smem_u32(Qs), sK = smem_u32(Ks), sV = smem_u32(Vs);

    auto issueK = [&](int ct){
        int kb = ct << 7;
        #pragma unroll
        for (int j=0;j<4;j++){
            int rr = rr0 + j*32;
            #pragma unroll
            for (int ch=0;ch<2;ch++)
                cpa16(sK + (uint32_t)(((ch*128 + rr)*AQS + c4)*4),
                      Kg + (size_t)(kb+rr)*3072 + ch*32 + c4, 1);
        }
        CPA_COMMIT;
    };
    auto issueV = [&](int ct){
        int kb = ct << 7;
        #pragma unroll
        for (int j=0;j<8;j++){
            int idx = tid + (j << 8);
            int vk = idx >> 4, vc4 = (idx & 15) << 2;
            cpa16(sV + (uint32_t)((((vk>>5)*32 + (vk&31))*AVS + vc4)*4),
                  Vg + (size_t)(kb+vk)*3072 + vc4, 1);
        }
        CPA_COMMIT;
    };

    // prologue: Q + K0 + V0
    #pragma unroll
    for (int j=0;j<4;j++){
        int rr = rr0 + j*32;
        #pragma unroll
        for (int ch=0;ch<2;ch++)
            cpa16(sQ + (uint32_t)(((ch*128 + rr)*AQS + c4)*4),
                  Qg + (size_t)(bm+rr)*3072 + ch*32 + c4, 1);
    }
    CPA_COMMIT;
    issueK(0); issueV(0);
    CPA_WAIT(0);
    __syncthreads();

    float runmax[4][2], runsum[4][2];
    #pragma unroll
    for (int i=0;i<4;i++){ runmax[i][0]=-1e30f; runmax[i][1]=-1e30f; runsum[i][0]=0.f; runsum[i][1]=0.f; }
    float pvacc[4][2][4];
    #pragma unroll
    for (int i=0;i<4;i++)
        #pragma unroll
        for (int j=0;j<2;j++)
            #pragma unroll
            for (int r=0;r<4;r++) pvacc[i][j][r]=0.f;

    for (int ct=0; ct<8; ct++){
        const int kb = ct*128;

        // S = Q K^T
        float sacc[4][4][4];
        #pragma unroll
        for (int i=0;i<4;i++)
            #pragma unroll
            for (int j=0;j<4;j++)
                #pragma unroll
                for (int r=0;r<4;r++) sacc[i][j][r]=0.f;
        #pragma unroll
        for (int ch=0;ch<2;ch++){
            const float* Qc = Qs + ch*128*AQS;
            const float* Kc = Ks + ch*128*AQS;
            #pragma unroll
            for (int ks=0;ks<4;ks++){
                uint32_t af[4][4], bf[4][2];
                #pragma unroll
                for (int mt=0;mt<4;mt++){
                    const float* p = Qc + (wm*64 + mt*16)*AQS + ks*8;
                    af[mt][0] = f2tf(p[lr*AQS + lc]);
                    af[mt][1] = f2tf(p[(lr+8)*AQS + lc]);
                    af[mt][2] = f2tf(p[lr*AQS + lc + 4]);
                    af[mt][3] = f2tf(p[(lr+8)*AQS + lc + 4]);
                }
                #pragma unroll
                for (int nt=0;nt<4;nt++){
                    const float* p = Kc + (wn*32 + nt*8)*AQS + ks*8;
                    bf[nt][0] = f2tf(p[lr*AQS + lc]);
                    bf[nt][1] = f2tf(p[lr*AQS + lc + 4]);
                }
                #pragma unroll
                for (int mt=0;mt<4;mt++)
                    #pragma unroll
                    for (int nt=0;nt<4;nt++)
                        mma8(sacc[mt][nt], af[mt], bf[nt]);
            }
        }
        // scale + write qk logits + tile row max
        #pragma unroll
        for (int mt=0;mt<4;mt++)
            #pragma unroll
            for (int nt=0;nt<4;nt++){
                #pragma unroll
                for (int r=0;r<4;r++) sacc[mt][nt][r] *= 0.125f;
                int n = kb + wn*32 + nt*8 + 2*lc;
                int m0 = bm + wm*64 + mt*16 + lr;
                *(float2*)(qko + (size_t)m0*Sd + n)     = make_float2(sacc[mt][nt][0], sacc[mt][nt][1]);
                *(float2*)(qko + (size_t)(m0+8)*Sd + n) = make_float2(sacc[mt][nt][2], sacc[mt][nt][3]);
            }
        #pragma unroll
        for (int mt=0;mt<4;mt++)
            #pragma unroll
            for (int half=0;half<2;half++){
                float tm = -1e30f;
                #pragma unroll
                for (int nt=0;nt<4;nt++)
                    tm = fmaxf(tm, fmaxf(sacc[mt][nt][half*2], sacc[mt][nt][half*2+1]));
                tm = fmaxf(tm, __shfl_xor_sync(0xffffffffu, tm, 1));
                tm = fmaxf(tm, __shfl_xor_sync(0xffffffffu, tm, 2));
                if (lc == 0) Smax[(wm*64 + mt*16 + half*8 + lr)*4 + wn] = tm;
            }
        __syncthreads();                 // Ks reads done + Smax ready
        if (ct < 7) issueK(ct+1);        // K(ct+1) flies during softmax

        #pragma unroll
        for (int mt=0;mt<4;mt++)
            #pragma unroll
            for (int half=0;half<2;half++){
                int row = wm*64 + mt*16 + half*8 + lr;
                const float* sp = Smax + row*4;
                float tm = fmaxf(fmaxf(sp[0],sp[1]), fmaxf(sp[2],sp[3]));
                float mn = fmaxf(runmax[mt][half], tm);
                float f = fexp(runmax[mt][half] - mn);
                runmax[mt][half] = mn;
                runsum[mt][half] *= f;
                #pragma unroll
                for (int nt=0;nt<2;nt++){
                    pvacc[mt][nt][half*2+0] *= f;
                    pvacc[mt][nt][half*2+1] *= f;
                }
                float s = 0.f;
                #pragma unroll
                for (int nt=0;nt<4;nt++){
                    float p0 = fexp(sacc[mt][nt][half*2+0] - mn);
                    float p1 = fexp(sacc[mt][nt][half*2+1] - mn);
                    s += p0 + p1;
                    uint32_t* pp = Ps + row*132 + wn*32 + nt*8 + 2*lc;
                    pp[0] = f2tf(p0); pp[1] = f2tf(p1);
                }
                s += __shfl_xor_sync(0xffffffffu, s, 1);
                s += __shfl_xor_sync(0xffffffffu, s, 2);
                if (lc == 0) Ssum[row*4 + wn] = s;
            }
        __syncthreads();                 // Ps + Ssum ready
        #pragma unroll
        for (int mt=0;mt<4;mt++)
            #pragma unroll
            for (int half=0;half<2;half++){
                int row = wm*64 + mt*16 + half*8 + lr;
                const float* sp = Ssum + row*4;
                runsum[mt][half] += sp[0]+sp[1]+sp[2]+sp[3];
            }
        if (ct < 7) CPA_WAIT(1); else CPA_WAIT(0);   // V(ct) complete
        __syncthreads();

        // PV
        #pragma unroll
        for (int ks=0;ks<16;ks++){
            uint32_t af[4][4], bf[2][2];
            #pragma unroll
            for (int mt=0;mt<4;mt++){
                const uint32_t* p = Ps + (wm*64 + mt*16)*132 + ks*8;
                af[mt][0] = p[lr*132 + lc];
                af[mt][1] = p[(lr+8)*132 + lc];
                af[mt][2] = p[lr*132 + lc + 4];
                af[mt][3] = p[(lr+8)*132 + lc + 4];
            }
            #pragma unroll
            for (int nt=0;nt<2;nt++){
                const float* p = Vs + (ks>>2)*32*AVS + ((ks&3)*8)*AVS + wn*16 + nt*8;
                bf[nt][0] = f2tf(p[lc*AVS + lr]);
                bf[nt][1] = f2tf(p[(lc+4)*AVS + lr]);
            }
            #pragma unroll
            for (int mt=0;mt<4;mt++)
                #pragma unroll
                for (int nt=0;nt<2;nt++)
                    mma8(pvacc[mt][nt], af[mt], bf[nt]);
        }
        __syncthreads();                 // Vs reads done
        if (ct < 7){
            issueV(ct+1);                // V(ct+1) flies during next S
            CPA_WAIT(1);                 // ensure K(ct+1) complete
            __syncthreads();
        }
    }

    float* Cw = wv + (size_t)bq*Sd*Dd + h*DHd;
    #pragma unroll
    for (int mt=0;mt<4;mt++)
        #pragma unroll
        for (int half=0;half<2;half++){
            int row = wm*64 + mt*16 + half*8 + lr;
            float inv = 1.f / runsum[mt][half];
            #pragma unroll
            for (int nt=0;nt<2;nt++){
                int n = wn*16 + nt*8 + 2*lc;
                *(float2*)(Cw + (size_t)(bm+row)*Dd + n) =
                    make_float2(pvacc[mt][nt][half*2]*inv, pvacc[mt][nt][half*2+1]*inv);
            }
        }
}

// ---- router (conv folded out algebraically) ----
__global__ __launch_bounds__(256) void r_g(const float* __restrict__ cw,
                                           const float* __restrict__ pw, float* __restrict__ g){
    int idx = blockIdx.x*8 + (threadIdx.x >> 5);
    int lane = threadIdx.x & 31;
    float acc = 0.f;
    for (int o = lane; o < Dd; o += 32)
        acc = fmaf(pw[o], cw[(size_t)o*3072 + idx], acc);
    acc = warpRedSum(acc);
    if (lane == 0) g[idx] = acc;
}
__global__ __launch_bounds__(128) void r_scores(const float* __restrict__ x,
                                                const float* __restrict__ g, float* __restrict__ scores){
    int m = blockIdx.x;
    int b = m >> 10, s = m & 1023;
    int tid = threadIdx.x;
    __shared__ float gs[3072];
    #pragma unroll
    for (int j=0;j<24;j++) gs[tid + j*128] = g[tid + j*128];
    __syncthreads();
    const float* x0 = x + (size_t)m*Dd;
    const float* xm = x0 - Dd;
    const float* xp1 = x0 + Dd;
    bool okm = (s > 0), okp = (s < 1023);
    float acc = 0.f;
    #pragma unroll
    for (int j=0;j<8;j++){
        int i = tid + j*128;
        float vm = okm ? xm[i] : 0.f;
        float v0 = x0[i];
        float vp = okp ? xp1[i] : 0.f;
        const float* gg = gs + i*3;
        acc = fmaf(gg[0], vm, acc);
        acc = fmaf(gg[1], v0, acc);
        acc = fmaf(gg[2], vp, acc);
    }
    acc = warpRedSum(acc);
    __shared__ float sm[4];
    if ((tid&31)==0) sm[tid>>5]=acc;
    __syncthreads();
    if (tid==0) scores[m] = sm[0]+sm[1]+sm[2]+sm[3];
}
__global__ void softmax_w(const float* __restrict__ scores, float* __restrict__ w){
    int b = blockIdx.x, tid = threadIdx.x;
    float4 v = *(const float4*)(scores + (size_t)b*Sd + tid*4);
    float m = fmaxf(fmaxf(v.x,v.y), fmaxf(v.z,v.w));
    m = warpRedMax(m);
    __shared__ float sm[8];
    __shared__ float gmax, gisum;
    if ((tid&31)==0) sm[tid>>5]=m;
    __syncthreads();
    if (tid==0){ float mm=sm[0]; for(int i=1;i<8;i++) mm=fmaxf(mm,sm[i]); gmax=mm; }
    __syncthreads();
    float e0=expf(v.x-gmax), e1=expf(v.y-gmax), e2=expf(v.z-gmax), e3=expf(v.w-gmax);
    float s = e0+e1+e2+e3;
    s = warpRedSum(s);
    if ((tid&31)==0) sm[tid>>5]=s;
    __syncthreads();
    if (tid==0){ float ss=0; for(int i=0;i<8;i++) ss+=sm[i]; gisum = 1.f/ss; }
    __syncthreads();
    *(float4*)(w + (size_t)b*Sd + tid*4) = make_float4(e0*gisum, e1*gisum, e2*gisum, e3*gisum);
}
__global__ __launch_bounds__(128) void r_xw(const float* __restrict__ x,
                                            const float* __restrict__ w, float* __restrict__ xw){
    int b = blockIdx.y;
    int i = blockIdx.x*128 + threadIdx.x;
    __shared__ float ws[Sd];
    for (int j = threadIdx.x; j < Sd; j += 128) ws[j] = w[(size_t)b*Sd + j];
    __syncthreads();
    const float* xb = x + (size_t)b*Sd*Dd + i;
    float a0=0.f, a1=0.f, a2=0.f;
    for (int j=0;j<Sd;j++){
        float v = xb[(size_t)j*Dd];
        if (j <= 1022) a0 = fmaf(ws[j+1], v, a0);
        a1 = fmaf(ws[j], v, a1);
        if (j >= 1) a2 = fmaf(ws[j-1], v, a2);
    }
    float* o = xw + (size_t)b*3072 + i*3;
    o[0]=a0; o[1]=a1; o[2]=a2;
}
__global__ __launch_bounds__(256) void r_pooled(const float* __restrict__ cw,
                                                const float* __restrict__ cb,
                                                const float* __restrict__ xw, float* __restrict__ pooled){
    int b = blockIdx.y;
    int d = blockIdx.x*8 + (threadIdx.x >> 5);
    int lane = threadIdx.x & 31;
    __shared__ float sx[3072];
    for (int j = threadIdx.x; j < 3072; j += 256) sx[j] = xw[(size_t)b*3072 + j];
    __syncthreads();
    const float4* cr = (const float4*)(cw + (size_t)d*3072);
    float acc = 0.f;
    #pragma unroll
    for (int j=0;j<24;j++){
        float4 c = cr[lane + j*32];
        const float* s = sx + (lane + j*32)*4;
        acc += c.x*s[0] + c.y*s[1] + c.z*s[2] + c.w*s[3];
    }
    acc = warpRedSum(acc);
    if (lane == 0) pooled[b*Dd + d] = acc + cb[d];
}
__global__ void route_k(const float* __restrict__ pooled, const float* __restrict__ rw,
                        const float* __restrict__ rb, float* __restrict__ route){
    int tid = threadIdx.x;
    int e = tid >> 5, lane = tid & 31;
    __shared__ float lg[8];
    for (int b=0;b<Bd;b++){
        float s=0.f;
        for (int d=lane; d<Dd; d+=32) s += pooled[b*Dd+d]*rw[e*Dd+d];
        s = warpRedSum(s);
        if (lane==0) lg[e] = s + rb[e];
        __syncthreads();
        if (tid==0){
            float mm=lg[0];
            for (int i=1;i<8;i++) mm=fmaxf(mm,lg[i]);
            float ex[8]; float ss=0.f;
            for (int i=0;i<8;i++){ ex[i]=expf(lg[i]-mm); ss+=ex[i]; }
            float inv = 1.f/ss;
            for (int i=0;i<8;i++) route[b*8+i]=ex[i]*inv;
        }
        __syncthreads();
    }
}

// ---- prep ----
__global__ void tr_loraB3(const float* __restrict__ B0, const float* __restrict__ B1,
                          const float* __restrict__ B2, float* __restrict__ Bt){
    int idx = blockIdx.x*blockDim.x + threadIdx.x;
    if (idx >= 3*Dd*64) return;
    int zz = idx >> 16, rem = idx & 65535;
    int n = rem >> 6, e = (rem >> 3) & 7, r = rem & 7;
    const float* Bp = (zz==0) ? B0 : (zz==1 ? B1 : B2);
    Bt[idx] = Bp[(size_t)e*Dd*8 + (size_t)n*8 + r];
}
__global__ void tr_loraB(const float* __restrict__ Bp, float* __restrict__ Bt){
    int idx = blockIdx.x*blockDim.x + threadIdx.x;
    if (idx >= Dd*64) return;
    int n = idx >> 6, e = (idx >> 3) & 7, r = idx & 7;
    Bt[idx] = Bp[(size_t)e*Dd*8 + (size_t)n*8 + r];
}
__global__ void fill_b3(const float* __restrict__ qb, const float* __restrict__ vb,
                        float* __restrict__ b3){
    int i = blockIdx.x*blockDim.x + threadIdx.x;
    if (i >= 3072) return;
    b3[i] = (i < 1024) ? qb[i] : (i < 2048 ? 0.f : vb[i-2048]);
}

// ---- host launcher ----
extern "C" void kernel_launch(void* const* d_in, const int* in_sizes, int n_in,
                              void* d_out, int out_size)
{
    (void)in_sizes; (void)n_in; (void)out_size;
    const float* x      = (const float*)d_in[0];
    const float* conv_w = (const float*)d_in[1];
    const float* conv_b = (const float*)d_in[2];
    const float* pool_w = (const float*)d_in[3];
    const float* pool_b = (const float*)d_in[4];
    const float* rlin_w = (const float*)d_in[5];
    const float* rlin_b = (const float*)d_in[6];
    const float* qW=(const float*)d_in[7],  *qb=(const float*)d_in[8];
    const float* qA=(const float*)d_in[9],  *qB=(const float*)d_in[10];
    const float* kW=(const float*)d_in[11], *kA=(const float*)d_in[12], *kB=(const float*)d_in[13];
    const float* vW=(const float*)d_in[14], *vb=(const float*)d_in[15];
    const float* vA=(const float*)d_in[16], *vB=(const float*)d_in[17];
    const float* oW=(const float*)d_in[18], *ob=(const float*)d_in[19];
    const float* oA=(const float*)d_in[20], *oB=(const float*)d_in[21];
    (void)pool_b;

    float* out = (float*)d_out;
    float* qk  = out + OUT_OFF;

    float *qkv,*wv,*h,*W3,*b3,*AA,*Bt3,*Bt,*gv,*xw,*scores,*w,*pooled,*route;
    cudaGetSymbolAddress((void**)&qkv, g_qkv);
    cudaGetSymbolAddress((void**)&wv, g_wv);
    cudaGetSymbolAddress((void**)&h,  g_h);
    cudaGetSymbolAddress((void**)&W3,  g_W3);
    cudaGetSymbolAddress((void**)&b3,  g_b3);
    cudaGetSymbolAddress((void**)&AA,  g_AA);
    cudaGetSymbolAddress((void**)&Bt3, g_Bt3);
    cudaGetSymbolAddress((void**)&Bt,  g_Bt);
    cudaGetSymbolAddress((void**)&gv,  g_g);
    cudaGetSymbolAddress((void**)&xw,  g_xw);
    cudaGetSymbolAddress((void**)&scores, g_scores);
    cudaGetSymbolAddress((void**)&w,  g_wsm);
    cudaGetSymbolAddress((void**)&pooled, g_pooled);
    cudaGetSymbolAddress((void**)&route,  g_route);

    cudaFuncSetAttribute(mma_gemm, cudaFuncAttributeMaxDynamicSharedMemorySize, GEMM_SMEM);
    cudaFuncSetAttribute(attn_fused, cudaFuncAttributeMaxDynamicSharedMemorySize, ATTN_SMEM);

    cudaMemcpyAsync(W3,            qW, (size_t)Dd*Dd*4, cudaMemcpyDeviceToDevice);
    cudaMemcpyAsync(W3 + Dd*Dd,    kW, (size_t)Dd*Dd*4, cudaMemcpyDeviceToDevice);
    cudaMemcpyAsync(W3 + 2*Dd*Dd,  vW, (size_t)Dd*Dd*4, cudaMemcpyDeviceToDevice);
    cudaMemcpyAsync(AA,            qA, (size_t)64*Dd*4, cudaMemcpyDeviceToDevice);
    cudaMemcpyAsync(AA + 64*Dd,    kA, (size_t)64*Dd*4, cudaMemcpyDeviceToDevice);
    cudaMemcpyAsync(AA + 128*Dd,   vA, (size_t)64*Dd*4, cudaMemcpyDeviceToDevice);
    fill_b3<<<12, 256>>>(qb, vb, b3);
    tr_loraB3<<<(3*Dd*64 + 255)/256, 256>>>(qB, kB, vB, Bt3);

    // router (conv algebraically folded)
    r_g<<<384, 256>>>(conv_w, pool_w, gv);
    r_scores<<<Md, 128>>>(x, gv, scores);
    softmax_w<<<Bd, 256>>>(scores, w);
    r_xw<<<dim3(8,Bd), 128>>>(x, w, xw);
    r_pooled<<<dim3(128,Bd), 256>>>(conv_w, conv_b, xw, pooled);
    route_k<<<1, 256>>>(pooled, rlin_w, rlin_b, route);

    // batched qkv base projection: [M,3072]
    mma_gemm<<<dim3(24,32,1), 256, GEMM_SMEM>>>(x, W3, qkv, Md, 3072, Dd, Dd, Dd, 3072,
        0,0,0,0,0,0,1, 1.f, b3, nullptr, 0);

    // batched LoRA-A (route-scaled): h[4096,192]
    mma_gemm<<<dim3(2,32,1), 256, GEMM_SMEM>>>(x, AA, h, Md, 192, Dd, Dd, Dd, 192,
        0,0,0,0,0,0,1, 1.f, nullptr, route, 0);

    // z-batched LoRA-B adds into qkv
    mma_gemm<<<dim3(8,32,3), 256, GEMM_SMEM>>>(h, Bt3, qkv, Md, Dd, 64, 192, 64, 3072,
        0,64, 0,(long long)Dd*64, 0,1024, 3, 2.0f, nullptr, nullptr, 1);

    // fused qk + softmax + PV
    attn_fused<<<dim3(8,64), 256, ATTN_SMEM>>>(qkv, qk, wv);

    // o projection
    mma_gemm<<<dim3(8,32,1), 256, GEMM_SMEM>>>(wv, oW, out, Md, Dd, Dd, Dd, Dd, Dd,
        0,0,0,0,0,0,1, 1.f, ob, nullptr, 0);
    mma_gemm<<<dim3(1,32,1), 256, GEMM_SMEM>>>(wv, oA, h, Md, 64, Dd, Dd, Dd, 192,
        0,0,0,0,0,0,1, 1.f, nullptr, route, 0);
    tr_loraB<<<(Dd*64+255)/256, 256>>>(oB, Bt);
    mma_gemm<<<dim3(8,32,1), 256, GEMM_SMEM>>>(h, Bt, out, Md, Dd, 64, 192, 64, Dd,
        0,0,0,0,0,0,1, 2.0f, nullptr, nullptr, 1);
}

// round 10
// speedup vs baseline: 4.5428x; 1.0216x over previous
#include <cuda_runtime.h>
#include <cstdint>
#include <cstddef>

#define Bd 4
#define Sd 1024
#define Dd 1024
#define Hd 16
#define DHd 64
#define Md (Bd*Sd)
#define OUT_OFF ((size_t)Bd*Sd*Dd)

__device__ float g_qkv[(size_t)Md*3072];
__device__ float g_wv[Md*Dd];
__device__ float g_h[Md*192];
__device__ float g_W3[(size_t)3072*Dd];
__device__ float g_b3[3072];
__device__ float g_AA[192*Dd];
__device__ float g_Bt3f[3072*192];
__device__ float g_Bt[Dd*64];
__device__ float g_g[3072];
__device__ float g_xw[Bd*3072];
__device__ float g_scores[Md];
__device__ float g_wsm[Md];
__device__ float g_pooled[Bd*Dd];
__device__ float g_route[Bd*8];

__device__ __forceinline__ float warpRedSum(float v){
    #pragma unroll
    for (int o=16;o;o>>=1) v += __shfl_xor_sync(0xffffffffu, v, o);
    return v;
}
__device__ __forceinline__ float warpRedMax(float v){
    #pragma unroll
    for (int o=16;o;o>>=1) v = fmaxf(v, __shfl_xor_sync(0xffffffffu, v, o));
    return v;
}
__device__ __forceinline__ float fexp(float x){
    float t = x * 1.4426950408889634f;
    t = fmaxf(t, -126.0f);
    float ti = floorf(t);
    float f = t - ti;
    float p = 1.5403530393381608e-4f;
    p = fmaf(p, f, 1.3333558146428443e-3f);
    p = fmaf(p, f, 9.6181291076284770e-3f);
    p = fmaf(p, f, 5.5504108664821580e-2f);
    p = fmaf(p, f, 2.4022650695910070e-1f);
    p = fmaf(p, f, 6.9314718055994530e-1f);
    p = fmaf(p, f, 1.0f);
    return __int_as_float(((int)ti + 127) << 23) * p;
}
__device__ __forceinline__ uint32_t f2tf(float f){
    uint32_t r; asm("cvt.rna.tf32.f32 %0, %1;" : "=r"(r) : "f"(f)); return r;
}
__device__ __forceinline__ void mma8(float* d, const uint32_t* a, const uint32_t* b){
    asm volatile("mma.sync.aligned.m16n8k8.row.col.f32.tf32.tf32.f32 "
        "{%0,%1,%2,%3}, {%4,%5,%6,%7}, {%8,%9}, {%0,%1,%2,%3};"
        : "+f"(d[0]),"+f"(d[1]),"+f"(d[2]),"+f"(d[3])
        : "r"(a[0]),"r"(a[1]),"r"(a[2]),"r"(a[3]), "r"(b[0]),"r"(b[1]));
}
__device__ __forceinline__ uint32_t smem_u32(const void* p){
    uint32_t a; asm("{ .reg .u64 t; cvta.to.shared.u64 t, %1; cvt.u32.u64 %0, t; }" : "=r"(a) : "l"(p));
    return a;
}
__device__ __forceinline__ void cpa16(uint32_t dst, const void* src, int ok){
    asm volatile("cp.async.cg.shared.global [%0], [%1], 16, %2;"
        :: "r"(dst), "l"(src), "r"(ok ? 16 : 0));
}
#define CPA_COMMIT asm volatile("cp.async.commit_group;" ::: "memory")
#define CPA_WAIT(n) asm volatile("cp.async.wait_group %0;" :: "n"(n) : "memory")

// ---- tf32 mma.sync GEMM with split-K sources: C = alpha*[A|A2]([B|B2])^T ----
#define GSTRIDE 36
#define GEMM_SMEM (4*128*GSTRIDE*4)
__global__ __launch_bounds__(256,2)
void mma_gemm(const float* __restrict__ A, const float* __restrict__ B, float* __restrict__ C,
              int M, int N, int K, int lda, int ldb, int ldc,
              const float* __restrict__ A2, int lda2, const float* __restrict__ B2, int ldb2, int K1,
              long long sAb, long long sAh, long long sBb, long long sBh,
              long long sCb, long long sCh, int ZH,
              float alpha, const float* __restrict__ bias, const float* __restrict__ route, int addC)
{
    extern __shared__ __align__(16) float sm[];
    float* As = sm;
    float* Bs = sm + 2*128*GSTRIDE;

    const int tid = threadIdx.x, wid = tid >> 5, lane = tid & 31;
    const int wm = wid >> 2, wn = wid & 3;
    const int lr = lane >> 2, lc = lane & 3;
    int z = blockIdx.z, zb = z / ZH, zh = z - zb*ZH;
    A += (size_t)zb*sAb + (size_t)zh*sAh;
    B += (size_t)zb*sBb + (size_t)zh*sBh;
    C += (size_t)zb*sCb + (size_t)zh*sCh;
    const int bm = blockIdx.y*128, bn = blockIdx.x*128;

    const int row = tid >> 3, c4 = (tid & 7) << 2;
    const float* Ab  = A  + (size_t)bm*lda;
    const float* A2b = A2 + (size_t)bm*lda2;
    const float* Bb  = B  + (size_t)bn*ldb;
    const float* B2b = B2 + (size_t)bn*ldb2;
    const int nch = K >> 5;
    const uint32_t sA = smem_u32(As), sB = smem_u32(Bs);

    auto issue = [&](int c){
        int buf = c & 1;
        int k0 = c << 5;
        bool sec = (k0 >= K1);
        const float* Asrc = sec ? A2b : Ab;
        const float* Bsrc = sec ? B2b : Bb;
        int la = sec ? lda2 : lda;
        int lb = sec ? ldb2 : ldb;
        int kk = (sec ? (k0 - K1) : k0) + c4;
        #pragma unroll
        for (int j=0;j<4;j++){
            int rr = row + j*32;
            int bok = (bn + rr) < N;
            cpa16(sA + (uint32_t)((buf*128 + rr)*GSTRIDE + c4)*4,
                  Asrc + (size_t)rr*la + kk, 1);
            cpa16(sB + (uint32_t)((buf*128 + rr)*GSTRIDE + c4)*4,
                  Bsrc + (size_t)(bok ? rr : 0)*lb + kk, bok);
        }
        CPA_COMMIT;
    };

    float acc[4][4][4];
    #pragma unroll
    for (int i=0;i<4;i++)
        #pragma unroll
        for (int j=0;j<4;j++)
            #pragma unroll
            for (int r=0;r<4;r++) acc[i][j][r]=0.f;

    issue(0);
    if (nch > 1){ issue(1); CPA_WAIT(1); } else CPA_WAIT(0);
    __syncthreads();

    for (int c = 0; c < nch; c++){
        const float* Ac = As + (c&1)*128*GSTRIDE;
        const float* Bc = Bs + (c&1)*128*GSTRIDE;
        #pragma unroll
        for (int ks=0; ks<4; ks++){
            uint32_t af[4][4], bf[4][2];
            #pragma unroll
            for (int mt=0; mt<4; mt++){
                const float* p = Ac + (wm*64 + mt*16)*GSTRIDE + ks*8;
                af[mt][0] = f2tf(p[lr*GSTRIDE + lc]);
                af[mt][1] = f2tf(p[(lr+8)*GSTRIDE + lc]);
                af[mt][2] = f2tf(p[lr*GSTRIDE + lc + 4]);
                af[mt][3] = f2tf(p[(lr+8)*GSTRIDE + lc + 4]);
            }
            #pragma unroll
            for (int nt=0; nt<4; nt++){
                const float* p = Bc + (wn*32 + nt*8)*GSTRIDE + ks*8;
                bf[nt][0] = f2tf(p[lr*GSTRIDE + lc]);
                bf[nt][1] = f2tf(p[lr*GSTRIDE + lc + 4]);
            }
            #pragma unroll
            for (int mt=0; mt<4; mt++)
                #pragma unroll
                for (int nt=0; nt<4; nt++)
                    mma8(acc[mt][nt], af[mt], bf[nt]);
        }
        __syncthreads();
        if (c+2 < nch) issue(c+2);
        if (c+1 < nch){
            if (c+2 < nch) CPA_WAIT(1); else CPA_WAIT(0);
            __syncthreads();
        }
    }

    #pragma unroll
    for (int mt=0; mt<4; mt++){
        #pragma unroll
        for (int nt=0; nt<4; nt++){
            int n = bn + wn*32 + nt*8 + 2*lc;
            if (n >= N) continue;
            int m0 = bm + wm*64 + mt*16 + lr;
            #pragma unroll
            for (int half=0; half<2; half++){
                int m = m0 + half*8;
                float v0 = alpha*acc[mt][nt][half*2+0];
                float v1 = alpha*acc[mt][nt][half*2+1];
                if (route){
                    float rs = route[((m >> 10) << 3) + ((n & 63) >> 3)];
                    v0 *= rs; v1 *= rs;
                }
                if (bias){ v0 += bias[n]; v1 += bias[n+1]; }
                float2* cp = (float2*)(C + (size_t)m*ldc + n);
                if (addC){ float2 o = *cp; v0 += o.x; v1 += o.y; }
                *cp = make_float2(v0, v1);
            }
        }
    }
}

// ---- fused flash attention, FA2 warp layout: P in registers, V row-permuted ----
#define AQS 36
#define AVS 72
#define ATTN_SMEM ((2*128*AQS + 2*128*AQS + 4*32*AVS)*4)
__global__ __launch_bounds__(256,2) void attn_fused(
    const float* __restrict__ qkv, float* __restrict__ qk, float* __restrict__ wv)
{
    extern __shared__ __align__(16) float dsm[];
    float* Qs = dsm;
    float* Ks = dsm + 2*128*AQS;
    float* Vs = Ks + 2*128*AQS;

    const int z = blockIdx.y;
    const int bq = z >> 4, h = z & 15;
    const int bm = blockIdx.x * 128;
    const float* Qg = qkv + (size_t)bq*Sd*3072 + h*64;
    const float* Kg = Qg + 1024;
    const float* Vg = Qg + 2048;
    float* qko = qk + (size_t)z*Sd*Sd;

    const int tid = threadIdx.x, wid = tid >> 5, lane = tid & 31;
    const int lr = lane >> 2, lc = lane & 3;
    const int wr = wid * 16;
    const int rr0 = tid >> 3, c4 = (tid & 7) << 2;
    const uint32_t sQ = smem_u32(Qs), sK = smem_u32(Ks), sV = smem_u32(Vs);

    auto issueK = [&](int ct){
        int kb = ct << 7;
        #pragma unroll
        for (int j=0;j<4;j++){
            int rr = rr0 + j*32;
            #pragma unroll
            for (int ch=0;ch<2;ch++)
                cpa16(sK + (uint32_t)(((ch*128 + rr)*AQS + c4)*4),
                      Kg + (size_t)(kb+rr)*3072 + ch*32 + c4, 1);
        }
        CPA_COMMIT;
    };
    auto issueV = [&](int ct){
        int kb = ct << 7;
        #pragma unroll
        for (int j=0;j<8;j++){
            int idx = tid + (j << 8);
            int vk = idx >> 4, vc4 = (idx & 15) << 2;
            int w8 = vk & 7;
            int slot = (vk & ~7) | (w8 >> 1) | ((w8 & 1) << 2);  // V row permute
            cpa16(sV + (uint32_t)((((slot>>5)*32 + (slot&31))*AVS + vc4)*4),
                  Vg + (size_t)(kb+vk)*3072 + vc4, 1);
        }
        CPA_COMMIT;
    };

    #pragma unroll
    for (int j=0;j<4;j++){
        int rr = rr0 + j*32;
        #pragma unroll
        for (int ch=0;ch<2;ch++)
            cpa16(sQ + (uint32_t)(((ch*128 + rr)*AQS + c4)*4),
                  Qg + (size_t)(bm+rr)*3072 + ch*32 + c4, 1);
    }
    CPA_COMMIT;
    issueK(0); issueV(0);
    CPA_WAIT(1);              // Q + K0 done; V0 may fly
    __syncthreads();

    float runmax[2] = {-1e30f,-1e30f}, runsum[2] = {0.f,0.f};
    float pvacc[8][4];
    #pragma unroll
    for (int i=0;i<8;i++)
        #pragma unroll
        for (int r=0;r<4;r++) pvacc[i][r]=0.f;

    const int m0 = bm + wr + lr;

    for (int ct=0; ct<8; ct++){
        const int kb = ct*128;

        // S = Q K^T : warp owns rows wr..wr+16, all 128 cols
        float sacc[16][4];
        #pragma unroll
        for (int i=0;i<16;i++)
            #pragma unroll
            for (int r=0;r<4;r++) sacc[i][r]=0.f;
        #pragma unroll
        for (int ch=0;ch<2;ch++){
            const float* Qc = Qs + ch*128*AQS;
            const float* Kc = Ks + ch*128*AQS;
            #pragma unroll
            for (int ks=0;ks<4;ks++){
                uint32_t af[4];
                const float* p = Qc + (wr+lr)*AQS + ks*8;
                af[0] = f2tf(p[lc]);
                af[1] = f2tf(p[8*AQS + lc]);
                af[2] = f2tf(p[lc + 4]);
                af[3] = f2tf(p[8*AQS + lc + 4]);
                #pragma unroll
                for (int nt=0;nt<16;nt++){
                    const float* q = Kc + (nt*8+lr)*AQS + ks*8;
                    uint32_t bf[2];
                    bf[0] = f2tf(q[lc]);
                    bf[1] = f2tf(q[lc + 4]);
                    mma8(sacc[nt], af, bf);
                }
            }
        }
        __syncthreads();                 // Ks consumed by all warps
        if (ct < 7) issueK(ct+1);        // K(ct+1) flies during epilogue+softmax

        // scale + write qk logits
        #pragma unroll
        for (int nt=0;nt<16;nt++){
            #pragma unroll
            for (int r=0;r<4;r++) sacc[nt][r] *= 0.125f;
            int n = kb + nt*8 + 2*lc;
            *(float2*)(qko + (size_t)m0*Sd + n)     = make_float2(sacc[nt][0], sacc[nt][1]);
            *(float2*)(qko + (size_t)(m0+8)*Sd + n) = make_float2(sacc[nt][2], sacc[nt][3]);
        }
        // online softmax fully in registers (rows owned by warp; quad shfl only)
        #pragma unroll
        for (int half=0;half<2;half++){
            float tm = -1e30f;
            #pragma unroll
            for (int nt=0;nt<16;nt++)
                tm = fmaxf(tm, fmaxf(sacc[nt][half*2], sacc[nt][half*2+1]));
            tm = fmaxf(tm, __shfl_xor_sync(0xffffffffu, tm, 1));
            tm = fmaxf(tm, __shfl_xor_sync(0xffffffffu, tm, 2));
            float mn = fmaxf(runmax[half], tm);
            float f = fexp(runmax[half] - mn);
            runmax[half] = mn;
            runsum[half] *= f;
            #pragma unroll
            for (int nt=0;nt<8;nt++){
                pvacc[nt][half*2+0] *= f;
                pvacc[nt][half*2+1] *= f;
            }
            float s = 0.f;
            #pragma unroll
            for (int nt=0;nt<16;nt++){
                float p0 = fexp(sacc[nt][half*2+0] - mn);
                float p1 = fexp(sacc[nt][half*2+1] - mn);
                s += p0 + p1;
                sacc[nt][half*2+0] = p0;
                sacc[nt][half*2+1] = p1;
            }
            s += __shfl_xor_sync(0xffffffffu, s, 1);
            s += __shfl_xor_sync(0xffffffffu, s, 2);
            runsum[half] += s;
        }
        if (ct < 7) CPA_WAIT(1); else CPA_WAIT(0);   // V(ct) complete (K(ct+1) may fly)
        __syncthreads();

        // PV: P from registers (C-frag reused as A-frag; V rows pre-permuted)
        #pragma unroll
        for (int ks=0;ks<16;ks++){
            uint32_t af[4];
            af[0] = f2tf(sacc[ks][0]);
            af[1] = f2tf(sacc[ks][2]);
            af[2] = f2tf(sacc[ks][1]);
            af[3] = f2tf(sacc[ks][3]);
            const float* pbase = Vs + (ks>>2)*32*AVS + ((ks&3)*8)*AVS;
            #pragma unroll
            for (int nt=0;nt<8;nt++){
                const float* p = pbase + nt*8;
                uint32_t bf[2];
                bf[0] = f2tf(p[lc*AVS + lr]);
                bf[1] = f2tf(p[(lc+4)*AVS + lr]);
                mma8(pvacc[nt], af, bf);
            }
        }
        __syncthreads();                 // Vs consumed
        if (ct < 7){
            issueV(ct+1);                // V(ct+1) flies during next S
            CPA_WAIT(1);                 // K(ct+1) complete (V(ct+1) pending)
            __syncthreads();
        }
    }

    float* Cw = wv + (size_t)bq*Sd*Dd + h*DHd;
    float inv0 = 1.f / runsum[0], inv1 = 1.f / runsum[1];
    #pragma unroll
    for (int nt=0;nt<8;nt++){
        int n = nt*8 + 2*lc;
        *(float2*)(Cw + (size_t)m0*Dd + n)     = make_float2(pvacc[nt][0]*inv0, pvacc[nt][1]*inv0);
        *(float2*)(Cw + (size_t)(m0+8)*Dd + n) = make_float2(pvacc[nt][2]*inv1, pvacc[nt][3]*inv1);
    }
}

// ---- router (conv folded out algebraically) ----
__global__ __launch_bounds__(256) void r_g(const float* __restrict__ cw,
                                           const float* __restrict__ pw, float* __restrict__ g){
    int idx = blockIdx.x*8 + (threadIdx.x >> 5);
    int lane = threadIdx.x & 31;
    float acc = 0.f;
    for (int o = lane; o < Dd; o += 32)
        acc = fmaf(pw[o], cw[(size_t)o*3072 + idx], acc);
    acc = warpRedSum(acc);
    if (lane == 0) g[idx] = acc;
}
__global__ __launch_bounds__(128) void r_scores(const float* __restrict__ x,
                                                const float* __restrict__ g, float* __restrict__ scores){
    int m = blockIdx.x;
    int b = m >> 10, s = m & 1023;
    int tid = threadIdx.x;
    __shared__ float gs[3072];
    #pragma unroll
    for (int j=0;j<24;j++) gs[tid + j*128] = g[tid + j*128];
    __syncthreads();
    const float* x0 = x + (size_t)m*Dd;
    const float* xm = x0 - Dd;
    const float* xp1 = x0 + Dd;
    bool okm = (s > 0), okp = (s < 1023);
    float acc = 0.f;
    #pragma unroll
    for (int j=0;j<8;j++){
        int i = tid + j*128;
        float vm = okm ? xm[i] : 0.f;
        float v0 = x0[i];
        float vp = okp ? xp1[i] : 0.f;
        const float* gg = gs + i*3;
        acc = fmaf(gg[0], vm, acc);
        acc = fmaf(gg[1], v0, acc);
        acc = fmaf(gg[2], vp, acc);
    }
    acc = warpRedSum(acc);
    __shared__ float sm[4];
    if ((tid&31)==0) sm[tid>>5]=acc;
    __syncthreads();
    if (tid==0) scores[m] = sm[0]+sm[1]+sm[2]+sm[3];
}
__global__ void softmax_w(const float* __restrict__ scores, float* __restrict__ w){
    int b = blockIdx.x, tid = threadIdx.x;
    float4 v = *(const float4*)(scores + (size_t)b*Sd + tid*4);
    float m = fmaxf(fmaxf(v.x,v.y), fmaxf(v.z,v.w));
    m = warpRedMax(m);
    __shared__ float sm[8];
    __shared__ float gmax, gisum;
    if ((tid&31)==0) sm[tid>>5]=m;
    __syncthreads();
    if (tid==0){ float mm=sm[0]; for(int i=1;i<8;i++) mm=fmaxf(mm,sm[i]); gmax=mm; }
    __syncthreads();
    float e0=expf(v.x-gmax), e1=expf(v.y-gmax), e2=expf(v.z-gmax), e3=expf(v.w-gmax);
    float s = e0+e1+e2+e3;
    s = warpRedSum(s);
    if ((tid&31)==0) sm[tid>>5]=s;
    __syncthreads();
    if (tid==0){ float ss=0; for(int i=0;i<8;i++) ss+=sm[i]; gisum = 1.f/ss; }
    __syncthreads();
    *(float4*)(w + (size_t)b*Sd + tid*4) = make_float4(e0*gisum, e1*gisum, e2*gisum, e3*gisum);
}
__global__ __launch_bounds__(128) void r_xw(const float* __restrict__ x,
                                            const float* __restrict__ w, float* __restrict__ xw){
    int b = blockIdx.y;
    int i = blockIdx.x*128 + threadIdx.x;
    __shared__ float ws[Sd];
    for (int j = threadIdx.x; j < Sd; j += 128) ws[j] = w[(size_t)b*Sd + j];
    __syncthreads();
    const float* xb = x + (size_t)b*Sd*Dd + i;
    float a0=0.f, a1=0.f, a2=0.f;
    for (int j=0;j<Sd;j++){
        float v = xb[(size_t)j*Dd];
        if (j <= 1022) a0 = fmaf(ws[j+1], v, a0);
        a1 = fmaf(ws[j], v, a1);
        if (j >= 1) a2 = fmaf(ws[j-1], v, a2);
    }
    float* o = xw + (size_t)b*3072 + i*3;
    o[0]=a0; o[1]=a1; o[2]=a2;
}
__global__ __launch_bounds__(256) void r_pooled(const float* __restrict__ cw,
                                                const float* __restrict__ cb,
                                                const float* __restrict__ xw, float* __restrict__ pooled){
    int b = blockIdx.y;
    int d = blockIdx.x*8 + (threadIdx.x >> 5);
    int lane = threadIdx.x & 31;
    __shared__ float sx[3072];
    for (int j = threadIdx.x; j < 3072; j += 256) sx[j] = xw[(size_t)b*3072 + j];
    __syncthreads();
    const float4* cr = (const float4*)(cw + (size_t)d*3072);
    float acc = 0.f;
    #pragma unroll
    for (int j=0;j<24;j++){
        float4 c = cr[lane + j*32];
        const float* s = sx + (lane + j*32)*4;
        acc += c.x*s[0] + c.y*s[1] + c.z*s[2] + c.w*s[3];
    }
    acc = warpRedSum(acc);
    if (lane == 0) pooled[b*Dd + d] = acc + cb[d];
}
__global__ void route_k(const float* __restrict__ pooled, const float* __restrict__ rw,
                        const float* __restrict__ rb, float* __restrict__ route){
    int tid = threadIdx.x;
    int e = tid >> 5, lane = tid & 31;
    __shared__ float lg[8];
    for (int b=0;b<Bd;b++){
        float s=0.f;
        for (int d=lane; d<Dd; d+=32) s += pooled[b*Dd+d]*rw[e*Dd+d];
        s = warpRedSum(s);
        if (lane==0) lg[e] = s + rb[e];
        __syncthreads();
        if (tid==0){
            float mm=lg[0];
            for (int i=1;i<8;i++) mm=fmaxf(mm,lg[i]);
            float ex[8]; float ss=0.f;
            for (int i=0;i<8;i++){ ex[i]=expf(lg[i]-mm); ss+=ex[i]; }
            float inv = 1.f/ss;
            for (int i=0;i<8;i++) route[b*8+i]=ex[i]*inv;
        }
        __syncthreads();
    }
}

// ---- prep ----
// block-diagonal [3072 x 192] LoRA-B for q/k/v, pre-scaled by 2 (LORA_SCALING)
__global__ void build_Bt3f(const float* __restrict__ B0, const float* __restrict__ B1,
                           const float* __restrict__ B2, float* __restrict__ Bt){
    int idx = blockIdx.x*blockDim.x + threadIdx.x;
    if (idx >= 3072*192) return;
    int n = idx / 192, c = idx - n*192;
    int p = n >> 10, pp = c >> 6;
    float val = 0.f;
    if (pp == p){
        int e = (c >> 3) & 7, r = c & 7;
        const float* Bp = (p==0) ? B0 : (p==1 ? B1 : B2);
        val = 2.f * Bp[(size_t)e*Dd*8 + (size_t)(n & 1023)*8 + r];
    }
    Bt[idx] = val;
}
__global__ void tr_loraB2x(const float* __restrict__ Bp, float* __restrict__ Bt){
    int idx = blockIdx.x*blockDim.x + threadIdx.x;
    if (idx >= Dd*64) return;
    int n = idx >> 6, e = (idx >> 3) & 7, r = idx & 7;
    Bt[idx] = 2.f * Bp[(size_t)e*Dd*8 + (size_t)n*8 + r];
}
__global__ void fill_b3(const float* __restrict__ qb, const float* __restrict__ vb,
                        float* __restrict__ b3){
    int i = blockIdx.x*blockDim.x + threadIdx.x;
    if (i >= 3072) return;
    b3[i] = (i < 1024) ? qb[i] : (i < 2048 ? 0.f : vb[i-2048]);
}

// ---- host launcher ----
extern "C" void kernel_launch(void* const* d_in, const int* in_sizes, int n_in,
                              void* d_out, int out_size)
{
    (void)in_sizes; (void)n_in; (void)out_size;
    const float* x      = (const float*)d_in[0];
    const float* conv_w = (const float*)d_in[1];
    const float* conv_b = (const float*)d_in[2];
    const float* pool_w = (const float*)d_in[3];
    const float* pool_b = (const float*)d_in[4];
    const float* rlin_w = (const float*)d_in[5];
    const float* rlin_b = (const float*)d_in[6];
    const float* qW=(const float*)d_in[7],  *qb=(const float*)d_in[8];
    const float* qA=(const float*)d_in[9],  *qB=(const float*)d_in[10];
    const float* kW=(const float*)d_in[11], *kA=(const float*)d_in[12], *kB=(const float*)d_in[13];
    const float* vW=(const float*)d_in[14], *vb=(const float*)d_in[15];
    const float* vA=(const float*)d_in[16], *vB=(const float*)d_in[17];
    const float* oW=(const float*)d_in[18], *ob=(const float*)d_in[19];
    const float* oA=(const float*)d_in[20], *oB=(const float*)d_in[21];
    (void)pool_b;

    float* out = (float*)d_out;
    float* qk  = out + OUT_OFF;

    float *qkv,*wv,*h,*W3,*b3,*AA,*Bt3f,*Bt,*gv,*xw,*scores,*w,*pooled,*route;
    cudaGetSymbolAddress((void**)&qkv, g_qkv);
    cudaGetSymbolAddress((void**)&wv, g_wv);
    cudaGetSymbolAddress((void**)&h,  g_h);
    cudaGetSymbolAddress((void**)&W3,  g_W3);
    cudaGetSymbolAddress((void**)&b3,  g_b3);
    cudaGetSymbolAddress((void**)&AA,  g_AA);
    cudaGetSymbolAddress((void**)&Bt3f, g_Bt3f);
    cudaGetSymbolAddress((void**)&Bt,  g_Bt);
    cudaGetSymbolAddress((void**)&gv,  g_g);
    cudaGetSymbolAddress((void**)&xw,  g_xw);
    cudaGetSymbolAddress((void**)&scores, g_scores);
    cudaGetSymbolAddress((void**)&w,  g_wsm);
    cudaGetSymbolAddress((void**)&pooled, g_pooled);
    cudaGetSymbolAddress((void**)&route,  g_route);

    cudaFuncSetAttribute(mma_gemm, cudaFuncAttributeMaxDynamicSharedMemorySize, GEMM_SMEM);
    cudaFuncSetAttribute(attn_fused, cudaFuncAttributeMaxDynamicSharedMemorySize, ATTN_SMEM);

    cudaMemcpyAsync(W3,            qW, (size_t)Dd*Dd*4, cudaMemcpyDeviceToDevice);
    cudaMemcpyAsync(W3 + Dd*Dd,    kW, (size_t)Dd*Dd*4, cudaMemcpyDeviceToDevice);
    cudaMemcpyAsync(W3 + 2*Dd*Dd,  vW, (size_t)Dd*Dd*4, cudaMemcpyDeviceToDevice);
    cudaMemcpyAsync(AA,            qA, (size_t)64*Dd*4, cudaMemcpyDeviceToDevice);
    cudaMemcpyAsync(AA + 64*Dd,    kA, (size_t)64*Dd*4, cudaMemcpyDeviceToDevice);
    cudaMemcpyAsync(AA + 128*Dd,   vA, (size_t)64*Dd*4, cudaMemcpyDeviceToDevice);
    fill_b3<<<12, 256>>>(qb, vb, b3);
    build_Bt3f<<<(3072*192 + 255)/256, 256>>>(qB, kB, vB, Bt3f);
    tr_loraB2x<<<(Dd*64 + 255)/256, 256>>>(oB, Bt);

    // router (conv algebraically folded)
    r_g<<<384, 256>>>(conv_w, pool_w, gv);
    r_scores<<<Md, 128>>>(x, gv, scores);
    softmax_w<<<Bd, 256>>>(scores, w);
    r_xw<<<dim3(8,Bd), 128>>>(x, w, xw);
    r_pooled<<<dim3(128,Bd), 256>>>(conv_w, conv_b, xw, pooled);
    route_k<<<1, 256>>>(pooled, rlin_w, rlin_b, route);

    // batched LoRA-A (route-scaled): h[4096,192]
    mma_gemm<<<dim3(2,32,1), 256, GEMM_SMEM>>>(x, AA, h, Md, 192, Dd, Dd, Dd, 192,
        x, Dd, AA, Dd, Dd,
        0,0,0,0,0,0,1, 1.f, nullptr, route, 0);

    // merged qkv = [x|h]·[W3|Bt3f]^T + b3  (base + LoRA-B in one pass, K=1216)
    mma_gemm<<<dim3(24,32,1), 256, GEMM_SMEM>>>(x, W3, qkv, Md, 3072, 1216, Dd, Dd, 3072,
        h, 192, Bt3f, 192, Dd,
        0,0,0,0,0,0,1, 1.f, b3, nullptr, 0);

    // fused qk + softmax + PV
    attn_fused<<<dim3(8,64), 256, ATTN_SMEM>>>(qkv, qk, wv);

    // o LoRA-A (route-scaled) into h[:,0:64]
    mma_gemm<<<dim3(1,32,1), 256, GEMM_SMEM>>>(wv, oA, h, Md, 64, Dd, Dd, Dd, 192,
        wv, Dd, oA, Dd, Dd,
        0,0,0,0,0,0,1, 1.f, nullptr, route, 0);

    // merged o = [wv|h]·[oW|BtO]^T + ob  (K=1088)
    mma_gemm<<<dim3(8,32,1), 256, GEMM_SMEM>>>(wv, oW, out, Md, Dd, 1088, Dd, Dd, Dd,
        h, 192, Bt, 64, Dd,
        0,0,0,0,0,0,1, 1.f, ob, nullptr, 0);
}

// round 11
// speedup vs baseline: 4.7122x; 1.0373x over previous
#include <cuda_runtime.h>
#include <cstdint>
#include <cstddef>

#define Bd 4
#define Sd 1024
#define Dd 1024
#define Hd 16
#define DHd 64
#define Md (Bd*Sd)
#define OUT_OFF ((size_t)Bd*Sd*Dd)

__device__ float g_qkv[(size_t)Md*3072];
__device__ float g_wv[Md*Dd];
__device__ float g_h[Md*192];
__device__ float g_Bt3f[3072*192];
__device__ float g_Bt[Dd*64];
__device__ float g_g[3072];
__device__ float g_gpart[8*3072];
__device__ float g_xw[Bd*3072];
__device__ float g_xwpart[8*Bd*3072];
__device__ float g_scores[Md];
__device__ float g_wsm[Md];
__device__ float g_pooled[Bd*Dd];
__device__ float g_route[Bd*8];

__device__ __forceinline__ float warpRedSum(float v){
    #pragma unroll
    for (int o=16;o;o>>=1) v += __shfl_xor_sync(0xffffffffu, v, o);
    return v;
}
__device__ __forceinline__ float warpRedMax(float v){
    #pragma unroll
    for (int o=16;o;o>>=1) v = fmaxf(v, __shfl_xor_sync(0xffffffffu, v, o));
    return v;
}
__device__ __forceinline__ float fexp(float x){
    float t = x * 1.4426950408889634f;
    t = fmaxf(t, -126.0f);
    float ti = floorf(t);
    float f = t - ti;
    float p = 1.5403530393381608e-4f;
    p = fmaf(p, f, 1.3333558146428443e-3f);
    p = fmaf(p, f, 9.6181291076284770e-3f);
    p = fmaf(p, f, 5.5504108664821580e-2f);
    p = fmaf(p, f, 2.4022650695910070e-1f);
    p = fmaf(p, f, 6.9314718055994530e-1f);
    p = fmaf(p, f, 1.0f);
    return __int_as_float(((int)ti + 127) << 23) * p;
}
__device__ __forceinline__ uint32_t f2tf(float f){
    uint32_t r; asm("cvt.rna.tf32.f32 %0, %1;" : "=r"(r) : "f"(f)); return r;
}
__device__ __forceinline__ void mma8(float* d, const uint32_t* a, const uint32_t* b){
    asm volatile("mma.sync.aligned.m16n8k8.row.col.f32.tf32.tf32.f32 "
        "{%0,%1,%2,%3}, {%4,%5,%6,%7}, {%8,%9}, {%0,%1,%2,%3};"
        : "+f"(d[0]),"+f"(d[1]),"+f"(d[2]),"+f"(d[3])
        : "r"(a[0]),"r"(a[1]),"r"(a[2]),"r"(a[3]), "r"(b[0]),"r"(b[1]));
}
__device__ __forceinline__ uint32_t smem_u32(const void* p){
    uint32_t a; asm("{ .reg .u64 t; cvta.to.shared.u64 t, %1; cvt.u32.u64 %0, t; }" : "=r"(a) : "l"(p));
    return a;
}
__device__ __forceinline__ void cpa16(uint32_t dst, const void* src, int ok){
    asm volatile("cp.async.cg.shared.global [%0], [%1], 16, %2;"
        :: "r"(dst), "l"(src), "r"(ok ? 16 : 0));
}
#define CPA_COMMIT asm volatile("cp.async.commit_group;" ::: "memory")
#define CPA_WAIT(n) asm volatile("cp.async.wait_group %0;" :: "n"(n) : "memory")

// ---- tf32 mma.sync GEMM, segmented-B + split-K: C = alpha*[A|A2]([Bseg|BK2])^T ----
#define GSTRIDE 36
#define GEMM_SMEM (4*128*GSTRIDE*4)
__global__ __launch_bounds__(256,2)
void mma_gemm(const float* __restrict__ A,
              const float* __restrict__ B0, const float* __restrict__ B1,
              const float* __restrict__ B2s, int segShift,
              float* __restrict__ C,
              int M, int N, int K, int lda, int ldb, int ldc,
              const float* __restrict__ A2, int lda2,
              const float* __restrict__ BK2, int ldbk2, int K1,
              float alpha,
              const float* __restrict__ bias0, const float* __restrict__ bias1,
              const float* __restrict__ bias2,
              const float* __restrict__ route, int addC)
{
    extern __shared__ __align__(16) float sm[];
    float* As = sm;
    float* Bs = sm + 2*128*GSTRIDE;

    const int tid = threadIdx.x, wid = tid >> 5, lane = tid & 31;
    const int wm = wid >> 2, wn = wid & 3;
    const int lr = lane >> 2, lc = lane & 3;
    const int bm = blockIdx.y*128, bn = blockIdx.x*128;

    const int row = tid >> 3, c4 = (tid & 7) << 2;
    const float* Ab  = A  + (size_t)bm*lda;
    const float* A2b = A2 + (size_t)bm*lda2;
    const int nch = K >> 5;
    const int segMask = (segShift >= 0) ? ((1 << segShift) - 1) : -1;
    const uint32_t sA = smem_u32(As), sB = smem_u32(Bs);

    auto issue = [&](int c){
        int buf = c & 1;
        int k0 = c << 5;
        bool sec = (k0 >= K1);
        const float* Asrc = sec ? A2b : Ab;
        int la = sec ? lda2 : lda;
        int kk = (sec ? (k0 - K1) : k0) + c4;
        #pragma unroll
        for (int j=0;j<4;j++){
            int rr = row + j*32;
            int n = bn + rr;
            int bok = n < N;
            cpa16(sA + (uint32_t)((buf*128 + rr)*GSTRIDE + c4)*4,
                  Asrc + (size_t)rr*la + kk, 1);
            const float* Bsrc;
            if (sec){
                Bsrc = BK2 + (size_t)(bok ? n : 0)*ldbk2;
            } else if (segShift >= 0){
                int sel = bok ? (n >> segShift) : 0;
                int rowb = bok ? (n & segMask) : 0;
                const float* Bp = (sel==0) ? B0 : (sel==1 ? B1 : B2s);
                Bsrc = Bp + (size_t)rowb*ldb;
            } else {
                Bsrc = B0 + (size_t)(bok ? n : 0)*ldb;
            }
            cpa16(sB + (uint32_t)((buf*128 + rr)*GSTRIDE + c4)*4, Bsrc + kk, bok);
        }
        CPA_COMMIT;
    };

    float acc[4][4][4];
    #pragma unroll
    for (int i=0;i<4;i++)
        #pragma unroll
        for (int j=0;j<4;j++)
            #pragma unroll
            for (int r=0;r<4;r++) acc[i][j][r]=0.f;

    issue(0);
    if (nch > 1){ issue(1); CPA_WAIT(1); } else CPA_WAIT(0);
    __syncthreads();

    for (int c = 0; c < nch; c++){
        const float* Ac = As + (c&1)*128*GSTRIDE;
        const float* Bc = Bs + (c&1)*128*GSTRIDE;
        #pragma unroll
        for (int ks=0; ks<4; ks++){
            uint32_t af[4][4], bf[4][2];
            #pragma unroll
            for (int mt=0; mt<4; mt++){
                const float* p = Ac + (wm*64 + mt*16)*GSTRIDE + ks*8;
                af[mt][0] = f2tf(p[lr*GSTRIDE + lc]);
                af[mt][1] = f2tf(p[(lr+8)*GSTRIDE + lc]);
                af[mt][2] = f2tf(p[lr*GSTRIDE + lc + 4]);
                af[mt][3] = f2tf(p[(lr+8)*GSTRIDE + lc + 4]);
            }
            #pragma unroll
            for (int nt=0; nt<4; nt++){
                const float* p = Bc + (wn*32 + nt*8)*GSTRIDE + ks*8;
                bf[nt][0] = f2tf(p[lr*GSTRIDE + lc]);
                bf[nt][1] = f2tf(p[lr*GSTRIDE + lc + 4]);
            }
            #pragma unroll
            for (int mt=0; mt<4; mt++)
                #pragma unroll
                for (int nt=0; nt<4; nt++)
                    mma8(acc[mt][nt], af[mt], bf[nt]);
        }
        __syncthreads();
        if (c+2 < nch) issue(c+2);
        if (c+1 < nch){
            if (c+2 < nch) CPA_WAIT(1); else CPA_WAIT(0);
            __syncthreads();
        }
    }

    #pragma unroll
    for (int mt=0; mt<4; mt++){
        #pragma unroll
        for (int nt=0; nt<4; nt++){
            int n = bn + wn*32 + nt*8 + 2*lc;
            if (n >= N) continue;
            int m0 = bm + wm*64 + mt*16 + lr;
            float bv0 = 0.f, bv1 = 0.f;
            if (bias0){
                if (segShift >= 0){
                    int sel = n >> segShift;
                    const float* bp = (sel==0) ? bias0 : (sel==1 ? bias1 : bias2);
                    if (bp){ bv0 = bp[n & segMask]; bv1 = bp[(n+1) & segMask]; }
                } else { bv0 = bias0[n]; bv1 = bias0[n+1]; }
            }
            #pragma unroll
            for (int half=0; half<2; half++){
                int m = m0 + half*8;
                float v0 = alpha*acc[mt][nt][half*2+0];
                float v1 = alpha*acc[mt][nt][half*2+1];
                if (route){
                    float rs = route[((m >> 10) << 3) + ((n & 63) >> 3)];
                    v0 *= rs; v1 *= rs;
                }
                v0 += bv0; v1 += bv1;
                float2* cp = (float2*)(C + (size_t)m*ldc + n);
                if (addC){ float2 o = *cp; v0 += o.x; v1 += o.y; }
                *cp = make_float2(v0, v1);
            }
        }
    }
}

// ---- fused flash attention (unchanged from R9) ----
#define AQS 36
#define AVS 72
#define ATTN_SMEM ((2*128*AQS + 2*128*AQS + 4*32*AVS)*4)
__global__ __launch_bounds__(256,2) void attn_fused(
    const float* __restrict__ qkv, float* __restrict__ qk, float* __restrict__ wv)
{
    extern __shared__ __align__(16) float dsm[];
    float* Qs = dsm;
    float* Ks = dsm + 2*128*AQS;
    float* Vs = Ks + 2*128*AQS;

    const int z = blockIdx.y;
    const int bq = z >> 4, h = z & 15;
    const int bm = blockIdx.x * 128;
    const float* Qg = qkv + (size_t)bq*Sd*3072 + h*64;
    const float* Kg = Qg + 1024;
    const float* Vg = Qg + 2048;
    float* qko = qk + (size_t)z*Sd*Sd;

    const int tid = threadIdx.x, wid = tid >> 5, lane = tid & 31;
    const int lr = lane >> 2, lc = lane & 3;
    const int wr = wid * 16;
    const int rr0 = tid >> 3, c4 = (tid & 7) << 2;
    const uint32_t sQ = smem_u32(Qs), sK = smem_u32(Ks), sV = smem_u32(Vs);

    auto issueK = [&](int ct){
        int kb = ct << 7;
        #pragma unroll
        for (int j=0;j<4;j++){
            int rr = rr0 + j*32;
            #pragma unroll
            for (int ch=0;ch<2;ch++)
                cpa16(sK + (uint32_t)(((ch*128 + rr)*AQS + c4)*4),
                      Kg + (size_t)(kb+rr)*3072 + ch*32 + c4, 1);
        }
        CPA_COMMIT;
    };
    auto issueV = [&](int ct){
        int kb = ct << 7;
        #pragma unroll
        for (int j=0;j<8;j++){
            int idx = tid + (j << 8);
            int vk = idx >> 4, vc4 = (idx & 15) << 2;
            int w8 = vk & 7;
            int slot = (vk & ~7) | (w8 >> 1) | ((w8 & 1) << 2);
            cpa16(sV + (uint32_t)((((slot>>5)*32 + (slot&31))*AVS + vc4)*4),
                  Vg + (size_t)(kb+vk)*3072 + vc4, 1);
        }
        CPA_COMMIT;
    };

    #pragma unroll
    for (int j=0;j<4;j++){
        int rr = rr0 + j*32;
        #pragma unroll
        for (int ch=0;ch<2;ch++)
            cpa16(sQ + (uint32_t)(((ch*128 + rr)*AQS + c4)*4),
                  Qg + (size_t)(bm+rr)*3072 + ch*32 + c4, 1);
    }
    CPA_COMMIT;
    issueK(0); issueV(0);
    CPA_WAIT(1);
    __syncthreads();

    float runmax[2] = {-1e30f,-1e30f}, runsum[2] = {0.f,0.f};
    float pvacc[8][4];
    #pragma unroll
    for (int i=0;i<8;i++)
        #pragma unroll
        for (int r=0;r<4;r++) pvacc[i][r]=0.f;

    const int m0 = bm + wr + lr;

    for (int ct=0; ct<8; ct++){
        const int kb = ct*128;

        float sacc[16][4];
        #pragma unroll
        for (int i=0;i<16;i++)
            #pragma unroll
            for (int r=0;r<4;r++) sacc[i][r]=0.f;
        #pragma unroll
        for (int ch=0;ch<2;ch++){
            const float* Qc = Qs + ch*128*AQS;
            const float* Kc = Ks + ch*128*AQS;
            #pragma unroll
            for (int ks=0;ks<4;ks++){
                uint32_t af[4];
                const float* p = Qc + (wr+lr)*AQS + ks*8;
                af[0] = f2tf(p[lc]);
                af[1] = f2tf(p[8*AQS + lc]);
                af[2] = f2tf(p[lc + 4]);
                af[3] = f2tf(p[8*AQS + lc + 4]);
                #pragma unroll
                for (int nt=0;nt<16;nt++){
                    const float* q = Kc + (nt*8+lr)*AQS + ks*8;
                    uint32_t bf[2];
                    bf[0] = f2tf(q[lc]);
                    bf[1] = f2tf(q[lc + 4]);
                    mma8(sacc[nt], af, bf);
                }
            }
        }
        __syncthreads();
        if (ct < 7) issueK(ct+1);

        #pragma unroll
        for (int nt=0;nt<16;nt++){
            #pragma unroll
            for (int r=0;r<4;r++) sacc[nt][r] *= 0.125f;
            int n = kb + nt*8 + 2*lc;
            *(float2*)(qko + (size_t)m0*Sd + n)     = make_float2(sacc[nt][0], sacc[nt][1]);
            *(float2*)(qko + (size_t)(m0+8)*Sd + n) = make_float2(sacc[nt][2], sacc[nt][3]);
        }
        #pragma unroll
        for (int half=0;half<2;half++){
            float tm = -1e30f;
            #pragma unroll
            for (int nt=0;nt<16;nt++)
                tm = fmaxf(tm, fmaxf(sacc[nt][half*2], sacc[nt][half*2+1]));
            tm = fmaxf(tm, __shfl_xor_sync(0xffffffffu, tm, 1));
            tm = fmaxf(tm, __shfl_xor_sync(0xffffffffu, tm, 2));
            float mn = fmaxf(runmax[half], tm);
            float f = fexp(runmax[half] - mn);
            runmax[half] = mn;
            runsum[half] *= f;
            #pragma unroll
            for (int nt=0;nt<8;nt++){
                pvacc[nt][half*2+0] *= f;
                pvacc[nt][half*2+1] *= f;
            }
            float s = 0.f;
            #pragma unroll
            for (int nt=0;nt<16;nt++){
                float p0 = fexp(sacc[nt][half*2+0] - mn);
                float p1 = fexp(sacc[nt][half*2+1] - mn);
                s += p0 + p1;
                sacc[nt][half*2+0] = p0;
                sacc[nt][half*2+1] = p1;
            }
            s += __shfl_xor_sync(0xffffffffu, s, 1);
            s += __shfl_xor_sync(0xffffffffu, s, 2);
            runsum[half] += s;
        }
        if (ct < 7) CPA_WAIT(1); else CPA_WAIT(0);
        __syncthreads();

        #pragma unroll
        for (int ks=0;ks<16;ks++){
            uint32_t af[4];
            af[0] = f2tf(sacc[ks][0]);
            af[1] = f2tf(sacc[ks][2]);
            af[2] = f2tf(sacc[ks][1]);
            af[3] = f2tf(sacc[ks][3]);
            const float* pbase = Vs + (ks>>2)*32*AVS + ((ks&3)*8)*AVS;
            #pragma unroll
            for (int nt=0;nt<8;nt++){
                const float* p = pbase + nt*8;
                uint32_t bf[2];
                bf[0] = f2tf(p[lc*AVS + lr]);
                bf[1] = f2tf(p[(lc+4)*AVS + lr]);
                mma8(pvacc[nt], af, bf);
            }
        }
        __syncthreads();
        if (ct < 7){
            issueV(ct+1);
            CPA_WAIT(1);
            __syncthreads();
        }
    }

    float* Cw = wv + (size_t)bq*Sd*Dd + h*DHd;
    float inv0 = 1.f / runsum[0], inv1 = 1.f / runsum[1];
    #pragma unroll
    for (int nt=0;nt<8;nt++){
        int n = nt*8 + 2*lc;
        *(float2*)(Cw + (size_t)m0*Dd + n)     = make_float2(pvacc[nt][0]*inv0, pvacc[nt][1]*inv0);
        *(float2*)(Cw + (size_t)(m0+8)*Dd + n) = make_float2(pvacc[nt][2]*inv1, pvacc[nt][3]*inv1);
    }
}

// ---- router: coalesced, latency-parallel ----
__global__ __launch_bounds__(256) void r_g(const float* __restrict__ cw,
                                           const float* __restrict__ pw, float* __restrict__ gpart){
    int idx = blockIdx.x*256 + threadIdx.x;     // 0..3071
    int oz = blockIdx.y;                        // 0..7
    const float* base = cw + (size_t)(oz*128)*3072 + idx;
    const float* pwb = pw + oz*128;
    float a0=0.f, a1=0.f;
    #pragma unroll 8
    for (int o=0;o<128;o+=2){
        a0 = fmaf(pwb[o],   base[(size_t)o*3072], a0);
        a1 = fmaf(pwb[o+1], base[(size_t)(o+1)*3072], a1);
    }
    gpart[oz*3072 + idx] = a0 + a1;
}
__global__ void r_gred(const float* __restrict__ gpart, float* __restrict__ g){
    int idx = blockIdx.x*256 + threadIdx.x;
    float s = 0.f;
    #pragma unroll
    for (int oz=0;oz<8;oz++) s += gpart[oz*3072 + idx];
    g[idx] = s;
}
__global__ __launch_bounds__(128) void r_scores(const float* __restrict__ x,
                                                const float* __restrict__ g, float* __restrict__ scores){
    int m = blockIdx.x;
    int b = m >> 10, s = m & 1023;
    int tid = threadIdx.x;
    __shared__ float gs[3072];
    #pragma unroll
    for (int j=0;j<24;j++) gs[tid + j*128] = g[tid + j*128];
    __syncthreads();
    const float* x0 = x + (size_t)m*Dd;
    const float* xm = x0 - Dd;
    const float* xp1 = x0 + Dd;
    bool okm = (s > 0), okp = (s < 1023);
    float acc = 0.f;
    #pragma unroll
    for (int j=0;j<8;j++){
        int i = tid + j*128;
        float vm = okm ? xm[i] : 0.f;
        float v0 = x0[i];
        float vp = okp ? xp1[i] : 0.f;
        const float* gg = gs + i*3;
        acc = fmaf(gg[0], vm, acc);
        acc = fmaf(gg[1], v0, acc);
        acc = fmaf(gg[2], vp, acc);
    }
    acc = warpRedSum(acc);
    __shared__ float sm[4];
    if ((tid&31)==0) sm[tid>>5]=acc;
    __syncthreads();
    if (tid==0) scores[m] = sm[0]+sm[1]+sm[2]+sm[3];
}
__global__ void softmax_w(const float* __restrict__ scores, float* __restrict__ w){
    int b = blockIdx.x, tid = threadIdx.x;
    float4 v = *(const float4*)(scores + (size_t)b*Sd + tid*4);
    float m = fmaxf(fmaxf(v.x,v.y), fmaxf(v.z,v.w));
    m = warpRedMax(m);
    __shared__ float sm[8];
    __shared__ float gmax, gisum;
    if ((tid&31)==0) sm[tid>>5]=m;
    __syncthreads();
    if (tid==0){ float mm=sm[0]; for(int i=1;i<8;i++) mm=fmaxf(mm,sm[i]); gmax=mm; }
    __syncthreads();
    float e0=expf(v.x-gmax), e1=expf(v.y-gmax), e2=expf(v.z-gmax), e3=expf(v.w-gmax);
    float s = e0+e1+e2+e3;
    s = warpRedSum(s);
    if ((tid&31)==0) sm[tid>>5]=s;
    __syncthreads();
    if (tid==0){ float ss=0; for(int i=0;i<8;i++) ss+=sm[i]; gisum = 1.f/ss; }
    __syncthreads();
    *(float4*)(w + (size_t)b*Sd + tid*4) = make_float4(e0*gisum, e1*gisum, e2*gisum, e3*gisum);
}
// xwpart[sc][b][i*3+t] = sum over s-chunk of w[b,s]*x[b,s+t-1,i]
__global__ __launch_bounds__(128) void r_xw(const float* __restrict__ x,
                                            const float* __restrict__ w, float* __restrict__ xwpart){
    int b = blockIdx.y;
    int sc = blockIdx.z;
    int i = blockIdx.x*128 + threadIdx.x;
    int s0 = sc*128;
    __shared__ float ws[130];   // w[s0-1 .. s0+128]
    for (int j = threadIdx.x; j < 130; j += 128){
        int s = s0 - 1 + j;
        ws[j] = ((unsigned)s < 1024u) ? w[(size_t)b*Sd + s] : 0.f;
    }
    __syncthreads();
    const float* xb = x + ((size_t)b*Sd + s0)*Dd + i;
    float a0=0.f, a1=0.f, a2=0.f;
    #pragma unroll 8
    for (int j=0;j<128;j++){
        float v = xb[(size_t)j*Dd];
        a0 = fmaf(ws[j+2], v, a0);   // w[s+1]*x[s]
        a1 = fmaf(ws[j+1], v, a1);   // w[s]*x[s]
        a2 = fmaf(ws[j],   v, a2);   // w[s-1]*x[s]
    }
    float* o = xwpart + ((size_t)(sc*Bd + b))*3072 + i*3;
    o[0]=a0; o[1]=a1; o[2]=a2;
}
__global__ void r_xwred(const float* __restrict__ xwpart, float* __restrict__ xw){
    int idx = blockIdx.x*256 + threadIdx.x;     // Bd*3072
    if (idx >= Bd*3072) return;
    int b = idx / 3072, r = idx - b*3072;
    float s = 0.f;
    #pragma unroll
    for (int sc=0;sc<8;sc++) s += xwpart[((size_t)(sc*Bd + b))*3072 + r];
    xw[(size_t)b*3072 + r] = s;
}
__global__ __launch_bounds__(256) void r_pooled(const float* __restrict__ cw,
                                                const float* __restrict__ cb,
                                                const float* __restrict__ xw, float* __restrict__ pooled){
    int b = blockIdx.y;
    int d = blockIdx.x*8 + (threadIdx.x >> 5);
    int lane = threadIdx.x & 31;
    __shared__ float sx[3072];
    for (int j = threadIdx.x; j < 3072; j += 256) sx[j] = xw[(size_t)b*3072 + j];
    __syncthreads();
    const float4* cr = (const float4*)(cw + (size_t)d*3072);
    float acc = 0.f;
    #pragma unroll
    for (int j=0;j<24;j++){
        float4 c = cr[lane + j*32];
        const float* s = sx + (lane + j*32)*4;
        acc += c.x*s[0] + c.y*s[1] + c.z*s[2] + c.w*s[3];
    }
    acc = warpRedSum(acc);
    if (lane == 0) pooled[b*Dd + d] = acc + cb[d];
}
__global__ void route_k(const float* __restrict__ pooled, const float* __restrict__ rw,
                        const float* __restrict__ rb, float* __restrict__ route){
    int tid = threadIdx.x;
    int e = tid >> 5, lane = tid & 31;
    __shared__ float lg[8];
    for (int b=0;b<Bd;b++){
        float s=0.f;
        for (int d=lane; d<Dd; d+=32) s += pooled[b*Dd+d]*rw[e*Dd+d];
        s = warpRedSum(s);
        if (lane==0) lg[e] = s + rb[e];
        __syncthreads();
        if (tid==0){
            float mm=lg[0];
            for (int i=1;i<8;i++) mm=fmaxf(mm,lg[i]);
            float ex[8]; float ss=0.f;
            for (int i=0;i<8;i++){ ex[i]=expf(lg[i]-mm); ss+=ex[i]; }
            float inv = 1.f/ss;
            for (int i=0;i<8;i++) route[b*8+i]=ex[i]*inv;
        }
        __syncthreads();
    }
}

// ---- prep ----
__global__ void build_Bt3f(const float* __restrict__ B0, const float* __restrict__ B1,
                           const float* __restrict__ B2, float* __restrict__ Bt){
    int idx = blockIdx.x*blockDim.x + threadIdx.x;
    if (idx >= 3072*192) return;
    int n = idx / 192, c = idx - n*192;
    int p = n >> 10, pp = c >> 6;
    float val = 0.f;
    if (pp == p){
        int e = (c >> 3) & 7, r = c & 7;
        const float* Bp = (p==0) ? B0 : (p==1 ? B1 : B2);
        val = 2.f * Bp[(size_t)e*Dd*8 + (size_t)(n & 1023)*8 + r];
    }
    Bt[idx] = val;
}
__global__ void tr_loraB2x(const float* __restrict__ Bp, float* __restrict__ Bt){
    int idx = blockIdx.x*blockDim.x + threadIdx.x;
    if (idx >= Dd*64) return;
    int n = idx >> 6, e = (idx >> 3) & 7, r = idx & 7;
    Bt[idx] = 2.f * Bp[(size_t)e*Dd*8 + (size_t)n*8 + r];
}

// ---- host launcher ----
extern "C" void kernel_launch(void* const* d_in, const int* in_sizes, int n_in,
                              void* d_out, int out_size)
{
    (void)in_sizes; (void)n_in; (void)out_size;
    const float* x      = (const float*)d_in[0];
    const float* conv_w = (const float*)d_in[1];
    const float* conv_b = (const float*)d_in[2];
    const float* pool_w = (const float*)d_in[3];
    const float* pool_b = (const float*)d_in[4];
    const float* rlin_w = (const float*)d_in[5];
    const float* rlin_b = (const float*)d_in[6];
    const float* qW=(const float*)d_in[7],  *qb=(const float*)d_in[8];
    const float* qA=(const float*)d_in[9],  *qB=(const float*)d_in[10];
    const float* kW=(const float*)d_in[11], *kA=(const float*)d_in[12], *kB=(const float*)d_in[13];
    const float* vW=(const float*)d_in[14], *vb=(const float*)d_in[15];
    const float* vA=(const float*)d_in[16], *vB=(const float*)d_in[17];
    const float* oW=(const float*)d_in[18], *ob=(const float*)d_in[19];
    const float* oA=(const float*)d_in[20], *oB=(const float*)d_in[21];
    (void)pool_b;

    float* out = (float*)d_out;
    float* qk  = out + OUT_OFF;

    float *qkv,*wv,*h,*Bt3f,*Bt,*gv,*gpart,*xw,*xwpart,*scores,*w,*pooled,*route;
    cudaGetSymbolAddress((void**)&qkv, g_qkv);
    cudaGetSymbolAddress((void**)&wv, g_wv);
    cudaGetSymbolAddress((void**)&h,  g_h);
    cudaGetSymbolAddress((void**)&Bt3f, g_Bt3f);
    cudaGetSymbolAddress((void**)&Bt,  g_Bt);
    cudaGetSymbolAddress((void**)&gv,  g_g);
    cudaGetSymbolAddress((void**)&gpart, g_gpart);
    cudaGetSymbolAddress((void**)&xw,  g_xw);
    cudaGetSymbolAddress((void**)&xwpart, g_xwpart);
    cudaGetSymbolAddress((void**)&scores, g_scores);
    cudaGetSymbolAddress((void**)&w,  g_wsm);
    cudaGetSymbolAddress((void**)&pooled, g_pooled);
    cudaGetSymbolAddress((void**)&route,  g_route);

    cudaFuncSetAttribute(mma_gemm, cudaFuncAttributeMaxDynamicSharedMemorySize, GEMM_SMEM);
    cudaFuncSetAttribute(attn_fused, cudaFuncAttributeMaxDynamicSharedMemorySize, ATTN_SMEM);

    build_Bt3f<<<(3072*192 + 255)/256, 256>>>(qB, kB, vB, Bt3f);
    tr_loraB2x<<<(Dd*64 + 255)/256, 256>>>(oB, Bt);

    // router (conv algebraically folded; coalesced/parallel)
    r_g<<<dim3(12,8), 256>>>(conv_w, pool_w, gpart);
    r_gred<<<12, 256>>>(gpart, gv);
    r_scores<<<Md, 128>>>(x, gv, scores);
    softmax_w<<<Bd, 256>>>(scores, w);
    r_xw<<<dim3(8,Bd,8), 128>>>(x, w, xwpart);
    r_xwred<<<(Bd*3072 + 255)/256, 256>>>(xwpart, xw);
    r_pooled<<<dim3(128,Bd), 256>>>(conv_w, conv_b, xw, pooled);
    route_k<<<1, 256>>>(pooled, rlin_w, rlin_b, route);

    // batched LoRA-A (route-scaled), segmented B over qA/kA/vA: h[4096,192]
    mma_gemm<<<dim3(2,32), 256, GEMM_SMEM>>>(x, qA, kA, vA, 6, h,
        Md, 192, 1024, 1024, 1024, 192,
        x, 1024, x, 1024, 1024,
        1.f, nullptr, nullptr, nullptr, route, 0);

    // merged qkv = [x|h]·[seg(qW,kW,vW)|Bt3f]^T + seg-bias  (K=1216)
    mma_gemm<<<dim3(24,32), 256, GEMM_SMEM>>>(x, qW, kW, vW, 10, qkv,
        Md, 3072, 1216, 1024, 1024, 3072,
        h, 192, Bt3f, 192, 1024,
        1.f, qb, nullptr, vb, nullptr, 0);

    // fused qk + softmax + PV
    attn_fused<<<dim3(8,64), 256, ATTN_SMEM>>>(qkv, qk, wv);

    // o LoRA-A (route-scaled) into h[:,0:64]
    mma_gemm<<<dim3(1,32), 256, GEMM_SMEM>>>(wv, oA, oA, oA, -1, h,
        Md, 64, 1024, 1024, 1024, 192,
        wv, 1024, wv, 1024, 1024,
        1.f, nullptr, nullptr, nullptr, route, 0);

    // merged o = [wv|h]·[oW|BtO]^T + ob  (K=1088)
    mma_gemm<<<dim3(8,32), 256, GEMM_SMEM>>>(wv, oW, oW, oW, -1, out,
        Md, 1024, 1088, 1024, 1024, 1024,
        h, 192, Bt, 64, 1024,
        1.f, ob, nullptr, nullptr, nullptr, 0);
}

// round 12
// speedup vs baseline: 4.7813x; 1.0147x over previous
#include <cuda_runtime.h>
#include <cstdint>
#include <cstddef>

#define Bd 4
#define Sd 1024
#define Dd 1024
#define Hd 16
#define DHd 64
#define Md (Bd*Sd)
#define OUT_OFF ((size_t)Bd*Sd*Dd)

__device__ float g_qkv[(size_t)Md*3072];
__device__ float g_wv[Md*Dd];
__device__ float g_h[Md*192];
__device__ float g_Bt3f[3072*192];
__device__ float g_Bt[Dd*64];
__device__ float g_g[3072];
__device__ float g_gpart[8*3072];
__device__ float g_xw[Bd*3072];
__device__ float g_xwpart[8*Bd*3072];
__device__ float g_scores[Md];
__device__ float g_wsm[Md];
__device__ float g_pooled[Bd*Dd];
__device__ float g_route[Bd*8];

__device__ __forceinline__ float warpRedSum(float v){
    #pragma unroll
    for (int o=16;o;o>>=1) v += __shfl_xor_sync(0xffffffffu, v, o);
    return v;
}
__device__ __forceinline__ float warpRedMax(float v){
    #pragma unroll
    for (int o=16;o;o>>=1) v = fmaxf(v, __shfl_xor_sync(0xffffffffu, v, o));
    return v;
}
__device__ __forceinline__ float fexp(float x){
    float t = x * 1.4426950408889634f;
    t = fmaxf(t, -126.0f);
    float ti = floorf(t);
    float f = t - ti;
    float p = 1.5403530393381608e-4f;
    p = fmaf(p, f, 1.3333558146428443e-3f);
    p = fmaf(p, f, 9.6181291076284770e-3f);
    p = fmaf(p, f, 5.5504108664821580e-2f);
    p = fmaf(p, f, 2.4022650695910070e-1f);
    p = fmaf(p, f, 6.9314718055994530e-1f);
    p = fmaf(p, f, 1.0f);
    return __int_as_float(((int)ti + 127) << 23) * p;
}
__device__ __forceinline__ uint32_t f2tf(float f){
    uint32_t r; asm("cvt.rna.tf32.f32 %0, %1;" : "=r"(r) : "f"(f)); return r;
}
__device__ __forceinline__ void mma8(float* d, const uint32_t* a, const uint32_t* b){
    asm volatile("mma.sync.aligned.m16n8k8.row.col.f32.tf32.tf32.f32 "
        "{%0,%1,%2,%3}, {%4,%5,%6,%7}, {%8,%9}, {%0,%1,%2,%3};"
        : "+f"(d[0]),"+f"(d[1]),"+f"(d[2]),"+f"(d[3])
        : "r"(a[0]),"r"(a[1]),"r"(a[2]),"r"(a[3]), "r"(b[0]),"r"(b[1]));
}
__device__ __forceinline__ uint32_t smem_u32(const void* p){
    uint32_t a; asm("{ .reg .u64 t; cvta.to.shared.u64 t, %1; cvt.u32.u64 %0, t; }" : "=r"(a) : "l"(p));
    return a;
}
__device__ __forceinline__ void cpa16(uint32_t dst, const void* src, int ok){
    asm volatile("cp.async.cg.shared.global [%0], [%1], 16, %2;"
        :: "r"(dst), "l"(src), "r"(ok ? 16 : 0));
}
#define CPA_COMMIT asm volatile("cp.async.commit_group;" ::: "memory")
#define CPA_WAIT(n) asm volatile("cp.async.wait_group %0;" :: "n"(n) : "memory")

// ---- tf32 mma.sync GEMM, segmented-B + split-K (unchanged from R10) ----
#define GSTRIDE 36
#define GEMM_SMEM (4*128*GSTRIDE*4)
__global__ __launch_bounds__(256,2)
void mma_gemm(const float* __restrict__ A,
              const float* __restrict__ B0, const float* __restrict__ B1,
              const float* __restrict__ B2s, int segShift,
              float* __restrict__ C,
              int M, int N, int K, int lda, int ldb, int ldc,
              const float* __restrict__ A2, int lda2,
              const float* __restrict__ BK2, int ldbk2, int K1,
              float alpha,
              const float* __restrict__ bias0, const float* __restrict__ bias1,
              const float* __restrict__ bias2,
              const float* __restrict__ route, int addC)
{
    extern __shared__ __align__(16) float sm[];
    float* As = sm;
    float* Bs = sm + 2*128*GSTRIDE;

    const int tid = threadIdx.x, wid = tid >> 5, lane = tid & 31;
    const int wm = wid >> 2, wn = wid & 3;
    const int lr = lane >> 2, lc = lane & 3;
    const int bm = blockIdx.y*128, bn = blockIdx.x*128;

    const int row = tid >> 3, c4 = (tid & 7) << 2;
    const float* Ab  = A  + (size_t)bm*lda;
    const float* A2b = A2 + (size_t)bm*lda2;
    const int nch = K >> 5;
    const int segMask = (segShift >= 0) ? ((1 << segShift) - 1) : -1;
    const uint32_t sA = smem_u32(As), sB = smem_u32(Bs);

    auto issue = [&](int c){
        int buf = c & 1;
        int k0 = c << 5;
        bool sec = (k0 >= K1);
        const float* Asrc = sec ? A2b : Ab;
        int la = sec ? lda2 : lda;
        int kk = (sec ? (k0 - K1) : k0) + c4;
        #pragma unroll
        for (int j=0;j<4;j++){
            int rr = row + j*32;
            int n = bn + rr;
            int bok = n < N;
            cpa16(sA + (uint32_t)((buf*128 + rr)*GSTRIDE + c4)*4,
                  Asrc + (size_t)rr*la + kk, 1);
            const float* Bsrc;
            if (sec){
                Bsrc = BK2 + (size_t)(bok ? n : 0)*ldbk2;
            } else if (segShift >= 0){
                int sel = bok ? (n >> segShift) : 0;
                int rowb = bok ? (n & segMask) : 0;
                const float* Bp = (sel==0) ? B0 : (sel==1 ? B1 : B2s);
                Bsrc = Bp + (size_t)rowb*ldb;
            } else {
                Bsrc = B0 + (size_t)(bok ? n : 0)*ldb;
            }
            cpa16(sB + (uint32_t)((buf*128 + rr)*GSTRIDE + c4)*4, Bsrc + kk, bok);
        }
        CPA_COMMIT;
    };

    float acc[4][4][4];
    #pragma unroll
    for (int i=0;i<4;i++)
        #pragma unroll
        for (int j=0;j<4;j++)
            #pragma unroll
            for (int r=0;r<4;r++) acc[i][j][r]=0.f;

    issue(0);
    if (nch > 1){ issue(1); CPA_WAIT(1); } else CPA_WAIT(0);
    __syncthreads();

    for (int c = 0; c < nch; c++){
        const float* Ac = As + (c&1)*128*GSTRIDE;
        const float* Bc = Bs + (c&1)*128*GSTRIDE;
        #pragma unroll
        for (int ks=0; ks<4; ks++){
            uint32_t af[4][4], bf[4][2];
            #pragma unroll
            for (int mt=0; mt<4; mt++){
                const float* p = Ac + (wm*64 + mt*16)*GSTRIDE + ks*8;
                af[mt][0] = f2tf(p[lr*GSTRIDE + lc]);
                af[mt][1] = f2tf(p[(lr+8)*GSTRIDE + lc]);
                af[mt][2] = f2tf(p[lr*GSTRIDE + lc + 4]);
                af[mt][3] = f2tf(p[(lr+8)*GSTRIDE + lc + 4]);
            }
            #pragma unroll
            for (int nt=0; nt<4; nt++){
                const float* p = Bc + (wn*32 + nt*8)*GSTRIDE + ks*8;
                bf[nt][0] = f2tf(p[lr*GSTRIDE + lc]);
                bf[nt][1] = f2tf(p[lr*GSTRIDE + lc + 4]);
            }
            #pragma unroll
            for (int mt=0; mt<4; mt++)
                #pragma unroll
                for (int nt=0; nt<4; nt++)
                    mma8(acc[mt][nt], af[mt], bf[nt]);
        }
        __syncthreads();
        if (c+2 < nch) issue(c+2);
        if (c+1 < nch){
            if (c+2 < nch) CPA_WAIT(1); else CPA_WAIT(0);
            __syncthreads();
        }
    }

    #pragma unroll
    for (int mt=0; mt<4; mt++){
        #pragma unroll
        for (int nt=0; nt<4; nt++){
            int n = bn + wn*32 + nt*8 + 2*lc;
            if (n >= N) continue;
            int m0 = bm + wm*64 + mt*16 + lr;
            float bv0 = 0.f, bv1 = 0.f;
            if (bias0){
                if (segShift >= 0){
                    int sel = n >> segShift;
                    const float* bp = (sel==0) ? bias0 : (sel==1 ? bias1 : bias2);
                    if (bp){ bv0 = bp[n & segMask]; bv1 = bp[(n+1) & segMask]; }
                } else { bv0 = bias0[n]; bv1 = bias0[n+1]; }
            }
            #pragma unroll
            for (int half=0; half<2; half++){
                int m = m0 + half*8;
                float v0 = alpha*acc[mt][nt][half*2+0];
                float v1 = alpha*acc[mt][nt][half*2+1];
                if (route){
                    float rs = route[((m >> 10) << 3) + ((n & 63) >> 3)];
                    v0 *= rs; v1 *= rs;
                }
                v0 += bv0; v1 += bv1;
                float2* cp = (float2*)(C + (size_t)m*ldc + n);
                if (addC){ float2 o = *cp; v0 += o.x; v1 += o.y; }
                *cp = make_float2(v0, v1);
            }
        }
    }
}

// ---- fused flash attention: in-place tf32 pre-conversion, scale folded into Q ----
#define AQS 36
#define AVS 72
#define ATTN_SMEM ((2*128*AQS + 2*128*AQS + 4*32*AVS)*4)
__global__ __launch_bounds__(256,2) void attn_fused(
    const float* __restrict__ qkv, float* __restrict__ qk, float* __restrict__ wv)
{
    extern __shared__ __align__(16) float dsm[];
    float* Qs = dsm;
    float* Ks = dsm + 2*128*AQS;
    float* Vs = Ks + 2*128*AQS;

    const int z = blockIdx.y;
    const int bq = z >> 4, h = z & 15;
    const int bm = blockIdx.x * 128;
    const float* Qg = qkv + (size_t)bq*Sd*3072 + h*64;
    const float* Kg = Qg + 1024;
    const float* Vg = Qg + 2048;
    float* qko = qk + (size_t)z*Sd*Sd;

    const int tid = threadIdx.x, wid = tid >> 5, lane = tid & 31;
    const int lr = lane >> 2, lc = lane & 3;
    const int wr = wid * 16;
    const int rr0 = tid >> 3, c4 = (tid & 7) << 2;
    const uint32_t sQ = smem_u32(Qs), sK = smem_u32(Ks), sV = smem_u32(Vs);

    auto issueK = [&](int ct){
        int kb = ct << 7;
        #pragma unroll
        for (int j=0;j<4;j++){
            int rr = rr0 + j*32;
            #pragma unroll
            for (int ch=0;ch<2;ch++)
                cpa16(sK + (uint32_t)(((ch*128 + rr)*AQS + c4)*4),
                      Kg + (size_t)(kb+rr)*3072 + ch*32 + c4, 1);
        }
        CPA_COMMIT;
    };
    auto issueV = [&](int ct){
        int kb = ct << 7;
        #pragma unroll
        for (int j=0;j<8;j++){
            int idx = tid + (j << 8);
            int vk = idx >> 4, vc4 = (idx & 15) << 2;
            int w8 = vk & 7;
            int slot = (vk & ~7) | (w8 >> 1) | ((w8 & 1) << 2);
            cpa16(sV + (uint32_t)((((slot>>5)*32 + (slot&31))*AVS + vc4)*4),
                  Vg + (size_t)(kb+vk)*3072 + vc4, 1);
        }
        CPA_COMMIT;
    };
    // in-place tf32 conversion of a Q/K-shaped tile [2ch x 128 x 32], optional scale
    auto convQK = [&](float* base, float scale){
        #pragma unroll
        for (int j=0;j<4;j++){
            int rr = rr0 + j*32;
            #pragma unroll
            for (int ch=0;ch<2;ch++){
                float4* p = (float4*)(base + (ch*128 + rr)*AQS + c4);
                float4 v = *p;
                uint4 u;
                u.x = f2tf(v.x*scale); u.y = f2tf(v.y*scale);
                u.z = f2tf(v.z*scale); u.w = f2tf(v.w*scale);
                *(uint4*)p = u;
            }
        }
    };
    auto convV = [&](){
        #pragma unroll
        for (int j=0;j<8;j++){
            int idx = tid + (j << 8);
            int vk = idx >> 4, vc4 = (idx & 15) << 2;
            float4* p = (float4*)(Vs + (vk>>5)*32*AVS + (vk&31)*AVS + vc4);
            float4 v = *p;
            uint4 u;
            u.x = f2tf(v.x); u.y = f2tf(v.y); u.z = f2tf(v.z); u.w = f2tf(v.w);
            *(uint4*)p = u;
        }
    };

    #pragma unroll
    for (int j=0;j<4;j++){
        int rr = rr0 + j*32;
        #pragma unroll
        for (int ch=0;ch<2;ch++)
            cpa16(sQ + (uint32_t)(((ch*128 + rr)*AQS + c4)*4),
                  Qg + (size_t)(bm+rr)*3072 + ch*32 + c4, 1);
    }
    CPA_COMMIT;
    issueK(0); issueV(0);
    CPA_WAIT(1);              // Q + K0 done
    __syncthreads();
    convQK(Qs, 0.125f);       // fold softmax scale into Q
    convQK(Ks, 1.f);
    __syncthreads();

    float runmax[2] = {-1e30f,-1e30f}, runsum[2] = {0.f,0.f};
    float pvacc[8][4];
    #pragma unroll
    for (int i=0;i<8;i++)
        #pragma unroll
        for (int r=0;r<4;r++) pvacc[i][r]=0.f;

    const int m0 = bm + wr + lr;

    for (int ct=0; ct<8; ct++){
        const int kb = ct*128;

        float sacc[16][4];
        #pragma unroll
        for (int i=0;i<16;i++)
            #pragma unroll
            for (int r=0;r<4;r++) sacc[i][r]=0.f;
        #pragma unroll
        for (int ch=0;ch<2;ch++){
            const uint32_t* Qc = (const uint32_t*)Qs + ch*128*AQS;
            const uint32_t* Kc = (const uint32_t*)Ks + ch*128*AQS;
            #pragma unroll
            for (int ks=0;ks<4;ks++){
                uint32_t af[4];
                const uint32_t* p = Qc + (wr+lr)*AQS + ks*8;
                af[0] = p[lc];
                af[1] = p[8*AQS + lc];
                af[2] = p[lc + 4];
                af[3] = p[8*AQS + lc + 4];
                #pragma unroll
                for (int nt=0;nt<16;nt++){
                    const uint32_t* q = Kc + (nt*8+lr)*AQS + ks*8;
                    uint32_t bf[2];
                    bf[0] = q[lc];
                    bf[1] = q[lc + 4];
                    mma8(sacc[nt], af, bf);
                }
            }
        }
        __syncthreads();                 // Ks consumed
        if (ct < 7) issueK(ct+1);

        // write qk logits (already scaled via Q); streaming stores
        #pragma unroll
        for (int nt=0;nt<16;nt++){
            int n = kb + nt*8 + 2*lc;
            __stcs((float2*)(qko + (size_t)m0*Sd + n),     make_float2(sacc[nt][0], sacc[nt][1]));
            __stcs((float2*)(qko + (size_t)(m0+8)*Sd + n), make_float2(sacc[nt][2], sacc[nt][3]));
        }
        #pragma unroll
        for (int half=0;half<2;half++){
            float tm = -1e30f;
            #pragma unroll
            for (int nt=0;nt<16;nt++)
                tm = fmaxf(tm, fmaxf(sacc[nt][half*2], sacc[nt][half*2+1]));
            tm = fmaxf(tm, __shfl_xor_sync(0xffffffffu, tm, 1));
            tm = fmaxf(tm, __shfl_xor_sync(0xffffffffu, tm, 2));
            float mn = fmaxf(runmax[half], tm);
            float f = fexp(runmax[half] - mn);
            runmax[half] = mn;
            runsum[half] *= f;
            #pragma unroll
            for (int nt=0;nt<8;nt++){
                pvacc[nt][half*2+0] *= f;
                pvacc[nt][half*2+1] *= f;
            }
            float s = 0.f;
            #pragma unroll
            for (int nt=0;nt<16;nt++){
                float p0 = fexp(sacc[nt][half*2+0] - mn);
                float p1 = fexp(sacc[nt][half*2+1] - mn);
                s += p0 + p1;
                sacc[nt][half*2+0] = p0;
                sacc[nt][half*2+1] = p1;
            }
            s += __shfl_xor_sync(0xffffffffu, s, 1);
            s += __shfl_xor_sync(0xffffffffu, s, 2);
            runsum[half] += s;
        }
        if (ct < 7) CPA_WAIT(1); else CPA_WAIT(0);   // V(ct) arrived
        __syncthreads();
        convV();
        __syncthreads();

        #pragma unroll
        for (int ks=0;ks<16;ks++){
            uint32_t af[4];
            af[0] = f2tf(sacc[ks][0]);
            af[1] = f2tf(sacc[ks][2]);
            af[2] = f2tf(sacc[ks][1]);
            af[3] = f2tf(sacc[ks][3]);
            const uint32_t* pbase = (const uint32_t*)Vs + (ks>>2)*32*AVS + ((ks&3)*8)*AVS;
            #pragma unroll
            for (int nt=0;nt<8;nt++){
                const uint32_t* p = pbase + nt*8;
                uint32_t bf[2];
                bf[0] = p[lc*AVS + lr];
                bf[1] = p[(lc+4)*AVS + lr];
                mma8(pvacc[nt], af, bf);
            }
        }
        __syncthreads();                 // Vs consumed
        if (ct < 7){
            issueV(ct+1);
            CPA_WAIT(1);                 // K(ct+1) arrived
            __syncthreads();
            convQK(Ks, 1.f);
            __syncthreads();
        }
    }

    float* Cw = wv + (size_t)bq*Sd*Dd + h*DHd;
    float inv0 = 1.f / runsum[0], inv1 = 1.f / runsum[1];
    #pragma unroll
    for (int nt=0;nt<8;nt++){
        int n = nt*8 + 2*lc;
        *(float2*)(Cw + (size_t)m0*Dd + n)     = make_float2(pvacc[nt][0]*inv0, pvacc[nt][1]*inv0);
        *(float2*)(Cw + (size_t)(m0+8)*Dd + n) = make_float2(pvacc[nt][2]*inv1, pvacc[nt][3]*inv1);
    }
}

// ---- router ----
__global__ __launch_bounds__(256) void r_g(const float* __restrict__ cw,
                                           const float* __restrict__ pw, float* __restrict__ gpart){
    int idx = blockIdx.x*256 + threadIdx.x;
    int oz = blockIdx.y;
    const float* base = cw + (size_t)(oz*128)*3072 + idx;
    const float* pwb = pw + oz*128;
    float a0=0.f, a1=0.f;
    #pragma unroll 8
    for (int o=0;o<128;o+=2){
        a0 = fmaf(pwb[o],   base[(size_t)o*3072], a0);
        a1 = fmaf(pwb[o+1], base[(size_t)(o+1)*3072], a1);
    }
    gpart[oz*3072 + idx] = a0 + a1;
}
__global__ void r_gred(const float* __restrict__ gpart, float* __restrict__ g){
    int idx = blockIdx.x*256 + threadIdx.x;
    float s = 0.f;
    #pragma unroll
    for (int oz=0;oz<8;oz++) s += gpart[oz*3072 + idx];
    g[idx] = s;
}
__global__ __launch_bounds__(128) void r_scores(const float* __restrict__ x,
                                                const float* __restrict__ g, float* __restrict__ scores){
    int m = blockIdx.x;
    int b = m >> 10, s = m & 1023;
    int tid = threadIdx.x;
    __shared__ float gs[3072];
    #pragma unroll
    for (int j=0;j<24;j++) gs[tid + j*128] = g[tid + j*128];
    __syncthreads();
    const float* x0 = x + (size_t)m*Dd;
    const float* xm = x0 - Dd;
    const float* xp1 = x0 + Dd;
    bool okm = (s > 0), okp = (s < 1023);
    float acc = 0.f;
    #pragma unroll
    for (int j=0;j<8;j++){
        int i = tid + j*128;
        float vm = okm ? xm[i] : 0.f;
        float v0 = x0[i];
        float vp = okp ? xp1[i] : 0.f;
        const float* gg = gs + i*3;
        acc = fmaf(gg[0], vm, acc);
        acc = fmaf(gg[1], v0, acc);
        acc = fmaf(gg[2], vp, acc);
    }
    acc = warpRedSum(acc);
    __shared__ float sm[4];
    if ((tid&31)==0) sm[tid>>5]=acc;
    __syncthreads();
    if (tid==0) scores[m] = sm[0]+sm[1]+sm[2]+sm[3];
}
__global__ void softmax_w(const float* __restrict__ scores, float* __restrict__ w){
    int b = blockIdx.x, tid = threadIdx.x;
    float4 v = *(const float4*)(scores + (size_t)b*Sd + tid*4);
    float m = fmaxf(fmaxf(v.x,v.y), fmaxf(v.z,v.w));
    m = warpRedMax(m);
    __shared__ float sm[8];
    __shared__ float gmax, gisum;
    if ((tid&31)==0) sm[tid>>5]=m;
    __syncthreads();
    if (tid==0){ float mm=sm[0]; for(int i=1;i<8;i++) mm=fmaxf(mm,sm[i]); gmax=mm; }
    __syncthreads();
    float e0=expf(v.x-gmax), e1=expf(v.y-gmax), e2=expf(v.z-gmax), e3=expf(v.w-gmax);
    float s = e0+e1+e2+e3;
    s = warpRedSum(s);
    if ((tid&31)==0) sm[tid>>5]=s;
    __syncthreads();
    if (tid==0){ float ss=0; for(int i=0;i<8;i++) ss+=sm[i]; gisum = 1.f/ss; }
    __syncthreads();
    *(float4*)(w + (size_t)b*Sd + tid*4) = make_float4(e0*gisum, e1*gisum, e2*gisum, e3*gisum);
}
__global__ __launch_bounds__(128) void r_xw(const float* __restrict__ x,
                                            const float* __restrict__ w, float* __restrict__ xwpart){
    int b = blockIdx.y;
    int sc = blockIdx.z;
    int i = blockIdx.x*128 + threadIdx.x;
    int s0 = sc*128;
    __shared__ float ws[130];
    for (int j = threadIdx.x; j < 130; j += 128){
        int s = s0 - 1 + j;
        ws[j] = ((unsigned)s < 1024u) ? w[(size_t)b*Sd + s] : 0.f;
    }
    __syncthreads();
    const float* xb = x + ((size_t)b*Sd + s0)*Dd + i;
    float a0=0.f, a1=0.f, a2=0.f;
    #pragma unroll 8
    for (int j=0;j<128;j++){
        float v = xb[(size_t)j*Dd];
        a0 = fmaf(ws[j+2], v, a0);
        a1 = fmaf(ws[j+1], v, a1);
        a2 = fmaf(ws[j],   v, a2);
    }
    float* o = xwpart + ((size_t)(sc*Bd + b))*3072 + i*3;
    o[0]=a0; o[1]=a1; o[2]=a2;
}
__global__ void r_xwred(const float* __restrict__ xwpart, float* __restrict__ xw){
    int idx = blockIdx.x*256 + threadIdx.x;
    if (idx >= Bd*3072) return;
    int b = idx / 3072, r = idx - b*3072;
    float s = 0.f;
    #pragma unroll
    for (int sc=0;sc<8;sc++) s += xwpart[((size_t)(sc*Bd + b))*3072 + r];
    xw[(size_t)b*3072 + r] = s;
}
__global__ __launch_bounds__(256) void r_pooled(const float* __restrict__ cw,
                                                const float* __restrict__ cb,
                                                const float* __restrict__ xw, float* __restrict__ pooled){
    int b = blockIdx.y;
    int d = blockIdx.x*8 + (threadIdx.x >> 5);
    int lane = threadIdx.x & 31;
    __shared__ float sx[3072];
    for (int j = threadIdx.x; j < 3072; j += 256) sx[j] = xw[(size_t)b*3072 + j];
    __syncthreads();
    const float4* cr = (const float4*)(cw + (size_t)d*3072);
    float acc = 0.f;
    #pragma unroll
    for (int j=0;j<24;j++){
        float4 c = cr[lane + j*32];
        const float* s = sx + (lane + j*32)*4;
        acc += c.x*s[0] + c.y*s[1] + c.z*s[2] + c.w*s[3];
    }
    acc = warpRedSum(acc);
    if (lane == 0) pooled[b*Dd + d] = acc + cb[d];
}
__global__ void route_k(const float* __restrict__ pooled, const float* __restrict__ rw,
                        const float* __restrict__ rb, float* __restrict__ route){
    int tid = threadIdx.x;
    int e = tid >> 5, lane = tid & 31;
    __shared__ float lg[8];
    for (int b=0;b<Bd;b++){
        float s=0.f;
        for (int d=lane; d<Dd; d+=32) s += pooled[b*Dd+d]*rw[e*Dd+d];
        s = warpRedSum(s);
        if (lane==0) lg[e] = s + rb[e];
        __syncthreads();
        if (tid==0){
            float mm=lg[0];
            for (int i=1;i<8;i++) mm=fmaxf(mm,lg[i]);
            float ex[8]; float ss=0.f;
            for (int i=0;i<8;i++){ ex[i]=expf(lg[i]-mm); ss+=ex[i]; }
            float inv = 1.f/ss;
            for (int i=0;i<8;i++) route[b*8+i]=ex[i]*inv;
        }
        __syncthreads();
    }
}

// ---- prep ----
__global__ void build_Bt3f(const float* __restrict__ B0, const float* __restrict__ B1,
                           const float* __restrict__ B2, float* __restrict__ Bt){
    int idx = blockIdx.x*blockDim.x + threadIdx.x;
    if (idx >= 3072*192) return;
    int n = idx / 192, c = idx - n*192;
    int p = n >> 10, pp = c >> 6;
    float val = 0.f;
    if (pp == p){
        int e = (c >> 3) & 7, r = c & 7;
        const float* Bp = (p==0) ? B0 : (p==1 ? B1 : B2);
        val = 2.f * Bp[(size_t)e*Dd*8 + (size_t)(n & 1023)*8 + r];
    }
    Bt[idx] = val;
}
__global__ void tr_loraB2x(const float* __restrict__ Bp, float* __restrict__ Bt){
    int idx = blockIdx.x*blockDim.x + threadIdx.x;
    if (idx >= Dd*64) return;
    int n = idx >> 6, e = (idx >> 3) & 7, r = idx & 7;
    Bt[idx] = 2.f * Bp[(size_t)e*Dd*8 + (size_t)n*8 + r];
}

// ---- host launcher ----
extern "C" void kernel_launch(void* const* d_in, const int* in_sizes, int n_in,
                              void* d_out, int out_size)
{
    (void)in_sizes; (void)n_in; (void)out_size;
    const float* x      = (const float*)d_in[0];
    const float* conv_w = (const float*)d_in[1];
    const float* conv_b = (const float*)d_in[2];
    const float* pool_w = (const float*)d_in[3];
    const float* pool_b = (const float*)d_in[4];
    const float* rlin_w = (const float*)d_in[5];
    const float* rlin_b = (const float*)d_in[6];
    const float* qW=(const float*)d_in[7],  *qb=(const float*)d_in[8];
    const float* qA=(const float*)d_in[9],  *qB=(const float*)d_in[10];
    const float* kW=(const float*)d_in[11], *kA=(const float*)d_in[12], *kB=(const float*)d_in[13];
    const float* vW=(const float*)d_in[14], *vb=(const float*)d_in[15];
    const float* vA=(const float*)d_in[16], *vB=(const float*)d_in[17];
    const float* oW=(const float*)d_in[18], *ob=(const float*)d_in[19];
    const float* oA=(const float*)d_in[20], *oB=(const float*)d_in[21];
    (void)pool_b;

    float* out = (float*)d_out;
    float* qk  = out + OUT_OFF;

    float *qkv,*wv,*h,*Bt3f,*Bt,*gv,*gpart,*xw,*xwpart,*scores,*w,*pooled,*route;
    cudaGetSymbolAddress((void**)&qkv, g_qkv);
    cudaGetSymbolAddress((void**)&wv, g_wv);
    cudaGetSymbolAddress((void**)&h,  g_h);
    cudaGetSymbolAddress((void**)&Bt3f, g_Bt3f);
    cudaGetSymbolAddress((void**)&Bt,  g_Bt);
    cudaGetSymbolAddress((void**)&gv,  g_g);
    cudaGetSymbolAddress((void**)&gpart, g_gpart);
    cudaGetSymbolAddress((void**)&xw,  g_xw);
    cudaGetSymbolAddress((void**)&xwpart, g_xwpart);
    cudaGetSymbolAddress((void**)&scores, g_scores);
    cudaGetSymbolAddress((void**)&w,  g_wsm);
    cudaGetSymbolAddress((void**)&pooled, g_pooled);
    cudaGetSymbolAddress((void**)&route,  g_route);

    cudaFuncSetAttribute(mma_gemm, cudaFuncAttributeMaxDynamicSharedMemorySize, GEMM_SMEM);
    cudaFuncSetAttribute(attn_fused, cudaFuncAttributeMaxDynamicSharedMemorySize, ATTN_SMEM);

    build_Bt3f<<<(3072*192 + 255)/256, 256>>>(qB, kB, vB, Bt3f);
    tr_loraB2x<<<(Dd*64 + 255)/256, 256>>>(oB, Bt);

    // router
    r_g<<<dim3(12,8), 256>>>(conv_w, pool_w, gpart);
    r_gred<<<12, 256>>>(gpart, gv);
    r_scores<<<Md, 128>>>(x, gv, scores);
    softmax_w<<<Bd, 256>>>(scores, w);
    r_xw<<<dim3(8,Bd,8), 128>>>(x, w, xwpart);
    r_xwred<<<(Bd*3072 + 255)/256, 256>>>(xwpart, xw);
    r_pooled<<<dim3(128,Bd), 256>>>(conv_w, conv_b, xw, pooled);
    route_k<<<1, 256>>>(pooled, rlin_w, rlin_b, route);

    // batched LoRA-A (route-scaled), segmented B over qA/kA/vA
    mma_gemm<<<dim3(2,32), 256, GEMM_SMEM>>>(x, qA, kA, vA, 6, h,
        Md, 192, 1024, 1024, 1024, 192,
        x, 1024, x, 1024, 1024,
        1.f, nullptr, nullptr, nullptr, route, 0);

    // merged qkv = [x|h]·[seg(qW,kW,vW)|Bt3f]^T + seg-bias  (K=1216)
    mma_gemm<<<dim3(24,32), 256, GEMM_SMEM>>>(x, qW, kW, vW, 10, qkv,
        Md, 3072, 1216, 1024, 1024, 3072,
        h, 192, Bt3f, 192, 1024,
        1.f, qb, nullptr, vb, nullptr, 0);

    // fused qk + softmax + PV
    attn_fused<<<dim3(8,64), 256, ATTN_SMEM>>>(qkv, qk, wv);

    // o LoRA-A (route-scaled)
    mma_gemm<<<dim3(1,32), 256, GEMM_SMEM>>>(wv, oA, oA, oA, -1, h,
        Md, 64, 1024, 1024, 1024, 192,
        wv, 1024, wv, 1024, 1024,
        1.f, nullptr, nullptr, nullptr, route, 0);

    // merged o = [wv|h]·[oW|BtO]^T + ob  (K=1088)
    mma_gemm<<<dim3(8,32), 256, GEMM_SMEM>>>(wv, oW, oW, oW, -1, out,
        Md, 1024, 1088, 1024, 1024, 1024,
        h, 192, Bt, 64, 1024,
        1.f, ob, nullptr, nullptr, nullptr, 0);
}

// round 13
// speedup vs baseline: 5.2380x; 1.0955x over previous
#include <cuda_runtime.h>
#include <cstdint>
#include <cstddef>

#define Bd 4
#define Sd 1024
#define Dd 1024
#define Hd 16
#define DHd 64
#define Md (Bd*Sd)
#define OUT_OFF ((size_t)Bd*Sd*Dd)

__device__ float g_qkv[(size_t)Md*3072];
__device__ float g_wv[Md*Dd];
__device__ float g_h[Md*192];
__device__ float g_hpart[4*(size_t)Md*192];
__device__ float g_Bt3f[3072*192];
__device__ float g_Bt[Dd*64];
__device__ float g_g[3072];
__device__ float g_gpart[8*3072];
__device__ float g_xw[Bd*3072];
__device__ float g_xwpart[8*Bd*3072];
__device__ float g_scores[Md];
__device__ float g_wsm[Md];
__device__ float g_pooled[Bd*Dd];
__device__ float g_route[Bd*8];

__device__ __forceinline__ float warpRedSum(float v){
    #pragma unroll
    for (int o=16;o;o>>=1) v += __shfl_xor_sync(0xffffffffu, v, o);
    return v;
}
__device__ __forceinline__ float warpRedMax(float v){
    #pragma unroll
    for (int o=16;o;o>>=1) v = fmaxf(v, __shfl_xor_sync(0xffffffffu, v, o));
    return v;
}
__device__ __forceinline__ float fexp(float x){
    float t = x * 1.4426950408889634f;
    t = fmaxf(t, -126.0f);
    float ti = floorf(t);
    float f = t - ti;
    float p = 1.5403530393381608e-4f;
    p = fmaf(p, f, 1.3333558146428443e-3f);
    p = fmaf(p, f, 9.6181291076284770e-3f);
    p = fmaf(p, f, 5.5504108664821580e-2f);
    p = fmaf(p, f, 2.4022650695910070e-1f);
    p = fmaf(p, f, 6.9314718055994530e-1f);
    p = fmaf(p, f, 1.0f);
    return __int_as_float(((int)ti + 127) << 23) * p;
}
__device__ __forceinline__ uint32_t f2tf(float f){
    uint32_t r; asm("cvt.rna.tf32.f32 %0, %1;" : "=r"(r) : "f"(f)); return r;
}
__device__ __forceinline__ void mma8(float* d, const uint32_t* a, const uint32_t* b){
    asm volatile("mma.sync.aligned.m16n8k8.row.col.f32.tf32.tf32.f32 "
        "{%0,%1,%2,%3}, {%4,%5,%6,%7}, {%8,%9}, {%0,%1,%2,%3};"
        : "+f"(d[0]),"+f"(d[1]),"+f"(d[2]),"+f"(d[3])
        : "r"(a[0]),"r"(a[1]),"r"(a[2]),"r"(a[3]), "r"(b[0]),"r"(b[1]));
}
__device__ __forceinline__ uint32_t smem_u32(const void* p){
    uint32_t a; asm("{ .reg .u64 t; cvta.to.shared.u64 t, %1; cvt.u32.u64 %0, t; }" : "=r"(a) : "l"(p));
    return a;
}
__device__ __forceinline__ void cpa16(uint32_t dst, const void* src, int ok){
    asm volatile("cp.async.cg.shared.global [%0], [%1], 16, %2;"
        :: "r"(dst), "l"(src), "r"(ok ? 16 : 0));
}
#define CPA_COMMIT asm volatile("cp.async.commit_group;" ::: "memory")
#define CPA_WAIT(n) asm volatile("cp.async.wait_group %0;" :: "n"(n) : "memory")

// ---- tf32 mma.sync GEMM, segmented-B + split-K sources + grid.z K-window ----
#define GSTRIDE 36
#define GEMM_SMEM (4*128*GSTRIDE*4)
__global__ __launch_bounds__(256,2)
void mma_gemm(const float* __restrict__ A,
              const float* __restrict__ B0, const float* __restrict__ B1,
              const float* __restrict__ B2s, int segShift,
              float* __restrict__ C,
              int M, int N, int K, int lda, int ldb, int ldc,
              const float* __restrict__ A2, int lda2,
              const float* __restrict__ BK2, int ldbk2, int K1,
              long long sCz,
              float alpha,
              const float* __restrict__ bias0, const float* __restrict__ bias1,
              const float* __restrict__ bias2,
              const float* __restrict__ route, int addC)
{
    extern __shared__ __align__(16) float sm[];
    float* As = sm;
    float* Bs = sm + 2*128*GSTRIDE;

    const int tid = threadIdx.x, wid = tid >> 5, lane = tid & 31;
    const int wm = wid >> 2, wn = wid & 3;
    const int lr = lane >> 2, lc = lane & 3;
    const int bm = blockIdx.y*128, bn = blockIdx.x*128;
    const int zc = blockIdx.z;
    const int kzbase = zc * K;
    C += (size_t)zc * sCz;

    const int row = tid >> 3, c4 = (tid & 7) << 2;
    const float* Ab  = A  + (size_t)bm*lda;
    const float* A2b = A2 + (size_t)bm*lda2;
    const int nch = K >> 5;
    const int segMask = (segShift >= 0) ? ((1 << segShift) - 1) : -1;
    const uint32_t sA = smem_u32(As), sB = smem_u32(Bs);

    auto issue = [&](int c){
        int buf = c & 1;
        int kglob = kzbase + (c << 5);
        bool sec = (kglob >= K1);
        const float* Asrc = sec ? A2b : Ab;
        int la = sec ? lda2 : lda;
        int kk = (sec ? (kglob - K1) : kglob) + c4;
        #pragma unroll
        for (int j=0;j<4;j++){
            int rr = row + j*32;
            int n = bn + rr;
            int bok = n < N;
            cpa16(sA + (uint32_t)((buf*128 + rr)*GSTRIDE + c4)*4,
                  Asrc + (size_t)rr*la + kk, 1);
            const float* Bsrc;
            if (sec){
                Bsrc = BK2 + (size_t)(bok ? n : 0)*ldbk2;
            } else if (segShift >= 0){
                int sel = bok ? (n >> segShift) : 0;
                int rowb = bok ? (n & segMask) : 0;
                const float* Bp = (sel==0) ? B0 : (sel==1 ? B1 : B2s);
                Bsrc = Bp + (size_t)rowb*ldb;
            } else {
                Bsrc = B0 + (size_t)(bok ? n : 0)*ldb;
            }
            cpa16(sB + (uint32_t)((buf*128 + rr)*GSTRIDE + c4)*4, Bsrc + kk, bok);
        }
        CPA_COMMIT;
    };

    float acc[4][4][4];
    #pragma unroll
    for (int i=0;i<4;i++)
        #pragma unroll
        for (int j=0;j<4;j++)
            #pragma unroll
            for (int r=0;r<4;r++) acc[i][j][r]=0.f;

    issue(0);
    if (nch > 1){ issue(1); CPA_WAIT(1); } else CPA_WAIT(0);
    __syncthreads();

    for (int c = 0; c < nch; c++){
        const float* Ac = As + (c&1)*128*GSTRIDE;
        const float* Bc = Bs + (c&1)*128*GSTRIDE;
        #pragma unroll
        for (int ks=0; ks<4; ks++){
            uint32_t af[4][4], bf[4][2];
            #pragma unroll
            for (int mt=0; mt<4; mt++){
                const float* p = Ac + (wm*64 + mt*16)*GSTRIDE + ks*8;
                af[mt][0] = f2tf(p[lr*GSTRIDE + lc]);
                af[mt][1] = f2tf(p[(lr+8)*GSTRIDE + lc]);
                af[mt][2] = f2tf(p[lr*GSTRIDE + lc + 4]);
                af[mt][3] = f2tf(p[(lr+8)*GSTRIDE + lc + 4]);
            }
            #pragma unroll
            for (int nt=0; nt<4; nt++){
                const float* p = Bc + (wn*32 + nt*8)*GSTRIDE + ks*8;
                bf[nt][0] = f2tf(p[lr*GSTRIDE + lc]);
                bf[nt][1] = f2tf(p[lr*GSTRIDE + lc + 4]);
            }
            #pragma unroll
            for (int mt=0; mt<4; mt++)
                #pragma unroll
                for (int nt=0; nt<4; nt++)
                    mma8(acc[mt][nt], af[mt], bf[nt]);
        }
        __syncthreads();
        if (c+2 < nch) issue(c+2);
        if (c+1 < nch){
            if (c+2 < nch) CPA_WAIT(1); else CPA_WAIT(0);
            __syncthreads();
        }
    }

    #pragma unroll
    for (int mt=0; mt<4; mt++){
        #pragma unroll
        for (int nt=0; nt<4; nt++){
            int n = bn + wn*32 + nt*8 + 2*lc;
            if (n >= N) continue;
            int m0 = bm + wm*64 + mt*16 + lr;
            float bv0 = 0.f, bv1 = 0.f;
            if (bias0){
                if (segShift >= 0){
                    int sel = n >> segShift;
                    const float* bp = (sel==0) ? bias0 : (sel==1 ? bias1 : bias2);
                    if (bp){ bv0 = bp[n & segMask]; bv1 = bp[(n+1) & segMask]; }
                } else { bv0 = bias0[n]; bv1 = bias0[n+1]; }
            }
            #pragma unroll
            for (int half=0; half<2; half++){
                int m = m0 + half*8;
                float v0 = alpha*acc[mt][nt][half*2+0];
                float v1 = alpha*acc[mt][nt][half*2+1];
                if (route){
                    float rs = route[((m >> 10) << 3) + ((n & 63) >> 3)];
                    v0 *= rs; v1 *= rs;
                }
                v0 += bv0; v1 += bv1;
                float2* cp = (float2*)(C + (size_t)m*ldc + n);
                if (addC){ float2 o = *cp; v0 += o.x; v1 += o.y; }
                *cp = make_float2(v0, v1);
            }
        }
    }
}

// reduce split-K partials + apply route: h[m*192+c] = route * sum_z hp[z][m*C+c]
__global__ void red_h(const float* __restrict__ hp, const float* __restrict__ route,
                      float* __restrict__ h, int C){
    int idx = blockIdx.x*256 + threadIdx.x;
    if (idx >= Md*C) return;
    int m = idx / C, c = idx - m*C;
    size_t stride = (size_t)Md*C;
    float s = hp[idx] + hp[stride + idx] + hp[2*stride + idx] + hp[3*stride + idx];
    h[(size_t)m*192 + c] = s * route[((m >> 10) << 3) + ((c & 63) >> 3)];
}

// ---- fused flash attention (unchanged from R11) ----
#define AQS 36
#define AVS 72
#define ATTN_SMEM ((2*128*AQS + 2*128*AQS + 4*32*AVS)*4)
__global__ __launch_bounds__(256,2) void attn_fused(
    const float* __restrict__ qkv, float* __restrict__ qk, float* __restrict__ wv)
{
    extern __shared__ __align__(16) float dsm[];
    float* Qs = dsm;
    float* Ks = dsm + 2*128*AQS;
    float* Vs = Ks + 2*128*AQS;

    const int z = blockIdx.y;
    const int bq = z >> 4, h = z & 15;
    const int bm = blockIdx.x * 128;
    const float* Qg = qkv + (size_t)bq*Sd*3072 + h*64;
    const float* Kg = Qg + 1024;
    const float* Vg = Qg + 2048;
    float* qko = qk + (size_t)z*Sd*Sd;

    const int tid = threadIdx.x, wid = tid >> 5, lane = tid & 31;
    const int lr = lane >> 2, lc = lane & 3;
    const int wr = wid * 16;
    const int rr0 = tid >> 3, c4 = (tid & 7) << 2;
    const uint32_t sQ = smem_u32(Qs), sK = smem_u32(Ks), sV = smem_u32(Vs);

    auto issueK = [&](int ct){
        int kb = ct << 7;
        #pragma unroll
        for (int j=0;j<4;j++){
            int rr = rr0 + j*32;
            #pragma unroll
            for (int ch=0;ch<2;ch++)
                cpa16(sK + (uint32_t)(((ch*128 + rr)*AQS + c4)*4),
                      Kg + (size_t)(kb+rr)*3072 + ch*32 + c4, 1);
        }
        CPA_COMMIT;
    };
    auto issueV = [&](int ct){
        int kb = ct << 7;
        #pragma unroll
        for (int j=0;j<8;j++){
            int idx = tid + (j << 8);
            int vk = idx >> 4, vc4 = (idx & 15) << 2;
            int w8 = vk & 7;
            int slot = (vk & ~7) | (w8 >> 1) | ((w8 & 1) << 2);
            cpa16(sV + (uint32_t)((((slot>>5)*32 + (slot&31))*AVS + vc4)*4),
                  Vg + (size_t)(kb+vk)*3072 + vc4, 1);
        }
        CPA_COMMIT;
    };
    auto convQK = [&](float* base, float scale){
        #pragma unroll
        for (int j=0;j<4;j++){
            int rr = rr0 + j*32;
            #pragma unroll
            for (int ch=0;ch<2;ch++){
                float4* p = (float4*)(base + (ch*128 + rr)*AQS + c4);
                float4 v = *p;
                uint4 u;
                u.x = f2tf(v.x*scale); u.y = f2tf(v.y*scale);
                u.z = f2tf(v.z*scale); u.w = f2tf(v.w*scale);
                *(uint4*)p = u;
            }
        }
    };
    auto convV = [&](){
        #pragma unroll
        for (int j=0;j<8;j++){
            int idx = tid + (j << 8);
            int vk = idx >> 4, vc4 = (idx & 15) << 2;
            float4* p = (float4*)(Vs + (vk>>5)*32*AVS + (vk&31)*AVS + vc4);
            float4 v = *p;
            uint4 u;
            u.x = f2tf(v.x); u.y = f2tf(v.y); u.z = f2tf(v.z); u.w = f2tf(v.w);
            *(uint4*)p = u;
        }
    };

    #pragma unroll
    for (int j=0;j<4;j++){
        int rr = rr0 + j*32;
        #pragma unroll
        for (int ch=0;ch<2;ch++)
            cpa16(sQ + (uint32_t)(((ch*128 + rr)*AQS + c4)*4),
                  Qg + (size_t)(bm+rr)*3072 + ch*32 + c4, 1);
    }
    CPA_COMMIT;
    issueK(0); issueV(0);
    CPA_WAIT(1);
    __syncthreads();
    convQK(Qs, 0.125f);
    convQK(Ks, 1.f);
    __syncthreads();

    float runmax[2] = {-1e30f,-1e30f}, runsum[2] = {0.f,0.f};
    float pvacc[8][4];
    #pragma unroll
    for (int i=0;i<8;i++)
        #pragma unroll
        for (int r=0;r<4;r++) pvacc[i][r]=0.f;

    const int m0 = bm + wr + lr;

    for (int ct=0; ct<8; ct++){
        const int kb = ct*128;

        float sacc[16][4];
        #pragma unroll
        for (int i=0;i<16;i++)
            #pragma unroll
            for (int r=0;r<4;r++) sacc[i][r]=0.f;
        #pragma unroll
        for (int ch=0;ch<2;ch++){
            const uint32_t* Qc = (const uint32_t*)Qs + ch*128*AQS;
            const uint32_t* Kc = (const uint32_t*)Ks + ch*128*AQS;
            #pragma unroll
            for (int ks=0;ks<4;ks++){
                uint32_t af[4];
                const uint32_t* p = Qc + (wr+lr)*AQS + ks*8;
                af[0] = p[lc];
                af[1] = p[8*AQS + lc];
                af[2] = p[lc + 4];
                af[3] = p[8*AQS + lc + 4];
                #pragma unroll
                for (int nt=0;nt<16;nt++){
                    const uint32_t* q = Kc + (nt*8+lr)*AQS + ks*8;
                    uint32_t bf[2];
                    bf[0] = q[lc];
                    bf[1] = q[lc + 4];
                    mma8(sacc[nt], af, bf);
                }
            }
        }
        __syncthreads();
        if (ct < 7) issueK(ct+1);

        #pragma unroll
        for (int nt=0;nt<16;nt++){
            int n = kb + nt*8 + 2*lc;
            __stcs((float2*)(qko + (size_t)m0*Sd + n),     make_float2(sacc[nt][0], sacc[nt][1]));
            __stcs((float2*)(qko + (size_t)(m0+8)*Sd + n), make_float2(sacc[nt][2], sacc[nt][3]));
        }
        #pragma unroll
        for (int half=0;half<2;half++){
            float tm = -1e30f;
            #pragma unroll
            for (int nt=0;nt<16;nt++)
                tm = fmaxf(tm, fmaxf(sacc[nt][half*2], sacc[nt][half*2+1]));
            tm = fmaxf(tm, __shfl_xor_sync(0xffffffffu, tm, 1));
            tm = fmaxf(tm, __shfl_xor_sync(0xffffffffu, tm, 2));
            float mn = fmaxf(runmax[half], tm);
            float f = fexp(runmax[half] - mn);
            runmax[half] = mn;
            runsum[half] *= f;
            #pragma unroll
            for (int nt=0;nt<8;nt++){
                pvacc[nt][half*2+0] *= f;
                pvacc[nt][half*2+1] *= f;
            }
            float s = 0.f;
            #pragma unroll
            for (int nt=0;nt<16;nt++){
                float p0 = fexp(sacc[nt][half*2+0] - mn);
                float p1 = fexp(sacc[nt][half*2+1] - mn);
                s += p0 + p1;
                sacc[nt][half*2+0] = p0;
                sacc[nt][half*2+1] = p1;
            }
            s += __shfl_xor_sync(0xffffffffu, s, 1);
            s += __shfl_xor_sync(0xffffffffu, s, 2);
            runsum[half] += s;
        }
        if (ct < 7) CPA_WAIT(1); else CPA_WAIT(0);
        __syncthreads();
        convV();
        __syncthreads();

        #pragma unroll
        for (int ks=0;ks<16;ks++){
            uint32_t af[4];
            af[0] = f2tf(sacc[ks][0]);
            af[1] = f2tf(sacc[ks][2]);
            af[2] = f2tf(sacc[ks][1]);
            af[3] = f2tf(sacc[ks][3]);
            const uint32_t* pbase = (const uint32_t*)Vs + (ks>>2)*32*AVS + ((ks&3)*8)*AVS;
            #pragma unroll
            for (int nt=0;nt<8;nt++){
                const uint32_t* p = pbase + nt*8;
                uint32_t bf[2];
                bf[0] = p[lc*AVS + lr];
                bf[1] = p[(lc+4)*AVS + lr];
                mma8(pvacc[nt], af, bf);
            }
        }
        __syncthreads();
        if (ct < 7){
            issueV(ct+1);
            CPA_WAIT(1);
            __syncthreads();
            convQK(Ks, 1.f);
            __syncthreads();
        }
    }

    float* Cw = wv + (size_t)bq*Sd*Dd + h*DHd;
    float inv0 = 1.f / runsum[0], inv1 = 1.f / runsum[1];
    #pragma unroll
    for (int nt=0;nt<8;nt++){
        int n = nt*8 + 2*lc;
        *(float2*)(Cw + (size_t)m0*Dd + n)     = make_float2(pvacc[nt][0]*inv0, pvacc[nt][1]*inv0);
        *(float2*)(Cw + (size_t)(m0+8)*Dd + n) = make_float2(pvacc[nt][2]*inv1, pvacc[nt][3]*inv1);
    }
}

// ---- router ----
__global__ __launch_bounds__(256) void r_g(const float* __restrict__ cw,
                                           const float* __restrict__ pw, float* __restrict__ gpart){
    int idx = blockIdx.x*256 + threadIdx.x;
    int oz = blockIdx.y;
    const float* base = cw + (size_t)(oz*128)*3072 + idx;
    const float* pwb = pw + oz*128;
    float a0=0.f, a1=0.f;
    #pragma unroll 8
    for (int o=0;o<128;o+=2){
        a0 = fmaf(pwb[o],   base[(size_t)o*3072], a0);
        a1 = fmaf(pwb[o+1], base[(size_t)(o+1)*3072], a1);
    }
    gpart[oz*3072 + idx] = a0 + a1;
}
__global__ void r_gred(const float* __restrict__ gpart, float* __restrict__ g){
    int idx = blockIdx.x*256 + threadIdx.x;
    float s = 0.f;
    #pragma unroll
    for (int oz=0;oz<8;oz++) s += gpart[oz*3072 + idx];
    g[idx] = s;
}
// 8 rows per block: load g once, compute 8 scores
__global__ __launch_bounds__(256) void r_scores8(const float* __restrict__ x,
                                                 const float* __restrict__ g, float* __restrict__ scores){
    int m0 = blockIdx.x*8;
    int tid = threadIdx.x;
    __shared__ float gs[3072];
    __shared__ float sm[8];
    #pragma unroll
    for (int j=0;j<12;j++) gs[tid + j*256] = g[tid + j*256];
    __syncthreads();
    for (int r=0;r<8;r++){
        int m = m0 + r;
        int s = m & 1023;
        const float* x0 = x + (size_t)m*Dd;
        bool okm = (s > 0), okp = (s < 1023);
        float acc = 0.f;
        #pragma unroll
        for (int j=0;j<4;j++){
            int i = tid + j*256;
            float vm = okm ? x0[i - Dd] : 0.f;
            float v0 = x0[i];
            float vp = okp ? x0[i + Dd] : 0.f;
            const float* gg = gs + i*3;
            acc = fmaf(gg[0], vm, acc);
            acc = fmaf(gg[1], v0, acc);
            acc = fmaf(gg[2], vp, acc);
        }
        acc = warpRedSum(acc);
        if ((tid&31)==0) sm[tid>>5]=acc;
        __syncthreads();
        if (tid==0){
            float t = 0.f;
            #pragma unroll
            for (int i=0;i<8;i++) t += sm[i];
            scores[m] = t;
        }
        __syncthreads();
    }
}
__global__ void softmax_w(const float* __restrict__ scores, float* __restrict__ w){
    int b = blockIdx.x, tid = threadIdx.x;
    float4 v = *(const float4*)(scores + (size_t)b*Sd + tid*4);
    float m = fmaxf(fmaxf(v.x,v.y), fmaxf(v.z,v.w));
    m = warpRedMax(m);
    __shared__ float sm[8];
    __shared__ float gmax, gisum;
    if ((tid&31)==0) sm[tid>>5]=m;
    __syncthreads();
    if (tid==0){ float mm=sm[0]; for(int i=1;i<8;i++) mm=fmaxf(mm,sm[i]); gmax=mm; }
    __syncthreads();
    float e0=expf(v.x-gmax), e1=expf(v.y-gmax), e2=expf(v.z-gmax), e3=expf(v.w-gmax);
    float s = e0+e1+e2+e3;
    s = warpRedSum(s);
    if ((tid&31)==0) sm[tid>>5]=s;
    __syncthreads();
    if (tid==0){ float ss=0; for(int i=0;i<8;i++) ss+=sm[i]; gisum = 1.f/ss; }
    __syncthreads();
    *(float4*)(w + (size_t)b*Sd + tid*4) = make_float4(e0*gisum, e1*gisum, e2*gisum, e3*gisum);
}
__global__ __launch_bounds__(128) void r_xw(const float* __restrict__ x,
                                            const float* __restrict__ w, float* __restrict__ xwpart){
    int b = blockIdx.y;
    int sc = blockIdx.z;
    int i = blockIdx.x*128 + threadIdx.x;
    int s0 = sc*128;
    __shared__ float ws[130];
    for (int j = threadIdx.x; j < 130; j += 128){
        int s = s0 - 1 + j;
        ws[j] = ((unsigned)s < 1024u) ? w[(size_t)b*Sd + s] : 0.f;
    }
    __syncthreads();
    const float* xb = x + ((size_t)b*Sd + s0)*Dd + i;
    float a0=0.f, a1=0.f, a2=0.f;
    #pragma unroll 8
    for (int j=0;j<128;j++){
        float v = xb[(size_t)j*Dd];
        a0 = fmaf(ws[j+2], v, a0);
        a1 = fmaf(ws[j+1], v, a1);
        a2 = fmaf(ws[j],   v, a2);
    }
    float* o = xwpart + ((size_t)(sc*Bd + b))*3072 + i*3;
    o[0]=a0; o[1]=a1; o[2]=a2;
}
__global__ void r_xwred(const float* __restrict__ xwpart, float* __restrict__ xw){
    int idx = blockIdx.x*256 + threadIdx.x;
    if (idx >= Bd*3072) return;
    int b = idx / 3072, r = idx - b*3072;
    float s = 0.f;
    #pragma unroll
    for (int sc=0;sc<8;sc++) s += xwpart[((size_t)(sc*Bd + b))*3072 + r];
    xw[(size_t)b*3072 + r] = s;
}
__global__ __launch_bounds__(256) void r_pooled(const float* __restrict__ cw,
                                                const float* __restrict__ cb,
                                                const float* __restrict__ xw, float* __restrict__ pooled){
    int b = blockIdx.y;
    int d = blockIdx.x*8 + (threadIdx.x >> 5);
    int lane = threadIdx.x & 31;
    __shared__ float sx[3072];
    for (int j = threadIdx.x; j < 3072; j += 256) sx[j] = xw[(size_t)b*3072 + j];
    __syncthreads();
    const float4* cr = (const float4*)(cw + (size_t)d*3072);
    float acc = 0.f;
    #pragma unroll
    for (int j=0;j<24;j++){
        float4 c = cr[lane + j*32];
        const float* s = sx + (lane + j*32)*4;
        acc += c.x*s[0] + c.y*s[1] + c.z*s[2] + c.w*s[3];
    }
    acc = warpRedSum(acc);
    if (lane == 0) pooled[b*Dd + d] = acc + cb[d];
}
__global__ void route_k(const float* __restrict__ pooled, const float* __restrict__ rw,
                        const float* __restrict__ rb, float* __restrict__ route){
    int tid = threadIdx.x;
    int e = tid >> 5, lane = tid & 31;
    __shared__ float lg[8];
    for (int b=0;b<Bd;b++){
        float s=0.f;
        for (int d=lane; d<Dd; d+=32) s += pooled[b*Dd+d]*rw[e*Dd+d];
        s = warpRedSum(s);
        if (lane==0) lg[e] = s + rb[e];
        __syncthreads();
        if (tid==0){
            float mm=lg[0];
            for (int i=1;i<8;i++) mm=fmaxf(mm,lg[i]);
            float ex[8]; float ss=0.f;
            for (int i=0;i<8;i++){ ex[i]=expf(lg[i]-mm); ss+=ex[i]; }
            float inv = 1.f/ss;
            for (int i=0;i<8;i++) route[b*8+i]=ex[i]*inv;
        }
        __syncthreads();
    }
}

// ---- prep ----
__global__ void build_Bt3f(const float* __restrict__ B0, const float* __restrict__ B1,
                           const float* __restrict__ B2, float* __restrict__ Bt){
    int idx = blockIdx.x*blockDim.x + threadIdx.x;
    if (idx >= 3072*192) return;
    int n = idx / 192, c = idx - n*192;
    int p = n >> 10, pp = c >> 6;
    float val = 0.f;
    if (pp == p){
        int e = (c >> 3) & 7, r = c & 7;
        const float* Bp = (p==0) ? B0 : (p==1 ? B1 : B2);
        val = 2.f * Bp[(size_t)e*Dd*8 + (size_t)(n & 1023)*8 + r];
    }
    Bt[idx] = val;
}
__global__ void tr_loraB2x(const float* __restrict__ Bp, float* __restrict__ Bt){
    int idx = blockIdx.x*blockDim.x + threadIdx.x;
    if (idx >= Dd*64) return;
    int n = idx >> 6, e = (idx >> 3) & 7, r = idx & 7;
    Bt[idx] = 2.f * Bp[(size_t)e*Dd*8 + (size_t)n*8 + r];
}

// ---- host launcher ----
extern "C" void kernel_launch(void* const* d_in, const int* in_sizes, int n_in,
                              void* d_out, int out_size)
{
    (void)in_sizes; (void)n_in; (void)out_size;
    const float* x      = (const float*)d_in[0];
    const float* conv_w = (const float*)d_in[1];
    const float* conv_b = (const float*)d_in[2];
    const float* pool_w = (const float*)d_in[3];
    const float* pool_b = (const float*)d_in[4];
    const float* rlin_w = (const float*)d_in[5];
    const float* rlin_b = (const float*)d_in[6];
    const float* qW=(const float*)d_in[7],  *qb=(const float*)d_in[8];
    const float* qA=(const float*)d_in[9],  *qB=(const float*)d_in[10];
    const float* kW=(const float*)d_in[11], *kA=(const float*)d_in[12], *kB=(const float*)d_in[13];
    const float* vW=(const float*)d_in[14], *vb=(const float*)d_in[15];
    const float* vA=(const float*)d_in[16], *vB=(const float*)d_in[17];
    const float* oW=(const float*)d_in[18], *ob=(const float*)d_in[19];
    const float* oA=(const float*)d_in[20], *oB=(const float*)d_in[21];
    (void)pool_b;

    float* out = (float*)d_out;
    float* qk  = out + OUT_OFF;

    float *qkv,*wv,*h,*hpart,*Bt3f,*Bt,*gv,*gpart,*xw,*xwpart,*scores,*w,*pooled,*route;
    cudaGetSymbolAddress((void**)&qkv, g_qkv);
    cudaGetSymbolAddress((void**)&wv, g_wv);
    cudaGetSymbolAddress((void**)&h,  g_h);
    cudaGetSymbolAddress((void**)&hpart, g_hpart);
    cudaGetSymbolAddress((void**)&Bt3f, g_Bt3f);
    cudaGetSymbolAddress((void**)&Bt,  g_Bt);
    cudaGetSymbolAddress((void**)&gv,  g_g);
    cudaGetSymbolAddress((void**)&gpart, g_gpart);
    cudaGetSymbolAddress((void**)&xw,  g_xw);
    cudaGetSymbolAddress((void**)&xwpart, g_xwpart);
    cudaGetSymbolAddress((void**)&scores, g_scores);
    cudaGetSymbolAddress((void**)&w,  g_wsm);
    cudaGetSymbolAddress((void**)&pooled, g_pooled);
    cudaGetSymbolAddress((void**)&route,  g_route);

    cudaFuncSetAttribute(mma_gemm, cudaFuncAttributeMaxDynamicSharedMemorySize, GEMM_SMEM);
    cudaFuncSetAttribute(attn_fused, cudaFuncAttributeMaxDynamicSharedMemorySize, ATTN_SMEM);

    build_Bt3f<<<(3072*192 + 255)/256, 256>>>(qB, kB, vB, Bt3f);
    tr_loraB2x<<<(Dd*64 + 255)/256, 256>>>(oB, Bt);

    // router
    r_g<<<dim3(12,8), 256>>>(conv_w, pool_w, gpart);
    r_gred<<<12, 256>>>(gpart, gv);
    r_scores8<<<Md/8, 256>>>(x, gv, scores);
    softmax_w<<<Bd, 256>>>(scores, w);
    r_xw<<<dim3(8,Bd,8), 128>>>(x, w, xwpart);
    r_xwred<<<(Bd*3072 + 255)/256, 256>>>(xwpart, xw);
    r_pooled<<<dim3(128,Bd), 256>>>(conv_w, conv_b, xw, pooled);
    route_k<<<1, 256>>>(pooled, rlin_w, rlin_b, route);

    // LoRA-A (q/k/v), split-K into 4 partials, segmented B over qA/kA/vA
    mma_gemm<<<dim3(2,32,4), 256, GEMM_SMEM>>>(x, qA, kA, vA, 6, hpart,
        Md, 192, 256, 1024, 1024, 192,
        x, 1024, x, 1024, 1<<30,
        (long long)Md*192,
        1.f, nullptr, nullptr, nullptr, nullptr, 0);
    red_h<<<(Md*192 + 255)/256, 256>>>(hpart, route, h, 192);

    // merged qkv = [x|h]·[seg(qW,kW,vW)|Bt3f]^T + seg-bias  (K=1216)
    mma_gemm<<<dim3(24,32,1), 256, GEMM_SMEM>>>(x, qW, kW, vW, 10, qkv,
        Md, 3072, 1216, 1024, 1024, 3072,
        h, 192, Bt3f, 192, 1024,
        0,
        1.f, qb, nullptr, vb, nullptr, 0);

    // fused qk + softmax + PV
    attn_fused<<<dim3(8,64), 256, ATTN_SMEM>>>(qkv, qk, wv);

    // o LoRA-A, split-K into 4 partials (N=64)
    mma_gemm<<<dim3(1,32,4), 256, GEMM_SMEM>>>(wv, oA, oA, oA, -1, hpart,
        Md, 64, 256, 1024, 1024, 64,
        wv, 1024, wv, 1024, 1<<30,
        (long long)Md*64,
        1.f, nullptr, nullptr, nullptr, nullptr, 0);
    red_h<<<(Md*64 + 255)/256, 256>>>(hpart, route, h, 64);

    // merged o = [wv|h]·[oW|BtO]^T + ob  (K=1088)
    mma_gemm<<<dim3(8,32,1), 256, GEMM_SMEM>>>(wv, oW, oW, oW, -1, out,
        Md, 1024, 1088, 1024, 1024, 1024,
        h, 192, Bt, 64, 1024,
        0,
        1.f, ob, nullptr, nullptr, nullptr, 0);
}

// round 14
// speedup vs baseline: 5.3244x; 1.0165x over previous
#include <cuda_runtime.h>
#include <cstdint>
#include <cstddef>

#define Bd 4
#define Sd 1024
#define Dd 1024
#define Hd 16
#define DHd 64
#define Md (Bd*Sd)
#define OUT_OFF ((size_t)Bd*Sd*Dd)

__device__ float g_qkv[(size_t)Md*3072];
__device__ float g_wv[Md*Dd];
__device__ float g_h[Md*192];
__device__ float g_hpart[4*(size_t)Md*192];
__device__ float g_Bt3f[3072*192];
__device__ float g_Bt[Dd*64];
__device__ float g_gpart[8*3072];
__device__ float g_xwpart[8*Bd*3072];
__device__ float g_scores[Md];
__device__ float g_wsm[Md];
__device__ float g_pooled[Bd*Dd];
__device__ float g_route[Bd*8];

__device__ __forceinline__ float warpRedSum(float v){
    #pragma unroll
    for (int o=16;o;o>>=1) v += __shfl_xor_sync(0xffffffffu, v, o);
    return v;
}
__device__ __forceinline__ float warpRedMax(float v){
    #pragma unroll
    for (int o=16;o;o>>=1) v = fmaxf(v, __shfl_xor_sync(0xffffffffu, v, o));
    return v;
}
__device__ __forceinline__ float fexp(float x){
    float t = x * 1.4426950408889634f;
    t = fmaxf(t, -126.0f);
    float ti = floorf(t);
    float f = t - ti;
    float p = 1.5403530393381608e-4f;
    p = fmaf(p, f, 1.3333558146428443e-3f);
    p = fmaf(p, f, 9.6181291076284770e-3f);
    p = fmaf(p, f, 5.5504108664821580e-2f);
    p = fmaf(p, f, 2.4022650695910070e-1f);
    p = fmaf(p, f, 6.9314718055994530e-1f);
    p = fmaf(p, f, 1.0f);
    return __int_as_float(((int)ti + 127) << 23) * p;
}
__device__ __forceinline__ uint32_t f2tf(float f){
    uint32_t r; asm("cvt.rna.tf32.f32 %0, %1;" : "=r"(r) : "f"(f)); return r;
}
__device__ __forceinline__ void mma8(float* d, const uint32_t* a, const uint32_t* b){
    asm volatile("mma.sync.aligned.m16n8k8.row.col.f32.tf32.tf32.f32 "
        "{%0,%1,%2,%3}, {%4,%5,%6,%7}, {%8,%9}, {%0,%1,%2,%3};"
        : "+f"(d[0]),"+f"(d[1]),"+f"(d[2]),"+f"(d[3])
        : "r"(a[0]),"r"(a[1]),"r"(a[2]),"r"(a[3]), "r"(b[0]),"r"(b[1]));
}
__device__ __forceinline__ uint32_t smem_u32(const void* p){
    uint32_t a; asm("{ .reg .u64 t; cvta.to.shared.u64 t, %1; cvt.u32.u64 %0, t; }" : "=r"(a) : "l"(p));
    return a;
}
__device__ __forceinline__ void cpa16(uint32_t dst, const void* src, int ok){
    asm volatile("cp.async.cg.shared.global [%0], [%1], 16, %2;"
        :: "r"(dst), "l"(src), "r"(ok ? 16 : 0));
}
#define CPA_COMMIT asm volatile("cp.async.commit_group;" ::: "memory")
#define CPA_WAIT(n) asm volatile("cp.async.wait_group %0;" :: "n"(n) : "memory")

// ---- tf32 mma.sync GEMM, segmented-B + split-K sources + grid.z K-window ----
#define GSTRIDE 36
#define GEMM_SMEM (4*128*GSTRIDE*4)
__global__ __launch_bounds__(256,2)
void mma_gemm(const float* __restrict__ A,
              const float* __restrict__ B0, const float* __restrict__ B1,
              const float* __restrict__ B2s, int segShift,
              float* __restrict__ C,
              int M, int N, int K, int lda, int ldb, int ldc,
              const float* __restrict__ A2, int lda2,
              const float* __restrict__ BK2, int ldbk2, int K1,
              long long sCz,
              float alpha,
              const float* __restrict__ bias0, const float* __restrict__ bias1,
              const float* __restrict__ bias2,
              const float* __restrict__ route, int addC)
{
    extern __shared__ __align__(16) float sm[];
    float* As = sm;
    float* Bs = sm + 2*128*GSTRIDE;

    const int tid = threadIdx.x, wid = tid >> 5, lane = tid & 31;
    const int wm = wid >> 2, wn = wid & 3;
    const int lr = lane >> 2, lc = lane & 3;
    const int bm = blockIdx.y*128, bn = blockIdx.x*128;
    const int zc = blockIdx.z;
    const int kzbase = zc * K;
    C += (size_t)zc * sCz;

    const int row = tid >> 3, c4 = (tid & 7) << 2;
    const float* Ab  = A  + (size_t)bm*lda;
    const float* A2b = A2 + (size_t)bm*lda2;
    const int nch = K >> 5;
    const int segMask = (segShift >= 0) ? ((1 << segShift) - 1) : -1;
    const uint32_t sA = smem_u32(As), sB = smem_u32(Bs);

    auto issue = [&](int c){
        int buf = c & 1;
        int kglob = kzbase + (c << 5);
        bool sec = (kglob >= K1);
        const float* Asrc = sec ? A2b : Ab;
        int la = sec ? lda2 : lda;
        int kk = (sec ? (kglob - K1) : kglob) + c4;
        #pragma unroll
        for (int j=0;j<4;j++){
            int rr = row + j*32;
            int n = bn + rr;
            int bok = n < N;
            cpa16(sA + (uint32_t)((buf*128 + rr)*GSTRIDE + c4)*4,
                  Asrc + (size_t)rr*la + kk, 1);
            const float* Bsrc;
            if (sec){
                Bsrc = BK2 + (size_t)(bok ? n : 0)*ldbk2;
            } else if (segShift >= 0){
                int sel = bok ? (n >> segShift) : 0;
                int rowb = bok ? (n & segMask) : 0;
                const float* Bp = (sel==0) ? B0 : (sel==1 ? B1 : B2s);
                Bsrc = Bp + (size_t)rowb*ldb;
            } else {
                Bsrc = B0 + (size_t)(bok ? n : 0)*ldb;
            }
            cpa16(sB + (uint32_t)((buf*128 + rr)*GSTRIDE + c4)*4, Bsrc + kk, bok);
        }
        CPA_COMMIT;
    };

    float acc[4][4][4];
    #pragma unroll
    for (int i=0;i<4;i++)
        #pragma unroll
        for (int j=0;j<4;j++)
            #pragma unroll
            for (int r=0;r<4;r++) acc[i][j][r]=0.f;

    issue(0);
    if (nch > 1){ issue(1); CPA_WAIT(1); } else CPA_WAIT(0);
    __syncthreads();

    for (int c = 0; c < nch; c++){
        const float* Ac = As + (c&1)*128*GSTRIDE;
        const float* Bc = Bs + (c&1)*128*GSTRIDE;
        #pragma unroll
        for (int ks=0; ks<4; ks++){
            uint32_t af[4][4], bf[4][2];
            #pragma unroll
            for (int mt=0; mt<4; mt++){
                const float* p = Ac + (wm*64 + mt*16)*GSTRIDE + ks*8;
                af[mt][0] = f2tf(p[lr*GSTRIDE + lc]);
                af[mt][1] = f2tf(p[(lr+8)*GSTRIDE + lc]);
                af[mt][2] = f2tf(p[lr*GSTRIDE + lc + 4]);
                af[mt][3] = f2tf(p[(lr+8)*GSTRIDE + lc + 4]);
            }
            #pragma unroll
            for (int nt=0; nt<4; nt++){
                const float* p = Bc + (wn*32 + nt*8)*GSTRIDE + ks*8;
                bf[nt][0] = f2tf(p[lr*GSTRIDE + lc]);
                bf[nt][1] = f2tf(p[lr*GSTRIDE + lc + 4]);
            }
            #pragma unroll
            for (int mt=0; mt<4; mt++)
                #pragma unroll
                for (int nt=0; nt<4; nt++)
                    mma8(acc[mt][nt], af[mt], bf[nt]);
        }
        __syncthreads();
        if (c+2 < nch) issue(c+2);
        if (c+1 < nch){
            if (c+2 < nch) CPA_WAIT(1); else CPA_WAIT(0);
            __syncthreads();
        }
    }

    #pragma unroll
    for (int mt=0; mt<4; mt++){
        #pragma unroll
        for (int nt=0; nt<4; nt++){
            int n = bn + wn*32 + nt*8 + 2*lc;
            if (n >= N) continue;
            int m0 = bm + wm*64 + mt*16 + lr;
            float bv0 = 0.f, bv1 = 0.f;
            if (bias0){
                if (segShift >= 0){
                    int sel = n >> segShift;
                    const float* bp = (sel==0) ? bias0 : (sel==1 ? bias1 : bias2);
                    if (bp){ bv0 = bp[n & segMask]; bv1 = bp[(n+1) & segMask]; }
                } else { bv0 = bias0[n]; bv1 = bias0[n+1]; }
            }
            #pragma unroll
            for (int half=0; half<2; half++){
                int m = m0 + half*8;
                float v0 = alpha*acc[mt][nt][half*2+0];
                float v1 = alpha*acc[mt][nt][half*2+1];
                if (route){
                    float rs = route[((m >> 10) << 3) + ((n & 63) >> 3)];
                    v0 *= rs; v1 *= rs;
                }
                v0 += bv0; v1 += bv1;
                float2* cp = (float2*)(C + (size_t)m*ldc + n);
                if (addC){ float2 o = *cp; v0 += o.x; v1 += o.y; }
                *cp = make_float2(v0, v1);
            }
        }
    }
}

// reduce split-K partials + apply route
__global__ void red_h(const float* __restrict__ hp, const float* __restrict__ route,
                      float* __restrict__ h, int C){
    int idx = blockIdx.x*256 + threadIdx.x;
    if (idx >= Md*C) return;
    int m = idx / C, c = idx - m*C;
    size_t stride = (size_t)Md*C;
    float s = hp[idx] + hp[stride + idx] + hp[2*stride + idx] + hp[3*stride + idx];
    h[(size_t)m*192 + c] = s * route[((m >> 10) << 3) + ((c & 63) >> 3)];
}

// ---- fused flash attention (unchanged) ----
#define AQS 36
#define AVS 72
#define ATTN_SMEM ((2*128*AQS + 2*128*AQS + 4*32*AVS)*4)
__global__ __launch_bounds__(256,2) void attn_fused(
    const float* __restrict__ qkv, float* __restrict__ qk, float* __restrict__ wv)
{
    extern __shared__ __align__(16) float dsm[];
    float* Qs = dsm;
    float* Ks = dsm + 2*128*AQS;
    float* Vs = Ks + 2*128*AQS;

    const int z = blockIdx.y;
    const int bq = z >> 4, h = z & 15;
    const int bm = blockIdx.x * 128;
    const float* Qg = qkv + (size_t)bq*Sd*3072 + h*64;
    const float* Kg = Qg + 1024;
    const float* Vg = Qg + 2048;
    float* qko = qk + (size_t)z*Sd*Sd;

    const int tid = threadIdx.x, wid = tid >> 5, lane = tid & 31;
    const int lr = lane >> 2, lc = lane & 3;
    const int wr = wid * 16;
    const int rr0 = tid >> 3, c4 = (tid & 7) << 2;
    const uint32_t sQ = smem_u32(Qs), sK = smem_u32(Ks), sV = smem_u32(Vs);

    auto issueK = [&](int ct){
        int kb = ct << 7;
        #pragma unroll
        for (int j=0;j<4;j++){
            int rr = rr0 + j*32;
            #pragma unroll
            for (int ch=0;ch<2;ch++)
                cpa16(sK + (uint32_t)(((ch*128 + rr)*AQS + c4)*4),
                      Kg + (size_t)(kb+rr)*3072 + ch*32 + c4, 1);
        }
        CPA_COMMIT;
    };
    auto issueV = [&](int ct){
        int kb = ct << 7;
        #pragma unroll
        for (int j=0;j<8;j++){
            int idx = tid + (j << 8);
            int vk = idx >> 4, vc4 = (idx & 15) << 2;
            int w8 = vk & 7;
            int slot = (vk & ~7) | (w8 >> 1) | ((w8 & 1) << 2);
            cpa16(sV + (uint32_t)((((slot>>5)*32 + (slot&31))*AVS + vc4)*4),
                  Vg + (size_t)(kb+vk)*3072 + vc4, 1);
        }
        CPA_COMMIT;
    };
    auto convQK = [&](float* base, float scale){
        #pragma unroll
        for (int j=0;j<4;j++){
            int rr = rr0 + j*32;
            #pragma unroll
            for (int ch=0;ch<2;ch++){
                float4* p = (float4*)(base + (ch*128 + rr)*AQS + c4);
                float4 v = *p;
                uint4 u;
                u.x = f2tf(v.x*scale); u.y = f2tf(v.y*scale);
                u.z = f2tf(v.z*scale); u.w = f2tf(v.w*scale);
                *(uint4*)p = u;
            }
        }
    };
    auto convV = [&](){
        #pragma unroll
        for (int j=0;j<8;j++){
            int idx = tid + (j << 8);
            int vk = idx >> 4, vc4 = (idx & 15) << 2;
            float4* p = (float4*)(Vs + (vk>>5)*32*AVS + (vk&31)*AVS + vc4);
            float4 v = *p;
            uint4 u;
            u.x = f2tf(v.x); u.y = f2tf(v.y); u.z = f2tf(v.z); u.w = f2tf(v.w);
            *(uint4*)p = u;
        }
    };

    #pragma unroll
    for (int j=0;j<4;j++){
        int rr = rr0 + j*32;
        #pragma unroll
        for (int ch=0;ch<2;ch++)
            cpa16(sQ + (uint32_t)(((ch*128 + rr)*AQS + c4)*4),
                  Qg + (size_t)(bm+rr)*3072 + ch*32 + c4, 1);
    }
    CPA_COMMIT;
    issueK(0); issueV(0);
    CPA_WAIT(1);
    __syncthreads();
    convQK(Qs, 0.125f);
    convQK(Ks, 1.f);
    __syncthreads();

    float runmax[2] = {-1e30f,-1e30f}, runsum[2] = {0.f,0.f};
    float pvacc[8][4];
    #pragma unroll
    for (int i=0;i<8;i++)
        #pragma unroll
        for (int r=0;r<4;r++) pvacc[i][r]=0.f;

    const int m0 = bm + wr + lr;

    for (int ct=0; ct<8; ct++){
        const int kb = ct*128;

        float sacc[16][4];
        #pragma unroll
        for (int i=0;i<16;i++)
            #pragma unroll
            for (int r=0;r<4;r++) sacc[i][r]=0.f;
        #pragma unroll
        for (int ch=0;ch<2;ch++){
            const uint32_t* Qc = (const uint32_t*)Qs + ch*128*AQS;
            const uint32_t* Kc = (const uint32_t*)Ks + ch*128*AQS;
            #pragma unroll
            for (int ks=0;ks<4;ks++){
                uint32_t af[4];
                const uint32_t* p = Qc + (wr+lr)*AQS + ks*8;
                af[0] = p[lc];
                af[1] = p[8*AQS + lc];
                af[2] = p[lc + 4];
                af[3] = p[8*AQS + lc + 4];
                #pragma unroll
                for (int nt=0;nt<16;nt++){
                    const uint32_t* q = Kc + (nt*8+lr)*AQS + ks*8;
                    uint32_t bf[2];
                    bf[0] = q[lc];
                    bf[1] = q[lc + 4];
                    mma8(sacc[nt], af, bf);
                }
            }
        }
        __syncthreads();
        if (ct < 7) issueK(ct+1);

        #pragma unroll
        for (int nt=0;nt<16;nt++){
            int n = kb + nt*8 + 2*lc;
            __stcs((float2*)(qko + (size_t)m0*Sd + n),     make_float2(sacc[nt][0], sacc[nt][1]));
            __stcs((float2*)(qko + (size_t)(m0+8)*Sd + n), make_float2(sacc[nt][2], sacc[nt][3]));
        }
        #pragma unroll
        for (int half=0;half<2;half++){
            float tm = -1e30f;
            #pragma unroll
            for (int nt=0;nt<16;nt++)
                tm = fmaxf(tm, fmaxf(sacc[nt][half*2], sacc[nt][half*2+1]));
            tm = fmaxf(tm, __shfl_xor_sync(0xffffffffu, tm, 1));
            tm = fmaxf(tm, __shfl_xor_sync(0xffffffffu, tm, 2));
            float mn = fmaxf(runmax[half], tm);
            float f = fexp(runmax[half] - mn);
            runmax[half] = mn;
            runsum[half] *= f;
            #pragma unroll
            for (int nt=0;nt<8;nt++){
                pvacc[nt][half*2+0] *= f;
                pvacc[nt][half*2+1] *= f;
            }
            float s = 0.f;
            #pragma unroll
            for (int nt=0;nt<16;nt++){
                float p0 = fexp(sacc[nt][half*2+0] - mn);
                float p1 = fexp(sacc[nt][half*2+1] - mn);
                s += p0 + p1;
                sacc[nt][half*2+0] = p0;
                sacc[nt][half*2+1] = p1;
            }
            s += __shfl_xor_sync(0xffffffffu, s, 1);
            s += __shfl_xor_sync(0xffffffffu, s, 2);
            runsum[half] += s;
        }
        if (ct < 7) CPA_WAIT(1); else CPA_WAIT(0);
        __syncthreads();
        convV();
        __syncthreads();

        #pragma unroll
        for (int ks=0;ks<16;ks++){
            uint32_t af[4];
            af[0] = f2tf(sacc[ks][0]);
            af[1] = f2tf(sacc[ks][2]);
            af[2] = f2tf(sacc[ks][1]);
            af[3] = f2tf(sacc[ks][3]);
            const uint32_t* pbase = (const uint32_t*)Vs + (ks>>2)*32*AVS + ((ks&3)*8)*AVS;
            #pragma unroll
            for (int nt=0;nt<8;nt++){
                const uint32_t* p = pbase + nt*8;
                uint32_t bf[2];
                bf[0] = p[lc*AVS + lr];
                bf[1] = p[(lc+4)*AVS + lr];
                mma8(pvacc[nt], af, bf);
            }
        }
        __syncthreads();
        if (ct < 7){
            issueV(ct+1);
            CPA_WAIT(1);
            __syncthreads();
            convQK(Ks, 1.f);
            __syncthreads();
        }
    }

    float* Cw = wv + (size_t)bq*Sd*Dd + h*DHd;
    float inv0 = 1.f / runsum[0], inv1 = 1.f / runsum[1];
    #pragma unroll
    for (int nt=0;nt<8;nt++){
        int n = nt*8 + 2*lc;
        *(float2*)(Cw + (size_t)m0*Dd + n)     = make_float2(pvacc[nt][0]*inv0, pvacc[nt][1]*inv0);
        *(float2*)(Cw + (size_t)(m0+8)*Dd + n) = make_float2(pvacc[nt][2]*inv1, pvacc[nt][3]*inv1);
    }
}

// ---- router ----
__global__ __launch_bounds__(256) void r_g(const float* __restrict__ cw,
                                           const float* __restrict__ pw, float* __restrict__ gpart){
    int idx = blockIdx.x*256 + threadIdx.x;
    int oz = blockIdx.y;
    const float* base = cw + (size_t)(oz*128)*3072 + idx;
    const float* pwb = pw + oz*128;
    float a0=0.f, a1=0.f;
    #pragma unroll 8
    for (int o=0;o<128;o+=2){
        a0 = fmaf(pwb[o],   base[(size_t)o*3072], a0);
        a1 = fmaf(pwb[o+1], base[(size_t)(o+1)*3072], a1);
    }
    gpart[oz*3072 + idx] = a0 + a1;
}
// 8 rows per block; sums gpart inline (r_gred folded in)
__global__ __launch_bounds__(256) void r_scores8(const float* __restrict__ x,
                                                 const float* __restrict__ gpart, float* __restrict__ scores){
    int m0 = blockIdx.x*8;
    int tid = threadIdx.x;
    __shared__ float gs[3072];
    __shared__ float sm[8];
    #pragma unroll
    for (int j=0;j<12;j++){
        int i = tid + j*256;
        float t = 0.f;
        #pragma unroll
        for (int oz=0;oz<8;oz++) t += gpart[oz*3072 + i];
        gs[i] = t;
    }
    __syncthreads();
    for (int r=0;r<8;r++){
        int m = m0 + r;
        int s = m & 1023;
        const float* x0 = x + (size_t)m*Dd;
        bool okm = (s > 0), okp = (s < 1023);
        float acc = 0.f;
        #pragma unroll
        for (int j=0;j<4;j++){
            int i = tid + j*256;
            float vm = okm ? x0[i - Dd] : 0.f;
            float v0 = x0[i];
            float vp = okp ? x0[i + Dd] : 0.f;
            const float* gg = gs + i*3;
            acc = fmaf(gg[0], vm, acc);
            acc = fmaf(gg[1], v0, acc);
            acc = fmaf(gg[2], vp, acc);
        }
        acc = warpRedSum(acc);
        if ((tid&31)==0) sm[tid>>5]=acc;
        __syncthreads();
        if (tid==0){
            float t = 0.f;
            #pragma unroll
            for (int i=0;i<8;i++) t += sm[i];
            scores[m] = t;
        }
        __syncthreads();
    }
}
__global__ void softmax_w(const float* __restrict__ scores, float* __restrict__ w){
    int b = blockIdx.x, tid = threadIdx.x;
    float4 v = *(const float4*)(scores + (size_t)b*Sd + tid*4);
    float m = fmaxf(fmaxf(v.x,v.y), fmaxf(v.z,v.w));
    m = warpRedMax(m);
    __shared__ float sm[8];
    __shared__ float gmax, gisum;
    if ((tid&31)==0) sm[tid>>5]=m;
    __syncthreads();
    if (tid==0){ float mm=sm[0]; for(int i=1;i<8;i++) mm=fmaxf(mm,sm[i]); gmax=mm; }
    __syncthreads();
    float e0=expf(v.x-gmax), e1=expf(v.y-gmax), e2=expf(v.z-gmax), e3=expf(v.w-gmax);
    float s = e0+e1+e2+e3;
    s = warpRedSum(s);
    if ((tid&31)==0) sm[tid>>5]=s;
    __syncthreads();
    if (tid==0){ float ss=0; for(int i=0;i<8;i++) ss+=sm[i]; gisum = 1.f/ss; }
    __syncthreads();
    *(float4*)(w + (size_t)b*Sd + tid*4) = make_float4(e0*gisum, e1*gisum, e2*gisum, e3*gisum);
}
__global__ __launch_bounds__(128) void r_xw(const float* __restrict__ x,
                                            const float* __restrict__ w, float* __restrict__ xwpart){
    int b = blockIdx.y;
    int sc = blockIdx.z;
    int i = blockIdx.x*128 + threadIdx.x;
    int s0 = sc*128;
    __shared__ float ws[130];
    for (int j = threadIdx.x; j < 130; j += 128){
        int s = s0 - 1 + j;
        ws[j] = ((unsigned)s < 1024u) ? w[(size_t)b*Sd + s] : 0.f;
    }
    __syncthreads();
    const float* xb = x + ((size_t)b*Sd + s0)*Dd + i;
    float a0=0.f, a1=0.f, a2=0.f;
    #pragma unroll 8
    for (int j=0;j<128;j++){
        float v = xb[(size_t)j*Dd];
        a0 = fmaf(ws[j+2], v, a0);
        a1 = fmaf(ws[j+1], v, a1);
        a2 = fmaf(ws[j],   v, a2);
    }
    float* o = xwpart + ((size_t)(sc*Bd + b))*3072 + i*3;
    o[0]=a0; o[1]=a1; o[2]=a2;
}
// r_xwred folded in: sums xwpart at smem load
__global__ __launch_bounds__(256) void r_pooled(const float* __restrict__ cw,
                                                const float* __restrict__ cb,
                                                const float* __restrict__ xwpart, float* __restrict__ pooled){
    int b = blockIdx.y;
    int d = blockIdx.x*8 + (threadIdx.x >> 5);
    int lane = threadIdx.x & 31;
    __shared__ float sx[3072];
    for (int j = threadIdx.x; j < 3072; j += 256){
        float t = 0.f;
        #pragma unroll
        for (int sc=0;sc<8;sc++) t += xwpart[((size_t)(sc*Bd + b))*3072 + j];
        sx[j] = t;
    }
    __syncthreads();
    const float4* cr = (const float4*)(cw + (size_t)d*3072);
    float acc = 0.f;
    #pragma unroll
    for (int j=0;j<24;j++){
        float4 c = cr[lane + j*32];
        const float* s = sx + (lane + j*32)*4;
        acc += c.x*s[0] + c.y*s[1] + c.z*s[2] + c.w*s[3];
    }
    acc = warpRedSum(acc);
    if (lane == 0) pooled[b*Dd + d] = acc + cb[d];
}
__global__ void route_k(const float* __restrict__ pooled, const float* __restrict__ rw,
                        const float* __restrict__ rb, float* __restrict__ route){
    int b = blockIdx.x;
    int tid = threadIdx.x;
    int e = tid >> 5, lane = tid & 31;
    __shared__ float lg[8];
    float s=0.f;
    for (int d=lane; d<Dd; d+=32) s += pooled[b*Dd+d]*rw[e*Dd+d];
    s = warpRedSum(s);
    if (lane==0) lg[e] = s + rb[e];
    __syncthreads();
    if (tid==0){
        float mm=lg[0];
        for (int i=1;i<8;i++) mm=fmaxf(mm,lg[i]);
        float ex[8]; float ss=0.f;
        for (int i=0;i<8;i++){ ex[i]=expf(lg[i]-mm); ss+=ex[i]; }
        float inv = 1.f/ss;
        for (int i=0;i<8;i++) route[b*8+i]=ex[i]*inv;
    }
}

// ---- prep ----
__global__ void build_Bt3f(const float* __restrict__ B0, const float* __restrict__ B1,
                           const float* __restrict__ B2, float* __restrict__ Bt){
    int idx = blockIdx.x*blockDim.x + threadIdx.x;
    if (idx >= 3072*192) return;
    int n = idx / 192, c = idx - n*192;
    int p = n >> 10, pp = c >> 6;
    float val = 0.f;
    if (pp == p){
        int e = (c >> 3) & 7, r = c & 7;
        const float* Bp = (p==0) ? B0 : (p==1 ? B1 : B2);
        val = 2.f * Bp[(size_t)e*Dd*8 + (size_t)(n & 1023)*8 + r];
    }
    Bt[idx] = val;
}
__global__ void tr_loraB2x(const float* __restrict__ Bp, float* __restrict__ Bt){
    int idx = blockIdx.x*blockDim.x + threadIdx.x;
    if (idx >= Dd*64) return;
    int n = idx >> 6, e = (idx >> 3) & 7, r = idx & 7;
    Bt[idx] = 2.f * Bp[(size_t)e*Dd*8 + (size_t)n*8 + r];
}

// ---- host launcher (stream-forked for overlap) ----
extern "C" void kernel_launch(void* const* d_in, const int* in_sizes, int n_in,
                              void* d_out, int out_size)
{
    (void)in_sizes; (void)n_in; (void)out_size;
    const float* x      = (const float*)d_in[0];
    const float* conv_w = (const float*)d_in[1];
    const float* conv_b = (const float*)d_in[2];
    const float* pool_w = (const float*)d_in[3];
    const float* pool_b = (const float*)d_in[4];
    const float* rlin_w = (const float*)d_in[5];
    const float* rlin_b = (const float*)d_in[6];
    const float* qW=(const float*)d_in[7],  *qb=(const float*)d_in[8];
    const float* qA=(const float*)d_in[9],  *qB=(const float*)d_in[10];
    const float* kW=(const float*)d_in[11], *kA=(const float*)d_in[12], *kB=(const float*)d_in[13];
    const float* vW=(const float*)d_in[14], *vb=(const float*)d_in[15];
    const float* vA=(const float*)d_in[16], *vB=(const float*)d_in[17];
    const float* oW=(const float*)d_in[18], *ob=(const float*)d_in[19];
    const float* oA=(const float*)d_in[20], *oB=(const float*)d_in[21];
    (void)pool_b;

    float* out = (float*)d_out;
    float* qk  = out + OUT_OFF;

    float *qkv,*wv,*h,*hpart,*Bt3f,*Bt,*gpart,*xwpart,*scores,*w,*pooled,*route;
    cudaGetSymbolAddress((void**)&qkv, g_qkv);
    cudaGetSymbolAddress((void**)&wv, g_wv);
    cudaGetSymbolAddress((void**)&h,  g_h);
    cudaGetSymbolAddress((void**)&hpart, g_hpart);
    cudaGetSymbolAddress((void**)&Bt3f, g_Bt3f);
    cudaGetSymbolAddress((void**)&Bt,  g_Bt);
    cudaGetSymbolAddress((void**)&gpart, g_gpart);
    cudaGetSymbolAddress((void**)&xwpart, g_xwpart);
    cudaGetSymbolAddress((void**)&scores, g_scores);
    cudaGetSymbolAddress((void**)&w,  g_wsm);
    cudaGetSymbolAddress((void**)&pooled, g_pooled);
    cudaGetSymbolAddress((void**)&route,  g_route);

    cudaFuncSetAttribute(mma_gemm, cudaFuncAttributeMaxDynamicSharedMemorySize, GEMM_SMEM);
    cudaFuncSetAttribute(attn_fused, cudaFuncAttributeMaxDynamicSharedMemorySize, ATTN_SMEM);

    cudaStream_t s2;
    cudaEvent_t ev1, ev2, ev3, ev4;
    cudaStreamCreateWithFlags(&s2, cudaStreamNonBlocking);
    cudaEventCreateWithFlags(&ev1, cudaEventDisableTiming);
    cudaEventCreateWithFlags(&ev2, cudaEventDisableTiming);
    cudaEventCreateWithFlags(&ev3, cudaEventDisableTiming);
    cudaEventCreateWithFlags(&ev4, cudaEventDisableTiming);

    // fork: s2 = prep + LoRA-A partials + base qkv GEMM (only depend on inputs)
    cudaEventRecord(ev1, 0);
    cudaStreamWaitEvent(s2, ev1, 0);

    build_Bt3f<<<(3072*192 + 255)/256, 256, 0, s2>>>(qB, kB, vB, Bt3f);
    tr_loraB2x<<<(Dd*64 + 255)/256, 256, 0, s2>>>(oB, Bt);
    mma_gemm<<<dim3(2,32,4), 256, GEMM_SMEM, s2>>>(x, qA, kA, vA, 6, hpart,
        Md, 192, 256, 1024, 1024, 192,
        x, 1024, x, 1024, 1<<30,
        (long long)Md*192,
        1.f, nullptr, nullptr, nullptr, nullptr, 0);
    // base qkv = x·seg(qW,kW,vW)^T + seg-bias (K=1024)
    mma_gemm<<<dim3(24,32,1), 256, GEMM_SMEM, s2>>>(x, qW, kW, vW, 10, qkv,
        Md, 3072, 1024, 1024, 1024, 3072,
        x, 1024, x, 1024, 1<<30,
        0,
        1.f, qb, nullptr, vb, nullptr, 0);

    // stream 0 (capture stream): router chain
    r_g<<<dim3(12,8), 256>>>(conv_w, pool_w, gpart);
    r_scores8<<<Md/8, 256>>>(x, gpart, scores);
    softmax_w<<<Bd, 256>>>(scores, w);
    r_xw<<<dim3(8,Bd,8), 128>>>(x, w, xwpart);
    r_pooled<<<dim3(128,Bd), 256>>>(conv_w, conv_b, xwpart, pooled);
    route_k<<<Bd, 256>>>(pooled, rlin_w, rlin_b, route);

    // join
    cudaEventRecord(ev2, s2);
    cudaStreamWaitEvent(0, ev2, 0);

    red_h<<<(Md*192 + 255)/256, 256>>>(hpart, route, h, 192);
    // LoRA-B add: qkv += h·Bt3f^T (K=192)
    mma_gemm<<<dim3(24,32,1), 256, GEMM_SMEM>>>(h, Bt3f, Bt3f, Bt3f, -1, qkv,
        Md, 3072, 192, 192, 192, 3072,
        h, 192, h, 192, 1<<30,
        0,
        1.f, nullptr, nullptr, nullptr, nullptr, 1);

    // fused qk + softmax + PV
    attn_fused<<<dim3(8,64), 256, ATTN_SMEM>>>(qkv, qk, wv);

    // fork 2: s2 = o LoRA-A partials + reduce ; stream 0 = base o GEMM
    cudaEventRecord(ev3, 0);
    cudaStreamWaitEvent(s2, ev3, 0);
    mma_gemm<<<dim3(1,32,4), 256, GEMM_SMEM, s2>>>(wv, oA, oA, oA, -1, hpart,
        Md, 64, 256, 1024, 1024, 64,
        wv, 1024, wv, 1024, 1<<30,
        (long long)Md*64,
        1.f, nullptr, nullptr, nullptr, nullptr, 0);
    red_h<<<(Md*64 + 255)/256, 256, 0, s2>>>(hpart, route, h, 64);

    // base o = wv·oW^T + ob (K=1024)
    mma_gemm<<<dim3(8,32,1), 256, GEMM_SMEM>>>(wv, oW, oW, oW, -1, out,
        Md, 1024, 1024, 1024, 1024, 1024,
        wv, 1024, wv, 1024, 1<<30,
        0,
        1.f, ob, nullptr, nullptr, nullptr, 0);

    cudaEventRecord(ev4, s2);
    cudaStreamWaitEvent(0, ev4, 0);

    // o LoRA-B add: out += h·Bt^T (K=64)
    mma_gemm<<<dim3(8,32,1), 256, GEMM_SMEM>>>(h, Bt, Bt, Bt, -1, out,
        Md, 1024, 64, 192, 64, 1024,
        h, 192, h, 192, 1<<30,
        0,
        1.f, nullptr, nullptr, nullptr, nullptr, 1);
}